// round 2
// baseline (speedup 1.0000x reference)
#include <cuda_runtime.h>
#include <math.h>

// ---------------- problem constants ----------------
#define NS    4096          // N samples
#define LS    16            // L tokens
#define DE    768           // D embedding
#define NHN   4             // heads (name attn)
#define DHN   192           // head dim (name attn)
#define HD    1024          // H
#define NLAY  4             // NL
#define NCLS  16            // C
#define XFD   256           // XF

// ---------------- scratch (device globals; no cudaMalloc allowed) ----------------
__device__ float g_qkv[(size_t)NS * LS * 3 * DE];   // 65536 x 2304
__device__ float g_attnsum[(size_t)NS * DE];        // 4096 x 768  (sum of o_s over masked q)
__device__ float g_proj[(size_t)NS * DE];           // 4096 x 768  (name_emb)
__device__ float g_h[(size_t)NS * HD];              // 4096 x 1024
__device__ float g_t1[(size_t)NS * 2 * HD];         // 4096 x 2048
__device__ float g_ta[(size_t)NS * HD];             // 4096 x 1024
__device__ float g_tv[(size_t)NS * HD];             // 4096 x 1024

// ---------------- generic SGEMM: C[M,N] = A[M,K] @ B[N,K]^T + bias ----------------
// AMODE: 0 = direct A, 1 = gathered A rows via tok[] (rows of A=wte), 2 = split A (A|A2 at K1)
// rowscale (optional): bias term becomes rowscale[m]*bias[n]
#define BMT 128
#define BNT 128
#define BKT 8

template<int AMODE, bool RELU>
__global__ __launch_bounds__(256) void sgemm_kernel(
    int M, int N, int K, int K1,
    const float* __restrict__ A, const float* __restrict__ A2,
    const int* __restrict__ tok,
    const float* __restrict__ B,
    const float* __restrict__ bias,
    const int* __restrict__ rowscale,
    float* __restrict__ C)
{
    __shared__ float As[BKT][BMT];
    __shared__ float Bs[BKT][BNT];
    __shared__ int toks[BMT];

    const int tid = threadIdx.x;
    const int bm  = blockIdx.y * BMT;
    const int bn  = blockIdx.x * BNT;

    if (AMODE == 1) {
        if (tid < BMT) toks[tid] = tok[bm + tid];
        __syncthreads();
    }

    const int lrow = tid >> 1;          // 0..127
    const int lcol = (tid & 1) * 4;     // 0 or 4
    const int ty   = tid >> 4;          // 0..15
    const int tx   = tid & 15;          // 0..15

    float acc[8][8];
#pragma unroll
    for (int i = 0; i < 8; i++)
#pragma unroll
        for (int j = 0; j < 8; j++) acc[i][j] = 0.f;

    for (int k0 = 0; k0 < K; k0 += BKT) {
        const int kk = k0 + lcol;
        float4 av;
        if (AMODE == 0) {
            av = *reinterpret_cast<const float4*>(A + (size_t)(bm + lrow) * K + kk);
        } else if (AMODE == 1) {
            av = *reinterpret_cast<const float4*>(A + (size_t)toks[lrow] * K + kk);
        } else {
            if (kk < K1)
                av = *reinterpret_cast<const float4*>(A + (size_t)(bm + lrow) * K1 + kk);
            else
                av = *reinterpret_cast<const float4*>(A2 + (size_t)(bm + lrow) * (K - K1) + (kk - K1));
        }
        const float4 bv = *reinterpret_cast<const float4*>(B + (size_t)(bn + lrow) * K + kk);

        As[lcol + 0][lrow] = av.x; As[lcol + 1][lrow] = av.y;
        As[lcol + 2][lrow] = av.z; As[lcol + 3][lrow] = av.w;
        Bs[lcol + 0][lrow] = bv.x; Bs[lcol + 1][lrow] = bv.y;
        Bs[lcol + 2][lrow] = bv.z; Bs[lcol + 3][lrow] = bv.w;
        __syncthreads();

#pragma unroll
        for (int k = 0; k < BKT; k++) {
            const float4 a0 = *reinterpret_cast<const float4*>(&As[k][ty * 8]);
            const float4 a1 = *reinterpret_cast<const float4*>(&As[k][ty * 8 + 4]);
            const float4 b0 = *reinterpret_cast<const float4*>(&Bs[k][tx * 8]);
            const float4 b1 = *reinterpret_cast<const float4*>(&Bs[k][tx * 8 + 4]);
            const float ra[8] = {a0.x, a0.y, a0.z, a0.w, a1.x, a1.y, a1.z, a1.w};
            const float rb[8] = {b0.x, b0.y, b0.z, b0.w, b1.x, b1.y, b1.z, b1.w};
#pragma unroll
            for (int i = 0; i < 8; i++)
#pragma unroll
                for (int j = 0; j < 8; j++)
                    acc[i][j] += ra[i] * rb[j];
        }
        __syncthreads();
    }

#pragma unroll
    for (int i = 0; i < 8; i++) {
        const int m = bm + ty * 8 + i;
        float rs = 1.f;
        if (rowscale) rs = (float)rowscale[m];
#pragma unroll
        for (int j = 0; j < 8; j++) {
            const int n = bn + tx * 8 + j;
            float v = acc[i][j] + rs * bias[n];
            if (RELU) v = fmaxf(v, 0.f);
            C[(size_t)m * N + n] = v;
        }
    }
}

// ---------------- name attention (S=16, 4 heads, dh=192), masked, q-summed ----------------
// One block per (head, sample); 192 threads (one per head-dim channel).
// Writes attnsum[b, h*192+d] = sum_{s<len} o[s, h, d]  (pre out-projection).
__global__ __launch_bounds__(192) void name_attn_kernel(
    const float* __restrict__ qkv, const int* __restrict__ lens,
    float* __restrict__ attnsum)
{
    __shared__ float Qs[LS][DHN];
    __shared__ float Ks[LS][DHN];
    __shared__ float Vs[LS][DHN];
    __shared__ float sc[LS][LS + 1];

    const int h = blockIdx.x;   // 0..3
    const int b = blockIdx.y;   // 0..4095
    const int d = threadIdx.x;  // 0..191

    const float* base = qkv + (size_t)b * LS * (3 * DE) + h * DHN + d;
#pragma unroll
    for (int s = 0; s < LS; s++) {
        Qs[s][d] = base[s * (3 * DE)];
        Ks[s][d] = base[s * (3 * DE) + DE];
        Vs[s][d] = base[s * (3 * DE) + 2 * DE];
    }
    __syncthreads();

    const int warp = d >> 5, lane = d & 31;
    const float scale = 1.0f / sqrtf((float)DHN);
    for (int p = warp; p < LS * LS; p += 6) {
        const int q = p >> 4, j = p & 15;
        float s = 0.f;
#pragma unroll
        for (int i = 0; i < 6; i++) s += Qs[q][lane + 32 * i] * Ks[j][lane + 32 * i];
#pragma unroll
        for (int o = 16; o; o >>= 1) s += __shfl_down_sync(0xffffffffu, s, o);
        if (lane == 0) sc[q][j] = s * scale;
    }
    __syncthreads();

    const int len = lens[b];
    if (d < LS) {
        float row[LS];
        float mx = -1e30f;
#pragma unroll
        for (int j = 0; j < LS; j++) {
            row[j] = (j < len) ? sc[d][j] : -1e9f;
            mx = fmaxf(mx, row[j]);
        }
        float sum = 0.f;
#pragma unroll
        for (int j = 0; j < LS; j++) { row[j] = expf(row[j] - mx); sum += row[j]; }
        const float inv = 1.f / sum;
#pragma unroll
        for (int j = 0; j < LS; j++) sc[d][j] = row[j] * inv;
    }
    __syncthreads();

    float accum = 0.f;
    for (int s = 0; s < len; s++) {   // only q positions inside the mask are summed
        float o = 0.f;
#pragma unroll
        for (int j = 0; j < LS; j++) o += sc[s][j] * Vs[j][d];
        accum += o;
    }
    attnsum[(size_t)b * DE + h * DHN + d] = accum;
}

// ---------------- residual + LayerNorm (in place on h): h = LN(h + a)*g + b ----------------
__device__ __forceinline__ float block_reduce_sum(float v) {
    __shared__ float red[8];
    const int lane = threadIdx.x & 31, warp = threadIdx.x >> 5;
#pragma unroll
    for (int o = 16; o; o >>= 1) v += __shfl_down_sync(0xffffffffu, v, o);
    if (lane == 0) red[warp] = v;
    __syncthreads();
    v = (threadIdx.x < 8) ? red[threadIdx.x] : 0.f;
    if (warp == 0)
#pragma unroll
        for (int o = 4; o; o >>= 1) v += __shfl_down_sync(0xffffffffu, v, o);
    return v;  // valid on thread 0
}

__global__ __launch_bounds__(256) void resid_ln_kernel(
    float* __restrict__ h, const float* __restrict__ a,
    const float* __restrict__ g, const float* __restrict__ b)
{
    const int row = blockIdx.x;
    const int t = threadIdx.x;
    float v[4];
    float s = 0.f;
#pragma unroll
    for (int i = 0; i < 4; i++) {
        const int c = t + 256 * i;
        v[i] = h[(size_t)row * HD + c] + a[(size_t)row * HD + c];
        s += v[i];
    }
    s = block_reduce_sum(s);
    __shared__ float mean_s, rstd_s;
    if (t == 0) mean_s = s * (1.f / HD);
    __syncthreads();
    const float m = mean_s;
    float s2 = 0.f;
#pragma unroll
    for (int i = 0; i < 4; i++) { const float dd = v[i] - m; s2 += dd * dd; }
    s2 = block_reduce_sum(s2);
    if (t == 0) rstd_s = rsqrtf(s2 * (1.f / HD) + 1e-5f);
    __syncthreads();
    const float r = rstd_s;
#pragma unroll
    for (int i = 0; i < 4; i++) {
        const int c = t + 256 * i;
        h[(size_t)row * HD + c] = (v[i] - m) * r * g[c] + b[c];
    }
}

// ---------------- classifier head: out[m,c] = h[m] . cls_w[c] + cls_b[c] ----------------
__global__ __launch_bounds__(512) void cls_kernel(
    const float* __restrict__ h, const float* __restrict__ w,
    const float* __restrict__ b, float* __restrict__ out)
{
    const int m = blockIdx.x;
    const int c = threadIdx.x >> 5;     // 16 warps = 16 classes
    const int lane = threadIdx.x & 31;
    const float* hr = h + (size_t)m * HD;
    const float* wr = w + (size_t)c * HD;
    float s = 0.f;
#pragma unroll
    for (int i = lane; i < HD; i += 32) s += hr[i] * wr[i];
#pragma unroll
    for (int o = 16; o; o >>= 1) s += __shfl_down_sync(0xffffffffu, s, o);
    if (lane == 0) out[(size_t)m * NCLS + c] = s + b[c];
}

// ---------------- orchestration ----------------
extern "C" void kernel_launch(void* const* d_in, const int* in_sizes, int n_in,
                              void* d_out, int out_size)
{
    const int*   name_tokens = (const int*)d_in[0];
    const int*   name_lens   = (const int*)d_in[1];
    const float* x_feats     = (const float*)d_in[2];
    const float* wte         = (const float*)d_in[3];
    const float* mha_in_w    = (const float*)d_in[4];
    const float* mha_in_b    = (const float*)d_in[5];
    const float* mha_out_w   = (const float*)d_in[6];
    const float* mha_out_b   = (const float*)d_in[7];
    const float* bott_w      = (const float*)d_in[8];
    const float* bott_b      = (const float*)d_in[9];
    const float* enc_in_w    = (const float*)d_in[10];
    const float* enc_in_b    = (const float*)d_in[11];
    const float* enc_out_w   = (const float*)d_in[12];
    const float* enc_out_b   = (const float*)d_in[13];
    const float* enc_ln1_g   = (const float*)d_in[14];
    const float* enc_ln1_b   = (const float*)d_in[15];
    const float* enc_ln2_g   = (const float*)d_in[16];
    const float* enc_ln2_b   = (const float*)d_in[17];
    const float* enc_ff1_w   = (const float*)d_in[18];
    const float* enc_ff1_b   = (const float*)d_in[19];
    const float* enc_ff2_w   = (const float*)d_in[20];
    const float* enc_ff2_b   = (const float*)d_in[21];
    const float* cls_w       = (const float*)d_in[22];
    const float* cls_b       = (const float*)d_in[23];
    float* out = (float*)d_out;

    float *qkv, *attnsum, *proj, *h, *t1, *ta, *tv;
    cudaGetSymbolAddress((void**)&qkv,     g_qkv);
    cudaGetSymbolAddress((void**)&attnsum, g_attnsum);
    cudaGetSymbolAddress((void**)&proj,    g_proj);
    cudaGetSymbolAddress((void**)&h,       g_h);
    cudaGetSymbolAddress((void**)&t1,      g_t1);
    cudaGetSymbolAddress((void**)&ta,      g_ta);
    cudaGetSymbolAddress((void**)&tv,      g_tv);

    const int MQ = NS * LS;          // 65536
    const int KQ = DE;               // 768
    const int NQ = 3 * DE;           // 2304

    // 1. qkv = gather(wte, tokens) @ mha_in_w^T + mha_in_b    [65536 x 2304]
    sgemm_kernel<1, false><<<dim3(NQ / BNT, MQ / BMT), 256>>>(
        MQ, NQ, KQ, 0, wte, nullptr, name_tokens, mha_in_w, mha_in_b, nullptr, qkv);

    // 2. masked name attention, summed over valid q positions -> attnsum [4096 x 768]
    name_attn_kernel<<<dim3(NHN, NS), 192>>>(qkv, name_lens, attnsum);

    // 3. name_emb = attnsum @ mha_out_w^T + len * mha_out_b   [4096 x 768]
    sgemm_kernel<0, false><<<dim3(DE / BNT, NS / BMT), 256>>>(
        NS, DE, DE, 0, attnsum, nullptr, nullptr, mha_out_w, mha_out_b, name_lens, proj);

    // 4. x = [x_feats | name_emb] @ bott_w^T + bott_b         [4096 x 1024]
    sgemm_kernel<2, false><<<dim3(HD / BNT, NS / BMT), 256>>>(
        NS, HD, XFD + DE, XFD, x_feats, proj, nullptr, bott_w, bott_b, nullptr, h);

    // 5. encoder layers (seq len 1 => attention == V/out projections only)
    for (int l = 0; l < NLAY; l++) {
        const float* wv = enc_in_w + (size_t)l * 3 * HD * HD + (size_t)2 * HD * HD;
        const float* bv = enc_in_b + (size_t)l * 3 * HD + 2 * HD;
        sgemm_kernel<0, false><<<dim3(HD / BNT, NS / BMT), 256>>>(
            NS, HD, HD, 0, h, nullptr, nullptr, wv, bv, nullptr, tv);
        sgemm_kernel<0, false><<<dim3(HD / BNT, NS / BMT), 256>>>(
            NS, HD, HD, 0, tv, nullptr, nullptr,
            enc_out_w + (size_t)l * HD * HD, enc_out_b + (size_t)l * HD, nullptr, ta);
        resid_ln_kernel<<<NS, 256>>>(h, ta, enc_ln1_g + (size_t)l * HD, enc_ln1_b + (size_t)l * HD);

        sgemm_kernel<0, true><<<dim3(2 * HD / BNT, NS / BMT), 256>>>(
            NS, 2 * HD, HD, 0, h, nullptr, nullptr,
            enc_ff1_w + (size_t)l * 2 * HD * HD, enc_ff1_b + (size_t)l * 2 * HD, nullptr, t1);
        sgemm_kernel<0, false><<<dim3(HD / BNT, NS / BMT), 256>>>(
            NS, HD, 2 * HD, 0, t1, nullptr, nullptr,
            enc_ff2_w + (size_t)l * HD * 2 * HD, enc_ff2_b + (size_t)l * HD, nullptr, ta);
        resid_ln_kernel<<<NS, 256>>>(h, ta, enc_ln2_g + (size_t)l * HD, enc_ln2_b + (size_t)l * HD);
    }

    // 6. classifier head -> out [4096 x 16]
    cls_kernel<<<NS, 512>>>(h, cls_w, cls_b, out);
}

// round 4
// speedup vs baseline: 2.5612x; 2.5612x over previous
#include <cuda_runtime.h>
#include <cuda_bf16.h>
#include <cstdint>
#include <math.h>

// ---------------- problem constants ----------------
#define NS    4096          // N samples
#define LS    16            // L tokens
#define DE    768           // D embedding
#define NHN   4             // heads (name attn)
#define DHN   192           // head dim (name attn)
#define HD    1024          // H
#define NLAY  4             // NL
#define NCLS  16            // C
#define XFD   256           // XF

// ---------------- scratch (device globals; no cudaMalloc allowed) ----------------
__device__ float g_qkv[(size_t)NS * LS * 3 * DE];   // 65536 x 2304
__device__ float g_attnsum[(size_t)NS * DE];        // 4096 x 768
__device__ float g_proj[(size_t)NS * DE];           // 4096 x 768
__device__ float g_h[(size_t)NS * HD];              // 4096 x 1024
__device__ float g_t1[(size_t)NS * 2 * HD];         // 4096 x 2048
__device__ float g_ta[(size_t)NS * HD];             // 4096 x 1024
__device__ float g_tv[(size_t)NS * HD];             // 4096 x 1024

// ================= helpers =================
__device__ __forceinline__ uint32_t smem_u32(const void* p) {
    uint32_t a;
    asm("{ .reg .u64 t; cvta.to.shared.u64 t, %1; cvt.u32.u64 %0, t; }" : "=r"(a) : "l"(p));
    return a;
}
__device__ __forceinline__ uint32_t sw128(uint32_t o) { return o ^ ((o >> 3) & 0x70); }

#define LDSM4(r, addr) \
    asm volatile("ldmatrix.sync.aligned.m8n8.x4.shared.b16 {%0,%1,%2,%3}, [%4];" \
        : "=r"((r)[0]), "=r"((r)[1]), "=r"((r)[2]), "=r"((r)[3]) : "r"(addr))

__device__ __forceinline__ void mma16816(float* c, const uint32_t* a, uint32_t b0, uint32_t b1) {
    asm volatile("mma.sync.aligned.m16n8k16.row.col.f32.bf16.bf16.f32 "
        "{%0,%1,%2,%3},{%4,%5,%6,%7},{%8,%9},{%0,%1,%2,%3};"
        : "+f"(c[0]), "+f"(c[1]), "+f"(c[2]), "+f"(c[3])
        : "r"(a[0]), "r"(a[1]), "r"(a[2]), "r"(a[3]), "r"(b0), "r"(b1));
}

// split fp32 pair -> packed bf16 hi (p) and lo residual (q). p = {lo16=bf16(x), hi16=bf16(y)}
__device__ __forceinline__ void split2(float x, float y, uint32_t& p, uint32_t& q) {
    asm("cvt.rn.bf16x2.f32 %0, %1, %2;" : "=r"(p) : "f"(y), "f"(x));
    float h0 = __uint_as_float(p << 16);
    float h1 = __uint_as_float(p & 0xffff0000u);
    float r0 = x - h0, r1 = y - h1;
    asm("cvt.rn.bf16x2.f32 %0, %1, %2;" : "=r"(q) : "f"(r1), "f"(r0));
}

// ================= HMMA GEMM: C[M,N] = A[M,K] @ B[N,K]^T + bias =================
// AMODE: 0 direct, 1 gather rows via tok[] (A = wte), 2 split A|A2 at K1 (K1 % 64 == 0)
// 3-term bf16 split: C = Ah*Bh + Ah*Bl + Al*Bh  (fp32-accurate to ~2^-16)
#define CHUNK 64
// dynamic smem layout (all tiles 128 rows x 128B, SW128-swizzled)
#define OFF_TOKS 0
#define OFF_A_H  1024
#define OFF_A_L  (1024 + 16384)
#define OFF_B_H  (1024 + 2 * 16384)
#define OFF_B_L  (1024 + 3 * 16384)
#define TG_SMEM  (1024 + 4 * 16384)

template<int AMODE, bool RELU>
__global__ __launch_bounds__(256, 2) void tgemm_kernel(
    int M, int N, int K, int K1,
    const float* __restrict__ A, const float* __restrict__ A2,
    const int* __restrict__ tok,
    const float* __restrict__ B,
    const float* __restrict__ bias,
    const int* __restrict__ rowscale,
    float* __restrict__ C)
{
    extern __shared__ char smem[];
    const uint32_t sb = smem_u32(smem);
    int* toks = (int*)(smem + OFF_TOKS);

    const int tid  = threadIdx.x;
    const int lane = tid & 31;
    const int wid  = tid >> 5;
    const int bm = blockIdx.y * 128, bn = blockIdx.x * 128;

    if (AMODE == 1 && tid < 128) toks[tid] = tok[bm + tid];
    __syncthreads();

    // warp tile: 32 (M) x 64 (N); warps laid out 4 (M) x 2 (N)
    const int wm = (wid >> 1) * 32;
    const int wn = (wid & 1) * 64;

    float acc[2][8][4];
#pragma unroll
    for (int i = 0; i < 2; i++)
#pragma unroll
        for (int j = 0; j < 8; j++)
#pragma unroll
            for (int t = 0; t < 4; t++) acc[i][j][t] = 0.f;

    // ldmatrix lane addressing (constant across chunks except k-step offset)
    const int a_row  = (lane & 15);                        // + wm + i*16
    const int a_kb   = (lane >> 4) * 16;                   // + ks*32
    const int b_row  = (lane & 7) + ((lane >> 4) << 3);    // + wn + j2*16
    const int b_kb   = ((lane >> 3) & 1) * 16;             // + ks*32

    const int nch = K / CHUNK;
    for (int c = 0; c < nch; c++) {
        const int k0 = c * CHUNK;

        // ---- fill stage: LDG fp32 -> split bf16 hi/lo -> swizzled STS ----
#pragma unroll
        for (int it = 0; it < 8; it++) {
            const int idx  = tid + 256 * it;    // 0..2047 float4 slots
            const int row  = idx >> 4;          // 0..127
            const int subk = idx & 15;          // float4 within row
            const float* ap;
            if (AMODE == 1) {
                ap = A + (size_t)toks[row] * K + k0 + subk * 4;
            } else if (AMODE == 2) {
                if (k0 < K1) ap = A  + (size_t)(bm + row) * K1       + k0        + subk * 4;
                else         ap = A2 + (size_t)(bm + row) * (K - K1) + (k0 - K1) + subk * 4;
            } else {
                ap = A + (size_t)(bm + row) * K + k0 + subk * 4;
            }
            const float4 av = *reinterpret_cast<const float4*>(ap);
            const float4 bv = *reinterpret_cast<const float4*>(B + (size_t)(bn + row) * K + k0 + subk * 4);

            const uint32_t sw = sw128(row * 128 + subk * 8);
            uint32_t h0, l0, h1, l1;
            split2(av.x, av.y, h0, l0);
            split2(av.z, av.w, h1, l1);
            *reinterpret_cast<uint2*>(smem + OFF_A_H + sw) = make_uint2(h0, h1);
            *reinterpret_cast<uint2*>(smem + OFF_A_L + sw) = make_uint2(l0, l1);
            split2(bv.x, bv.y, h0, l0);
            split2(bv.z, bv.w, h1, l1);
            *reinterpret_cast<uint2*>(smem + OFF_B_H + sw) = make_uint2(h0, h1);
            *reinterpret_cast<uint2*>(smem + OFF_B_L + sw) = make_uint2(l0, l1);
        }
        __syncthreads();

        // ---- compute: 4 k16 steps, 3-term ----
#pragma unroll
        for (int ks = 0; ks < 4; ks++) {
            const int kb = ks * 32;
            uint32_t ah0[4], ah1[4], al0[4], al1[4];
            {
                const uint32_t o0 = sw128((wm + a_row) * 128 + kb + a_kb);
                const uint32_t o1 = sw128((wm + 16 + a_row) * 128 + kb + a_kb);
                LDSM4(ah0, sb + OFF_A_H + o0);
                LDSM4(ah1, sb + OFF_A_H + o1);
                LDSM4(al0, sb + OFF_A_L + o0);
                LDSM4(al1, sb + OFF_A_L + o1);
            }
            uint32_t bf[4][4];
#pragma unroll
            for (int j2 = 0; j2 < 4; j2++) {
                const uint32_t ob = sw128((wn + j2 * 16 + b_row) * 128 + kb + b_kb);
                LDSM4(bf[j2], sb + OFF_B_H + ob);
            }
            // Ah*Bh + Al*Bh
#pragma unroll
            for (int j2 = 0; j2 < 4; j2++) {
                mma16816(acc[0][2 * j2 + 0], ah0, bf[j2][0], bf[j2][1]);
                mma16816(acc[0][2 * j2 + 1], ah0, bf[j2][2], bf[j2][3]);
                mma16816(acc[1][2 * j2 + 0], ah1, bf[j2][0], bf[j2][1]);
                mma16816(acc[1][2 * j2 + 1], ah1, bf[j2][2], bf[j2][3]);
                mma16816(acc[0][2 * j2 + 0], al0, bf[j2][0], bf[j2][1]);
                mma16816(acc[0][2 * j2 + 1], al0, bf[j2][2], bf[j2][3]);
                mma16816(acc[1][2 * j2 + 0], al1, bf[j2][0], bf[j2][1]);
                mma16816(acc[1][2 * j2 + 1], al1, bf[j2][2], bf[j2][3]);
            }
            // Ah*Bl
#pragma unroll
            for (int j2 = 0; j2 < 4; j2++) {
                const uint32_t ob = sw128((wn + j2 * 16 + b_row) * 128 + kb + b_kb);
                LDSM4(bf[j2], sb + OFF_B_L + ob);
            }
#pragma unroll
            for (int j2 = 0; j2 < 4; j2++) {
                mma16816(acc[0][2 * j2 + 0], ah0, bf[j2][0], bf[j2][1]);
                mma16816(acc[0][2 * j2 + 1], ah0, bf[j2][2], bf[j2][3]);
                mma16816(acc[1][2 * j2 + 0], ah1, bf[j2][0], bf[j2][1]);
                mma16816(acc[1][2 * j2 + 1], ah1, bf[j2][2], bf[j2][3]);
            }
        }
        __syncthreads();
    }

    // ---- epilogue: regs -> bias/rowscale/relu -> GMEM ----
#pragma unroll
    for (int i = 0; i < 2; i++) {
        const int r0 = bm + wm + i * 16 + (lane >> 2);
        const int r1 = r0 + 8;
        const float rs0 = rowscale ? (float)rowscale[r0] : 1.f;
        const float rs1 = rowscale ? (float)rowscale[r1] : 1.f;
#pragma unroll
        for (int j = 0; j < 8; j++) {
            const int col = bn + wn + j * 8 + (lane & 3) * 2;
            const float b0 = bias[col], b1 = bias[col + 1];
            float2 v0 = make_float2(acc[i][j][0] + rs0 * b0, acc[i][j][1] + rs0 * b1);
            float2 v1 = make_float2(acc[i][j][2] + rs1 * b0, acc[i][j][3] + rs1 * b1);
            if (RELU) {
                v0.x = fmaxf(v0.x, 0.f); v0.y = fmaxf(v0.y, 0.f);
                v1.x = fmaxf(v1.x, 0.f); v1.y = fmaxf(v1.y, 0.f);
            }
            *reinterpret_cast<float2*>(C + (size_t)r0 * N + col) = v0;
            *reinterpret_cast<float2*>(C + (size_t)r1 * N + col) = v1;
        }
    }
}

// ---------------- name attention (S=16, 4 heads, dh=192), masked, q-summed ----------------
__global__ __launch_bounds__(192) void name_attn_kernel(
    const float* __restrict__ qkv, const int* __restrict__ lens,
    float* __restrict__ attnsum)
{
    __shared__ float Qs[LS][DHN];
    __shared__ float Ks[LS][DHN];
    __shared__ float Vs[LS][DHN];
    __shared__ float sc[LS][LS + 1];

    const int h = blockIdx.x;
    const int b = blockIdx.y;
    const int d = threadIdx.x;

    const float* base = qkv + (size_t)b * LS * (3 * DE) + h * DHN + d;
#pragma unroll
    for (int s = 0; s < LS; s++) {
        Qs[s][d] = base[s * (3 * DE)];
        Ks[s][d] = base[s * (3 * DE) + DE];
        Vs[s][d] = base[s * (3 * DE) + 2 * DE];
    }
    __syncthreads();

    const int warp = d >> 5, lane = d & 31;
    const float scale = 1.0f / sqrtf((float)DHN);
    for (int p = warp; p < LS * LS; p += 6) {
        const int q = p >> 4, j = p & 15;
        float s = 0.f;
#pragma unroll
        for (int i = 0; i < 6; i++) s += Qs[q][lane + 32 * i] * Ks[j][lane + 32 * i];
#pragma unroll
        for (int o = 16; o; o >>= 1) s += __shfl_down_sync(0xffffffffu, s, o);
        if (lane == 0) sc[q][j] = s * scale;
    }
    __syncthreads();

    const int len = lens[b];
    if (d < LS) {
        float row[LS];
        float mx = -1e30f;
#pragma unroll
        for (int j = 0; j < LS; j++) {
            row[j] = (j < len) ? sc[d][j] : -1e9f;
            mx = fmaxf(mx, row[j]);
        }
        float sum = 0.f;
#pragma unroll
        for (int j = 0; j < LS; j++) { row[j] = expf(row[j] - mx); sum += row[j]; }
        const float inv = 1.f / sum;
#pragma unroll
        for (int j = 0; j < LS; j++) sc[d][j] = row[j] * inv;
    }
    __syncthreads();

    float accum = 0.f;
    for (int s = 0; s < len; s++) {
        float o = 0.f;
#pragma unroll
        for (int j = 0; j < LS; j++) o += sc[s][j] * Vs[j][d];
        accum += o;
    }
    attnsum[(size_t)b * DE + h * DHN + d] = accum;
}

// ---------------- residual + LayerNorm (in place on h) ----------------
__device__ __forceinline__ float block_reduce_sum(float v) {
    __shared__ float red[8];
    const int lane = threadIdx.x & 31, warp = threadIdx.x >> 5;
#pragma unroll
    for (int o = 16; o; o >>= 1) v += __shfl_down_sync(0xffffffffu, v, o);
    if (lane == 0) red[warp] = v;
    __syncthreads();
    v = (threadIdx.x < 8) ? red[threadIdx.x] : 0.f;
    if (warp == 0)
#pragma unroll
        for (int o = 4; o; o >>= 1) v += __shfl_down_sync(0xffffffffu, v, o);
    return v;
}

__global__ __launch_bounds__(256) void resid_ln_kernel(
    float* __restrict__ h, const float* __restrict__ a,
    const float* __restrict__ g, const float* __restrict__ b)
{
    const int row = blockIdx.x;
    const int t = threadIdx.x;
    float v[4];
    float s = 0.f;
#pragma unroll
    for (int i = 0; i < 4; i++) {
        const int c = t + 256 * i;
        v[i] = h[(size_t)row * HD + c] + a[(size_t)row * HD + c];
        s += v[i];
    }
    s = block_reduce_sum(s);
    __shared__ float mean_s, rstd_s;
    if (t == 0) mean_s = s * (1.f / HD);
    __syncthreads();
    const float m = mean_s;
    float s2 = 0.f;
#pragma unroll
    for (int i = 0; i < 4; i++) { const float dd = v[i] - m; s2 += dd * dd; }
    s2 = block_reduce_sum(s2);
    if (t == 0) rstd_s = rsqrtf(s2 * (1.f / HD) + 1e-5f);
    __syncthreads();
    const float r = rstd_s;
#pragma unroll
    for (int i = 0; i < 4; i++) {
        const int c = t + 256 * i;
        h[(size_t)row * HD + c] = (v[i] - m) * r * g[c] + b[c];
    }
}

// ---------------- classifier head ----------------
__global__ __launch_bounds__(512) void cls_kernel(
    const float* __restrict__ h, const float* __restrict__ w,
    const float* __restrict__ b, float* __restrict__ out)
{
    const int m = blockIdx.x;
    const int c = threadIdx.x >> 5;
    const int lane = threadIdx.x & 31;
    const float* hr = h + (size_t)m * HD;
    const float* wr = w + (size_t)c * HD;
    float s = 0.f;
#pragma unroll
    for (int i = lane; i < HD; i += 32) s += hr[i] * wr[i];
#pragma unroll
    for (int o = 16; o; o >>= 1) s += __shfl_down_sync(0xffffffffu, s, o);
    if (lane == 0) out[(size_t)m * NCLS + c] = s + b[c];
}

// ---------------- orchestration ----------------
extern "C" void kernel_launch(void* const* d_in, const int* in_sizes, int n_in,
                              void* d_out, int out_size)
{
    const int*   name_tokens = (const int*)d_in[0];
    const int*   name_lens   = (const int*)d_in[1];
    const float* x_feats     = (const float*)d_in[2];
    const float* wte         = (const float*)d_in[3];
    const float* mha_in_w    = (const float*)d_in[4];
    const float* mha_in_b    = (const float*)d_in[5];
    const float* mha_out_w   = (const float*)d_in[6];
    const float* mha_out_b   = (const float*)d_in[7];
    const float* bott_w      = (const float*)d_in[8];
    const float* bott_b      = (const float*)d_in[9];
    const float* enc_in_w    = (const float*)d_in[10];
    const float* enc_in_b    = (const float*)d_in[11];
    const float* enc_out_w   = (const float*)d_in[12];
    const float* enc_out_b   = (const float*)d_in[13];
    const float* enc_ln1_g   = (const float*)d_in[14];
    const float* enc_ln1_b   = (const float*)d_in[15];
    const float* enc_ln2_g   = (const float*)d_in[16];
    const float* enc_ln2_b   = (const float*)d_in[17];
    const float* enc_ff1_w   = (const float*)d_in[18];
    const float* enc_ff1_b   = (const float*)d_in[19];
    const float* enc_ff2_w   = (const float*)d_in[20];
    const float* enc_ff2_b   = (const float*)d_in[21];
    const float* cls_w       = (const float*)d_in[22];
    const float* cls_b       = (const float*)d_in[23];
    float* out = (float*)d_out;

    float *qkv, *attnsum, *proj, *h, *t1, *ta, *tv;
    cudaGetSymbolAddress((void**)&qkv,     g_qkv);
    cudaGetSymbolAddress((void**)&attnsum, g_attnsum);
    cudaGetSymbolAddress((void**)&proj,    g_proj);
    cudaGetSymbolAddress((void**)&h,       g_h);
    cudaGetSymbolAddress((void**)&t1,      g_t1);
    cudaGetSymbolAddress((void**)&ta,      g_ta);
    cudaGetSymbolAddress((void**)&tv,      g_tv);

    cudaFuncSetAttribute(tgemm_kernel<0, false>, cudaFuncAttributeMaxDynamicSharedMemorySize, TG_SMEM);
    cudaFuncSetAttribute(tgemm_kernel<0, true>,  cudaFuncAttributeMaxDynamicSharedMemorySize, TG_SMEM);
    cudaFuncSetAttribute(tgemm_kernel<1, false>, cudaFuncAttributeMaxDynamicSharedMemorySize, TG_SMEM);
    cudaFuncSetAttribute(tgemm_kernel<2, false>, cudaFuncAttributeMaxDynamicSharedMemorySize, TG_SMEM);

    const int MQ = NS * LS;          // 65536
    const int KQ = DE;               // 768
    const int NQ = 3 * DE;           // 2304

    // 1. qkv = gather(wte, tokens) @ mha_in_w^T + mha_in_b    [65536 x 2304]
    tgemm_kernel<1, false><<<dim3(NQ / 128, MQ / 128), 256, TG_SMEM>>>(
        MQ, NQ, KQ, 0, wte, nullptr, name_tokens, mha_in_w, mha_in_b, nullptr, qkv);

    // 2. masked name attention, summed over valid q positions -> attnsum [4096 x 768]
    name_attn_kernel<<<dim3(NHN, NS), 192>>>(qkv, name_lens, attnsum);

    // 3. name_emb = attnsum @ mha_out_w^T + len * mha_out_b   [4096 x 768]
    tgemm_kernel<0, false><<<dim3(DE / 128, NS / 128), 256, TG_SMEM>>>(
        NS, DE, DE, 0, attnsum, nullptr, nullptr, mha_out_w, mha_out_b, name_lens, proj);

    // 4. x = [x_feats | name_emb] @ bott_w^T + bott_b         [4096 x 1024]
    tgemm_kernel<2, false><<<dim3(HD / 128, NS / 128), 256, TG_SMEM>>>(
        NS, HD, XFD + DE, XFD, x_feats, proj, nullptr, bott_w, bott_b, nullptr, h);

    // 5. encoder layers (seq len 1 => attention == V/out projections only)
    for (int l = 0; l < NLAY; l++) {
        const float* wv = enc_in_w + (size_t)l * 3 * HD * HD + (size_t)2 * HD * HD;
        const float* bv = enc_in_b + (size_t)l * 3 * HD + 2 * HD;
        tgemm_kernel<0, false><<<dim3(HD / 128, NS / 128), 256, TG_SMEM>>>(
            NS, HD, HD, 0, h, nullptr, nullptr, wv, bv, nullptr, tv);
        tgemm_kernel<0, false><<<dim3(HD / 128, NS / 128), 256, TG_SMEM>>>(
            NS, HD, HD, 0, tv, nullptr, nullptr,
            enc_out_w + (size_t)l * HD * HD, enc_out_b + (size_t)l * HD, nullptr, ta);
        resid_ln_kernel<<<NS, 256>>>(h, ta, enc_ln1_g + (size_t)l * HD, enc_ln1_b + (size_t)l * HD);

        tgemm_kernel<0, true><<<dim3(2 * HD / 128, NS / 128), 256, TG_SMEM>>>(
            NS, 2 * HD, HD, 0, h, nullptr, nullptr,
            enc_ff1_w + (size_t)l * 2 * HD * HD, enc_ff1_b + (size_t)l * 2 * HD, nullptr, t1);
        tgemm_kernel<0, false><<<dim3(HD / 128, NS / 128), 256, TG_SMEM>>>(
            NS, HD, 2 * HD, 0, t1, nullptr, nullptr,
            enc_ff2_w + (size_t)l * HD * 2 * HD, enc_ff2_b + (size_t)l * HD, nullptr, ta);
        resid_ln_kernel<<<NS, 256>>>(h, ta, enc_ln2_g + (size_t)l * HD, enc_ln2_b + (size_t)l * HD);
    }

    // 6. classifier head -> out [4096 x 16]
    cls_kernel<<<NS, 512>>>(h, cls_w, cls_b, out);
}

// round 5
// speedup vs baseline: 2.9489x; 1.1514x over previous
#include <cuda_runtime.h>
#include <cuda_bf16.h>
#include <cstdint>
#include <math.h>

// ---------------- problem constants ----------------
#define NS    4096          // N samples
#define LS    16            // L tokens
#define DE    768           // D embedding
#define NHN   4             // heads (name attn)
#define DHN   192           // head dim (name attn)
#define HD    1024          // H
#define NLAY  4             // NL
#define NCLS  16            // C
#define XFD   256           // XF
#define VOCAB 50257

// ---------------- scratch (device globals; no cudaMalloc allowed) ----------------
__device__ float g_qkv[(size_t)NS * LS * 3 * DE];   // 65536 x 2304 fp32 (for attn)
__device__ float g_h[(size_t)NS * HD];              // fp32 residual stream
__device__ float g_ta[(size_t)NS * HD];             // fp32 (LN input)

// bf16 hi/lo split buffers (activations)
__device__ __align__(16) __nv_bfloat16 g_attn_h[(size_t)NS * DE],     g_attn_l[(size_t)NS * DE];
__device__ __align__(16) __nv_bfloat16 g_xf_h[(size_t)NS * XFD],      g_xf_l[(size_t)NS * XFD];
__device__ __align__(16) __nv_bfloat16 g_proj_h[(size_t)NS * DE],     g_proj_l[(size_t)NS * DE];
__device__ __align__(16) __nv_bfloat16 g_hh[(size_t)NS * HD],         g_hl[(size_t)NS * HD];
__device__ __align__(16) __nv_bfloat16 g_tv_h[(size_t)NS * HD],       g_tv_l[(size_t)NS * HD];
__device__ __align__(16) __nv_bfloat16 g_t1_h[(size_t)NS * 2 * HD],   g_t1_l[(size_t)NS * 2 * HD];

// bf16 hi/lo split buffers (weights)
__device__ __align__(16) __nv_bfloat16 g_wte_h[(size_t)VOCAB * DE],   g_wte_l[(size_t)VOCAB * DE];
__device__ __align__(16) __nv_bfloat16 g_wqkv_h[(size_t)3 * DE * DE], g_wqkv_l[(size_t)3 * DE * DE];
__device__ __align__(16) __nv_bfloat16 g_wout_h[(size_t)DE * DE],     g_wout_l[(size_t)DE * DE];
__device__ __align__(16) __nv_bfloat16 g_wbott_h[(size_t)HD * (XFD + DE)], g_wbott_l[(size_t)HD * (XFD + DE)];
__device__ __align__(16) __nv_bfloat16 g_wv_h[(size_t)NLAY * HD * HD],  g_wv_l[(size_t)NLAY * HD * HD];
__device__ __align__(16) __nv_bfloat16 g_wo_h[(size_t)NLAY * HD * HD],  g_wo_l[(size_t)NLAY * HD * HD];
__device__ __align__(16) __nv_bfloat16 g_wf1_h[(size_t)NLAY * 2 * HD * HD], g_wf1_l[(size_t)NLAY * 2 * HD * HD];
__device__ __align__(16) __nv_bfloat16 g_wf2_h[(size_t)NLAY * HD * 2 * HD], g_wf2_l[(size_t)NLAY * HD * 2 * HD];

// ================= helpers =================
__device__ __forceinline__ uint32_t smem_u32(const void* p) {
    uint32_t a;
    asm("{ .reg .u64 t; cvta.to.shared.u64 t, %1; cvt.u32.u64 %0, t; }" : "=r"(a) : "l"(p));
    return a;
}
__device__ __forceinline__ uint32_t sw128(uint32_t o) { return o ^ ((o >> 3) & 0x70); }

#define LDSM4(r, addr) \
    asm volatile("ldmatrix.sync.aligned.m8n8.x4.shared.b16 {%0,%1,%2,%3}, [%4];" \
        : "=r"((r)[0]), "=r"((r)[1]), "=r"((r)[2]), "=r"((r)[3]) : "r"(addr))

__device__ __forceinline__ void mma16816(float* c, const uint32_t* a, uint32_t b0, uint32_t b1) {
    asm volatile("mma.sync.aligned.m16n8k16.row.col.f32.bf16.bf16.f32 "
        "{%0,%1,%2,%3},{%4,%5,%6,%7},{%8,%9},{%0,%1,%2,%3};"
        : "+f"(c[0]), "+f"(c[1]), "+f"(c[2]), "+f"(c[3])
        : "r"(a[0]), "r"(a[1]), "r"(a[2]), "r"(a[3]), "r"(b0), "r"(b1));
}

#define CP_ASYNC16(dst, src) \
    asm volatile("cp.async.cg.shared.global [%0], [%1], 16;" :: "r"(dst), "l"(src))
#define CP_COMMIT() asm volatile("cp.async.commit_group;" ::: "memory")
#define CP_WAIT(n)  asm volatile("cp.async.wait_group %0;" :: "n"(n) : "memory")

// split fp32 pair -> packed bf16 hi (p) and lo residual (q). p = {lo16=bf16(x), hi16=bf16(y)}
__device__ __forceinline__ void split2(float x, float y, uint32_t& p, uint32_t& q) {
    asm("cvt.rn.bf16x2.f32 %0, %1, %2;" : "=r"(p) : "f"(y), "f"(x));
    float h0 = __uint_as_float(p << 16);
    float h1 = __uint_as_float(p & 0xffff0000u);
    float r0 = x - h0, r1 = y - h1;
    asm("cvt.rn.bf16x2.f32 %0, %1, %2;" : "=r"(q) : "f"(r1), "f"(r0));
}

// ---------------- fp32 -> bf16 hi/lo split (elementwise, n2 = n/2 pairs) ----------------
__global__ __launch_bounds__(256) void split_kernel(
    const float* __restrict__ src,
    __nv_bfloat16* __restrict__ hi, __nv_bfloat16* __restrict__ lo, int n2)
{
    const int i = blockIdx.x * blockDim.x + threadIdx.x;
    if (i < n2) {
        const float2 v = reinterpret_cast<const float2*>(src)[i];
        uint32_t p, q;
        split2(v.x, v.y, p, q);
        reinterpret_cast<uint32_t*>(hi)[i] = p;
        reinterpret_cast<uint32_t*>(lo)[i] = q;
    }
}

// ================= HMMA GEMM: C[M,N] = A[M,K] @ B[N,K]^T + bias =================
// A/B pre-split into bf16 hi/lo. 3-term: C = Ah*Bh + Ah*Bl + Al*Bh.
// AMODE: 0 direct, 1 gather rows via tok[], 2 concat A|A2 at K1 (K1 % 64 == 0)
// cp.async 3-stage pipeline; CTA 128x128, chunk K=64, 8 warps (32x64 each).
#define CHUNK  64
#define STAGES 3
#define STG_BYTES 65536          // 4 tiles x 16KB (Ah,Al,Bh,Bl; 128 rows x 128B)
#define OFF_AH 0
#define OFF_AL 16384
#define OFF_BH 32768
#define OFF_BL 49152
#define OFF_TOKS (STAGES * STG_BYTES)
#define TG_SMEM  (OFF_TOKS + 512)

template<int AMODE, bool RELU, bool WF32, bool WSPLIT>
__global__ __launch_bounds__(256, 1) void tgemm_kernel(
    int M, int N, int K, int K1,
    const __nv_bfloat16* __restrict__ Ah, const __nv_bfloat16* __restrict__ Al,
    const __nv_bfloat16* __restrict__ A2h, const __nv_bfloat16* __restrict__ A2l,
    const int* __restrict__ tok,
    const __nv_bfloat16* __restrict__ Bh, const __nv_bfloat16* __restrict__ Bl,
    const float* __restrict__ bias,
    const int* __restrict__ rowscale,
    float* __restrict__ C,
    __nv_bfloat16* __restrict__ Ch, __nv_bfloat16* __restrict__ Cl)
{
    extern __shared__ char smem[];
    const uint32_t sb = smem_u32(smem);
    int* toks = (int*)(smem + OFF_TOKS);

    const int tid  = threadIdx.x;
    const int lane = tid & 31;
    const int wid  = tid >> 5;
    const int bm = blockIdx.y * 128, bn = blockIdx.x * 128;

    if (AMODE == 1 && tid < 128) toks[tid] = tok[bm + tid];
    __syncthreads();

    const int nch = K / CHUNK;

    auto issue_stage = [&](int c) {
        const int k0 = c * CHUNK;
        const uint32_t st = sb + (c % STAGES) * STG_BYTES;
#pragma unroll
        for (int i = 0; i < 4; i++) {
            const int idx = tid + 256 * i;        // 0..1023
            const int row = idx >> 3;             // 0..127
            const int seg = idx & 7;              // 16B segment
            const uint32_t sw = sw128(row * 128 + seg * 16);
            const __nv_bfloat16 *pah, *pal;
            if (AMODE == 1) {
                const size_t off = (size_t)toks[row] * K + k0 + seg * 8;
                pah = Ah + off; pal = Al + off;
            } else if (AMODE == 2) {
                if (k0 < K1) {
                    const size_t off = (size_t)(bm + row) * K1 + k0 + seg * 8;
                    pah = Ah + off; pal = Al + off;
                } else {
                    const size_t off = (size_t)(bm + row) * (K - K1) + (k0 - K1) + seg * 8;
                    pah = A2h + off; pal = A2l + off;
                }
            } else {
                const size_t off = (size_t)(bm + row) * K + k0 + seg * 8;
                pah = Ah + off; pal = Al + off;
            }
            CP_ASYNC16(st + OFF_AH + sw, pah);
            CP_ASYNC16(st + OFF_AL + sw, pal);
            const size_t boff = (size_t)(bn + row) * K + k0 + seg * 8;
            CP_ASYNC16(st + OFF_BH + sw, Bh + boff);
            CP_ASYNC16(st + OFF_BL + sw, Bl + boff);
        }
        CP_COMMIT();
    };

    // prologue: fill the pipeline (all our K have nch >= 3)
#pragma unroll
    for (int s = 0; s < STAGES; s++)
        if (s < nch) issue_stage(s);

    // warp tile: 32 (M) x 64 (N); warps laid out 4 (M) x 2 (N)
    const int wm = (wid >> 1) * 32;
    const int wn = (wid & 1) * 64;

    float acc[2][8][4];
#pragma unroll
    for (int i = 0; i < 2; i++)
#pragma unroll
        for (int j = 0; j < 8; j++)
#pragma unroll
            for (int t = 0; t < 4; t++) acc[i][j][t] = 0.f;

    const int a_row  = (lane & 15);
    const int a_kb   = (lane >> 4) * 16;
    const int b_row  = (lane & 7) + ((lane >> 4) << 3);
    const int b_kb   = ((lane >> 3) & 1) * 16;

    for (int c = 0; c < nch; c++) {
        if (c == nch - 1) { CP_WAIT(0); } else { CP_WAIT(1); }
        __syncthreads();

        const uint32_t st = sb + (c % STAGES) * STG_BYTES;

#pragma unroll
        for (int ks = 0; ks < 4; ks++) {
            const int kb = ks * 32;
            uint32_t ah0[4], ah1[4], al0[4], al1[4];
            {
                const uint32_t o0 = sw128((wm + a_row) * 128 + kb + a_kb);
                const uint32_t o1 = sw128((wm + 16 + a_row) * 128 + kb + a_kb);
                LDSM4(ah0, st + OFF_AH + o0);
                LDSM4(ah1, st + OFF_AH + o1);
                LDSM4(al0, st + OFF_AL + o0);
                LDSM4(al1, st + OFF_AL + o1);
            }
            uint32_t bf[4][4];
#pragma unroll
            for (int j2 = 0; j2 < 4; j2++) {
                const uint32_t ob = sw128((wn + j2 * 16 + b_row) * 128 + kb + b_kb);
                LDSM4(bf[j2], st + OFF_BH + ob);
            }
            // Ah*Bh + Al*Bh
#pragma unroll
            for (int j2 = 0; j2 < 4; j2++) {
                mma16816(acc[0][2 * j2 + 0], ah0, bf[j2][0], bf[j2][1]);
                mma16816(acc[0][2 * j2 + 1], ah0, bf[j2][2], bf[j2][3]);
                mma16816(acc[1][2 * j2 + 0], ah1, bf[j2][0], bf[j2][1]);
                mma16816(acc[1][2 * j2 + 1], ah1, bf[j2][2], bf[j2][3]);
                mma16816(acc[0][2 * j2 + 0], al0, bf[j2][0], bf[j2][1]);
                mma16816(acc[0][2 * j2 + 1], al0, bf[j2][2], bf[j2][3]);
                mma16816(acc[1][2 * j2 + 0], al1, bf[j2][0], bf[j2][1]);
                mma16816(acc[1][2 * j2 + 1], al1, bf[j2][2], bf[j2][3]);
            }
            // Ah*Bl
#pragma unroll
            for (int j2 = 0; j2 < 4; j2++) {
                const uint32_t ob = sw128((wn + j2 * 16 + b_row) * 128 + kb + b_kb);
                LDSM4(bf[j2], st + OFF_BL + ob);
            }
#pragma unroll
            for (int j2 = 0; j2 < 4; j2++) {
                mma16816(acc[0][2 * j2 + 0], ah0, bf[j2][0], bf[j2][1]);
                mma16816(acc[0][2 * j2 + 1], ah0, bf[j2][2], bf[j2][3]);
                mma16816(acc[1][2 * j2 + 0], ah1, bf[j2][0], bf[j2][1]);
                mma16816(acc[1][2 * j2 + 1], ah1, bf[j2][2], bf[j2][3]);
            }
        }
        __syncthreads();
        if (c + STAGES < nch) issue_stage(c + STAGES);
    }

    // ---- epilogue: regs -> bias/rowscale/relu -> fp32 and/or bf16-split GMEM ----
#pragma unroll
    for (int i = 0; i < 2; i++) {
        const int r0 = bm + wm + i * 16 + (lane >> 2);
        const int r1 = r0 + 8;
        const float rs0 = rowscale ? (float)rowscale[r0] : 1.f;
        const float rs1 = rowscale ? (float)rowscale[r1] : 1.f;
#pragma unroll
        for (int j = 0; j < 8; j++) {
            const int col = bn + wn + j * 8 + (lane & 3) * 2;
            const float b0 = bias[col], b1 = bias[col + 1];
            float2 v0 = make_float2(acc[i][j][0] + rs0 * b0, acc[i][j][1] + rs0 * b1);
            float2 v1 = make_float2(acc[i][j][2] + rs1 * b0, acc[i][j][3] + rs1 * b1);
            if (RELU) {
                v0.x = fmaxf(v0.x, 0.f); v0.y = fmaxf(v0.y, 0.f);
                v1.x = fmaxf(v1.x, 0.f); v1.y = fmaxf(v1.y, 0.f);
            }
            if (WF32) {
                *reinterpret_cast<float2*>(C + (size_t)r0 * N + col) = v0;
                *reinterpret_cast<float2*>(C + (size_t)r1 * N + col) = v1;
            }
            if (WSPLIT) {
                uint32_t p, q;
                split2(v0.x, v0.y, p, q);
                reinterpret_cast<uint32_t*>(Ch)[((size_t)r0 * N + col) >> 1] = p;
                reinterpret_cast<uint32_t*>(Cl)[((size_t)r0 * N + col) >> 1] = q;
                split2(v1.x, v1.y, p, q);
                reinterpret_cast<uint32_t*>(Ch)[((size_t)r1 * N + col) >> 1] = p;
                reinterpret_cast<uint32_t*>(Cl)[((size_t)r1 * N + col) >> 1] = q;
            }
        }
    }
}

// ---------------- name attention (S=16, 4 heads, dh=192), masked, q-summed ----------------
// writes split bf16 hi/lo directly (consumed only by the out-proj GEMM)
__global__ __launch_bounds__(192) void name_attn_kernel(
    const float* __restrict__ qkv, const int* __restrict__ lens,
    __nv_bfloat16* __restrict__ attn_h, __nv_bfloat16* __restrict__ attn_l)
{
    __shared__ float Qs[LS][DHN];
    __shared__ float Ks[LS][DHN];
    __shared__ float Vs[LS][DHN];
    __shared__ float sc[LS][LS + 1];

    const int h = blockIdx.x;
    const int b = blockIdx.y;
    const int d = threadIdx.x;

    const float* base = qkv + (size_t)b * LS * (3 * DE) + h * DHN + d;
#pragma unroll
    for (int s = 0; s < LS; s++) {
        Qs[s][d] = base[s * (3 * DE)];
        Ks[s][d] = base[s * (3 * DE) + DE];
        Vs[s][d] = base[s * (3 * DE) + 2 * DE];
    }
    __syncthreads();

    const int warp = d >> 5, lane = d & 31;
    const float scale = 1.0f / sqrtf((float)DHN);
    for (int p = warp; p < LS * LS; p += 6) {
        const int q = p >> 4, j = p & 15;
        float s = 0.f;
#pragma unroll
        for (int i = 0; i < 6; i++) s += Qs[q][lane + 32 * i] * Ks[j][lane + 32 * i];
#pragma unroll
        for (int o = 16; o; o >>= 1) s += __shfl_down_sync(0xffffffffu, s, o);
        if (lane == 0) sc[q][j] = s * scale;
    }
    __syncthreads();

    const int len = lens[b];
    if (d < LS) {
        float row[LS];
        float mx = -1e30f;
#pragma unroll
        for (int j = 0; j < LS; j++) {
            row[j] = (j < len) ? sc[d][j] : -1e9f;
            mx = fmaxf(mx, row[j]);
        }
        float sum = 0.f;
#pragma unroll
        for (int j = 0; j < LS; j++) { row[j] = expf(row[j] - mx); sum += row[j]; }
        const float inv = 1.f / sum;
#pragma unroll
        for (int j = 0; j < LS; j++) sc[d][j] = row[j] * inv;
    }
    __syncthreads();

    float accum = 0.f;
    for (int s = 0; s < len; s++) {
        float o = 0.f;
#pragma unroll
        for (int j = 0; j < LS; j++) o += sc[s][j] * Vs[j][d];
        accum += o;
    }
    const float a1 = __shfl_down_sync(0xffffffffu, accum, 1);
    if (!(d & 1)) {
        uint32_t p, q;
        split2(accum, a1, p, q);
        const size_t id2 = ((size_t)b * DE + h * DHN + d) >> 1;
        reinterpret_cast<uint32_t*>(attn_h)[id2] = p;
        reinterpret_cast<uint32_t*>(attn_l)[id2] = q;
    }
}

// ---------------- residual + LayerNorm (in place on h) + bf16 split output ----------------
__device__ __forceinline__ float block_reduce_sum(float v) {
    __shared__ float red[8];
    const int lane = threadIdx.x & 31, warp = threadIdx.x >> 5;
#pragma unroll
    for (int o = 16; o; o >>= 1) v += __shfl_down_sync(0xffffffffu, v, o);
    if (lane == 0) red[warp] = v;
    __syncthreads();
    v = (threadIdx.x < 8) ? red[threadIdx.x] : 0.f;
    if (warp == 0)
#pragma unroll
        for (int o = 4; o; o >>= 1) v += __shfl_down_sync(0xffffffffu, v, o);
    return v;
}

__global__ __launch_bounds__(256) void resid_ln_kernel(
    float* __restrict__ h, const float* __restrict__ a,
    const float* __restrict__ g, const float* __restrict__ b,
    __nv_bfloat16* __restrict__ hh, __nv_bfloat16* __restrict__ hl)
{
    const int row = blockIdx.x;
    const int t = threadIdx.x;
    float v[4];
    float s = 0.f;
#pragma unroll
    for (int i = 0; i < 4; i++) {
        const int c = t + 256 * i;
        v[i] = h[(size_t)row * HD + c] + a[(size_t)row * HD + c];
        s += v[i];
    }
    s = block_reduce_sum(s);
    __shared__ float mean_s, rstd_s;
    if (t == 0) mean_s = s * (1.f / HD);
    __syncthreads();
    const float m = mean_s;
    float s2 = 0.f;
#pragma unroll
    for (int i = 0; i < 4; i++) { const float dd = v[i] - m; s2 += dd * dd; }
    s2 = block_reduce_sum(s2);
    if (t == 0) rstd_s = rsqrtf(s2 * (1.f / HD) + 1e-5f);
    __syncthreads();
    const float r = rstd_s;
#pragma unroll
    for (int i = 0; i < 4; i++) {
        const int c = t + 256 * i;
        const float y = (v[i] - m) * r * g[c] + b[c];
        h[(size_t)row * HD + c] = y;
        const float y1 = __shfl_down_sync(0xffffffffu, y, 1);
        if (!(t & 1)) {
            uint32_t p, q;
            split2(y, y1, p, q);
            const size_t id2 = ((size_t)row * HD + c) >> 1;
            reinterpret_cast<uint32_t*>(hh)[id2] = p;
            reinterpret_cast<uint32_t*>(hl)[id2] = q;
        }
    }
}

// ---------------- classifier head ----------------
__global__ __launch_bounds__(512) void cls_kernel(
    const float* __restrict__ h, const float* __restrict__ w,
    const float* __restrict__ b, float* __restrict__ out)
{
    const int m = blockIdx.x;
    const int c = threadIdx.x >> 5;
    const int lane = threadIdx.x & 31;
    const float* hr = h + (size_t)m * HD;
    const float* wr = w + (size_t)c * HD;
    float s = 0.f;
#pragma unroll
    for (int i = lane; i < HD; i += 32) s += hr[i] * wr[i];
#pragma unroll
    for (int o = 16; o; o >>= 1) s += __shfl_down_sync(0xffffffffu, s, o);
    if (lane == 0) out[(size_t)m * NCLS + c] = s + b[c];
}

// ---------------- orchestration ----------------
static inline void launch_split(const float* src, __nv_bfloat16* hi, __nv_bfloat16* lo, size_t n) {
    const int n2 = (int)(n / 2);
    split_kernel<<<(n2 + 255) / 256, 256>>>(src, hi, lo, n2);
}

extern "C" void kernel_launch(void* const* d_in, const int* in_sizes, int n_in,
                              void* d_out, int out_size)
{
    const int*   name_tokens = (const int*)d_in[0];
    const int*   name_lens   = (const int*)d_in[1];
    const float* x_feats     = (const float*)d_in[2];
    const float* wte         = (const float*)d_in[3];
    const float* mha_in_w    = (const float*)d_in[4];
    const float* mha_in_b    = (const float*)d_in[5];
    const float* mha_out_w   = (const float*)d_in[6];
    const float* mha_out_b   = (const float*)d_in[7];
    const float* bott_w      = (const float*)d_in[8];
    const float* bott_b      = (const float*)d_in[9];
    const float* enc_in_w    = (const float*)d_in[10];
    const float* enc_in_b    = (const float*)d_in[11];
    const float* enc_out_w   = (const float*)d_in[12];
    const float* enc_out_b   = (const float*)d_in[13];
    const float* enc_ln1_g   = (const float*)d_in[14];
    const float* enc_ln1_b   = (const float*)d_in[15];
    const float* enc_ln2_g   = (const float*)d_in[16];
    const float* enc_ln2_b   = (const float*)d_in[17];
    const float* enc_ff1_w   = (const float*)d_in[18];
    const float* enc_ff1_b   = (const float*)d_in[19];
    const float* enc_ff2_w   = (const float*)d_in[20];
    const float* enc_ff2_b   = (const float*)d_in[21];
    const float* cls_w       = (const float*)d_in[22];
    const float* cls_b       = (const float*)d_in[23];
    float* out = (float*)d_out;

    float *qkv, *h, *ta;
    cudaGetSymbolAddress((void**)&qkv, g_qkv);
    cudaGetSymbolAddress((void**)&h,   g_h);
    cudaGetSymbolAddress((void**)&ta,  g_ta);

    __nv_bfloat16 *attn_h, *attn_l, *xf_h, *xf_l, *proj_h, *proj_l, *hh, *hl, *tv_h, *tv_l, *t1_h, *t1_l;
    __nv_bfloat16 *wte_h, *wte_l, *wqkv_h, *wqkv_l, *wout_h, *wout_l, *wbott_h, *wbott_l;
    __nv_bfloat16 *wv_h, *wv_l, *wo_h, *wo_l, *wf1_h, *wf1_l, *wf2_h, *wf2_l;
    cudaGetSymbolAddress((void**)&attn_h, g_attn_h);  cudaGetSymbolAddress((void**)&attn_l, g_attn_l);
    cudaGetSymbolAddress((void**)&xf_h,   g_xf_h);    cudaGetSymbolAddress((void**)&xf_l,   g_xf_l);
    cudaGetSymbolAddress((void**)&proj_h, g_proj_h);  cudaGetSymbolAddress((void**)&proj_l, g_proj_l);
    cudaGetSymbolAddress((void**)&hh,     g_hh);      cudaGetSymbolAddress((void**)&hl,     g_hl);
    cudaGetSymbolAddress((void**)&tv_h,   g_tv_h);    cudaGetSymbolAddress((void**)&tv_l,   g_tv_l);
    cudaGetSymbolAddress((void**)&t1_h,   g_t1_h);    cudaGetSymbolAddress((void**)&t1_l,   g_t1_l);
    cudaGetSymbolAddress((void**)&wte_h,  g_wte_h);   cudaGetSymbolAddress((void**)&wte_l,  g_wte_l);
    cudaGetSymbolAddress((void**)&wqkv_h, g_wqkv_h);  cudaGetSymbolAddress((void**)&wqkv_l, g_wqkv_l);
    cudaGetSymbolAddress((void**)&wout_h, g_wout_h);  cudaGetSymbolAddress((void**)&wout_l, g_wout_l);
    cudaGetSymbolAddress((void**)&wbott_h,g_wbott_h); cudaGetSymbolAddress((void**)&wbott_l,g_wbott_l);
    cudaGetSymbolAddress((void**)&wv_h,   g_wv_h);    cudaGetSymbolAddress((void**)&wv_l,   g_wv_l);
    cudaGetSymbolAddress((void**)&wo_h,   g_wo_h);    cudaGetSymbolAddress((void**)&wo_l,   g_wo_l);
    cudaGetSymbolAddress((void**)&wf1_h,  g_wf1_h);   cudaGetSymbolAddress((void**)&wf1_l,  g_wf1_l);
    cudaGetSymbolAddress((void**)&wf2_h,  g_wf2_h);   cudaGetSymbolAddress((void**)&wf2_l,  g_wf2_l);

    cudaFuncSetAttribute(tgemm_kernel<1, false, true,  false>, cudaFuncAttributeMaxDynamicSharedMemorySize, TG_SMEM);
    cudaFuncSetAttribute(tgemm_kernel<0, false, false, true >, cudaFuncAttributeMaxDynamicSharedMemorySize, TG_SMEM);
    cudaFuncSetAttribute(tgemm_kernel<2, false, true,  true >, cudaFuncAttributeMaxDynamicSharedMemorySize, TG_SMEM);
    cudaFuncSetAttribute(tgemm_kernel<0, false, true,  false>, cudaFuncAttributeMaxDynamicSharedMemorySize, TG_SMEM);
    cudaFuncSetAttribute(tgemm_kernel<0, true,  false, true >, cudaFuncAttributeMaxDynamicSharedMemorySize, TG_SMEM);

    // ---- 0. split all GEMM operand sources to bf16 hi/lo ----
    launch_split(wte,       wte_h,   wte_l,   (size_t)VOCAB * DE);
    launch_split(mha_in_w,  wqkv_h,  wqkv_l,  (size_t)3 * DE * DE);
    launch_split(mha_out_w, wout_h,  wout_l,  (size_t)DE * DE);
    launch_split(bott_w,    wbott_h, wbott_l, (size_t)HD * (XFD + DE));
    launch_split(x_feats,   xf_h,    xf_l,    (size_t)NS * XFD);
    for (int l = 0; l < NLAY; l++) {
        launch_split(enc_in_w + (size_t)l * 3 * HD * HD + (size_t)2 * HD * HD,
                     wv_h + (size_t)l * HD * HD, wv_l + (size_t)l * HD * HD, (size_t)HD * HD);
        launch_split(enc_out_w + (size_t)l * HD * HD,
                     wo_h + (size_t)l * HD * HD, wo_l + (size_t)l * HD * HD, (size_t)HD * HD);
        launch_split(enc_ff1_w + (size_t)l * 2 * HD * HD,
                     wf1_h + (size_t)l * 2 * HD * HD, wf1_l + (size_t)l * 2 * HD * HD, (size_t)2 * HD * HD);
        launch_split(enc_ff2_w + (size_t)l * HD * 2 * HD,
                     wf2_h + (size_t)l * HD * 2 * HD, wf2_l + (size_t)l * HD * 2 * HD, (size_t)HD * 2 * HD);
    }

    const int MQ = NS * LS;          // 65536
    const int KQ = DE;               // 768
    const int NQ = 3 * DE;           // 2304

    // 1. qkv = gather(wte, tokens) @ mha_in_w^T + mha_in_b    [65536 x 2304] fp32
    tgemm_kernel<1, false, true, false><<<dim3(NQ / 128, MQ / 128), 256, TG_SMEM>>>(
        MQ, NQ, KQ, 0, wte_h, wte_l, nullptr, nullptr, name_tokens,
        wqkv_h, wqkv_l, mha_in_b, nullptr, qkv, nullptr, nullptr);

    // 2. masked name attention -> attnsum split [4096 x 768]
    name_attn_kernel<<<dim3(NHN, NS), 192>>>(qkv, name_lens, attn_h, attn_l);

    // 3. name_emb = attnsum @ mha_out_w^T + len * mha_out_b -> proj split [4096 x 768]
    tgemm_kernel<0, false, false, true><<<dim3(DE / 128, NS / 128), 256, TG_SMEM>>>(
        NS, DE, DE, 0, attn_h, attn_l, nullptr, nullptr, nullptr,
        wout_h, wout_l, mha_out_b, name_lens, nullptr, proj_h, proj_l);

    // 4. x = [x_feats | name_emb] @ bott_w^T + bott_b -> h fp32 + split  [4096 x 1024]
    tgemm_kernel<2, false, true, true><<<dim3(HD / 128, NS / 128), 256, TG_SMEM>>>(
        NS, HD, XFD + DE, XFD, xf_h, xf_l, proj_h, proj_l, nullptr,
        wbott_h, wbott_l, bott_b, nullptr, h, hh, hl);

    // 5. encoder layers (seq len 1 => attention == V/out projections only)
    for (int l = 0; l < NLAY; l++) {
        const float* bv = enc_in_b + (size_t)l * 3 * HD + 2 * HD;
        tgemm_kernel<0, false, false, true><<<dim3(HD / 128, NS / 128), 256, TG_SMEM>>>(
            NS, HD, HD, 0, hh, hl, nullptr, nullptr, nullptr,
            wv_h + (size_t)l * HD * HD, wv_l + (size_t)l * HD * HD, bv, nullptr,
            nullptr, tv_h, tv_l);
        tgemm_kernel<0, false, true, false><<<dim3(HD / 128, NS / 128), 256, TG_SMEM>>>(
            NS, HD, HD, 0, tv_h, tv_l, nullptr, nullptr, nullptr,
            wo_h + (size_t)l * HD * HD, wo_l + (size_t)l * HD * HD,
            enc_out_b + (size_t)l * HD, nullptr, ta, nullptr, nullptr);
        resid_ln_kernel<<<NS, 256>>>(h, ta, enc_ln1_g + (size_t)l * HD, enc_ln1_b + (size_t)l * HD, hh, hl);

        tgemm_kernel<0, true, false, true><<<dim3(2 * HD / 128, NS / 128), 256, TG_SMEM>>>(
            NS, 2 * HD, HD, 0, hh, hl, nullptr, nullptr, nullptr,
            wf1_h + (size_t)l * 2 * HD * HD, wf1_l + (size_t)l * 2 * HD * HD,
            enc_ff1_b + (size_t)l * 2 * HD, nullptr, nullptr, t1_h, t1_l);
        tgemm_kernel<0, false, true, false><<<dim3(HD / 128, NS / 128), 256, TG_SMEM>>>(
            NS, HD, 2 * HD, 0, t1_h, t1_l, nullptr, nullptr, nullptr,
            wf2_h + (size_t)l * HD * 2 * HD, wf2_l + (size_t)l * HD * 2 * HD,
            enc_ff2_b + (size_t)l * HD, nullptr, ta, nullptr, nullptr);
        resid_ln_kernel<<<NS, 256>>>(h, ta, enc_ln2_g + (size_t)l * HD, enc_ln2_b + (size_t)l * HD, hh, hl);
    }

    // 6. classifier head -> out [4096 x 16]
    cls_kernel<<<NS, 512>>>(h, cls_w, cls_b, out);
}

// round 6
// speedup vs baseline: 3.7794x; 1.2817x over previous
#include <cuda_runtime.h>
#include <cuda_bf16.h>
#include <cstdint>
#include <math.h>

// ---------------- problem constants ----------------
#define NS    4096          // N samples
#define LS    16            // L tokens
#define DE    768           // D embedding
#define NHN   4             // heads (name attn)
#define DHN   192           // head dim (name attn)
#define HD    1024          // H
#define NLAY  4             // NL
#define NCLS  16            // C
#define XFD   256           // XF

// ---------------- scratch (device globals; no cudaMalloc allowed) ----------------
__device__ float g_qkv[(size_t)NS * LS * 3 * DE];   // compacted qkv rows, fp32 (for attn)
__device__ float g_h[(size_t)NS * HD];              // fp32 residual stream
__device__ float g_ta[(size_t)NS * HD];             // fp32 (LN input)

__device__ int g_off[NS + 1];                       // exclusive prefix of name_lens
__device__ int g_total[1];                          // sum of name_lens
__device__ int g_rowtok[NS * LS];                   // compact row -> token id

// bf16 hi/lo split buffers (activations)
__device__ __align__(16) __nv_bfloat16 g_gah[(size_t)NS * LS * DE],   g_gal[(size_t)NS * LS * DE]; // gathered emb (compact)
__device__ __align__(16) __nv_bfloat16 g_attn_h[(size_t)NS * DE],     g_attn_l[(size_t)NS * DE];
__device__ __align__(16) __nv_bfloat16 g_xf_h[(size_t)NS * XFD],      g_xf_l[(size_t)NS * XFD];
__device__ __align__(16) __nv_bfloat16 g_proj_h[(size_t)NS * DE],     g_proj_l[(size_t)NS * DE];
__device__ __align__(16) __nv_bfloat16 g_hh[(size_t)NS * HD],         g_hl[(size_t)NS * HD];
__device__ __align__(16) __nv_bfloat16 g_tv_h[(size_t)NS * HD],       g_tv_l[(size_t)NS * HD];
__device__ __align__(16) __nv_bfloat16 g_t1_h[(size_t)NS * 2 * HD],   g_t1_l[(size_t)NS * 2 * HD];

// bf16 hi/lo split buffers (weights)
__device__ __align__(16) __nv_bfloat16 g_wqkv_h[(size_t)3 * DE * DE], g_wqkv_l[(size_t)3 * DE * DE];
__device__ __align__(16) __nv_bfloat16 g_wout_h[(size_t)DE * DE],     g_wout_l[(size_t)DE * DE];
__device__ __align__(16) __nv_bfloat16 g_wbott_h[(size_t)HD * (XFD + DE)], g_wbott_l[(size_t)HD * (XFD + DE)];
__device__ __align__(16) __nv_bfloat16 g_wv_h[(size_t)NLAY * HD * HD],  g_wv_l[(size_t)NLAY * HD * HD];
__device__ __align__(16) __nv_bfloat16 g_wo_h[(size_t)NLAY * HD * HD],  g_wo_l[(size_t)NLAY * HD * HD];
__device__ __align__(16) __nv_bfloat16 g_wf1_h[(size_t)NLAY * 2 * HD * HD], g_wf1_l[(size_t)NLAY * 2 * HD * HD];
__device__ __align__(16) __nv_bfloat16 g_wf2_h[(size_t)NLAY * HD * 2 * HD], g_wf2_l[(size_t)NLAY * HD * 2 * HD];

// ================= helpers =================
__device__ __forceinline__ uint32_t smem_u32(const void* p) {
    uint32_t a;
    asm("{ .reg .u64 t; cvta.to.shared.u64 t, %1; cvt.u32.u64 %0, t; }" : "=r"(a) : "l"(p));
    return a;
}
__device__ __forceinline__ uint32_t sw128(uint32_t o) { return o ^ ((o >> 3) & 0x70); }

#define LDSM4(r, addr) \
    asm volatile("ldmatrix.sync.aligned.m8n8.x4.shared.b16 {%0,%1,%2,%3}, [%4];" \
        : "=r"((r)[0]), "=r"((r)[1]), "=r"((r)[2]), "=r"((r)[3]) : "r"(addr))

__device__ __forceinline__ void mma16816(float* c, const uint32_t* a, uint32_t b0, uint32_t b1) {
    asm volatile("mma.sync.aligned.m16n8k16.row.col.f32.bf16.bf16.f32 "
        "{%0,%1,%2,%3},{%4,%5,%6,%7},{%8,%9},{%0,%1,%2,%3};"
        : "+f"(c[0]), "+f"(c[1]), "+f"(c[2]), "+f"(c[3])
        : "r"(a[0]), "r"(a[1]), "r"(a[2]), "r"(a[3]), "r"(b0), "r"(b1));
}

#define CP_ASYNC16(dst, src) \
    asm volatile("cp.async.cg.shared.global [%0], [%1], 16;" :: "r"(dst), "l"(src))
#define CP_COMMIT() asm volatile("cp.async.commit_group;" ::: "memory")
#define CP_WAIT(n)  asm volatile("cp.async.wait_group %0;" :: "n"(n) : "memory")

// split fp32 pair -> packed bf16 hi (p) and lo residual (q). p = {lo16=bf16(x), hi16=bf16(y)}
__device__ __forceinline__ void split2(float x, float y, uint32_t& p, uint32_t& q) {
    asm("cvt.rn.bf16x2.f32 %0, %1, %2;" : "=r"(p) : "f"(y), "f"(x));
    float h0 = __uint_as_float(p << 16);
    float h1 = __uint_as_float(p & 0xffff0000u);
    float r0 = x - h0, r1 = y - h1;
    asm("cvt.rn.bf16x2.f32 %0, %1, %2;" : "=r"(q) : "f"(r1), "f"(r0));
}

// ---------------- fp32 -> bf16 hi/lo split (elementwise, n2 = n/2 pairs) ----------------
__global__ __launch_bounds__(256) void split_kernel(
    const float* __restrict__ src,
    __nv_bfloat16* __restrict__ hi, __nv_bfloat16* __restrict__ lo, int n2)
{
    const int i = blockIdx.x * blockDim.x + threadIdx.x;
    if (i < n2) {
        const float2 v = reinterpret_cast<const float2*>(src)[i];
        uint32_t p, q;
        split2(v.x, v.y, p, q);
        reinterpret_cast<uint32_t*>(hi)[i] = p;
        reinterpret_cast<uint32_t*>(lo)[i] = q;
    }
}

// ---------------- compaction: exclusive scan of name_lens (NS = 4096 = 1024 x 4) ----------------
__global__ __launch_bounds__(1024) void scan_kernel(
    const int* __restrict__ lens, int* __restrict__ off, int* __restrict__ total)
{
    __shared__ int wsum[32];
    const int tid = threadIdx.x, lane = tid & 31, warp = tid >> 5;
    int v[4], s = 0;
#pragma unroll
    for (int i = 0; i < 4; i++) { v[i] = lens[tid * 4 + i]; s += v[i]; }
    int ws = s;
#pragma unroll
    for (int o = 1; o < 32; o <<= 1) { int t = __shfl_up_sync(0xffffffffu, ws, o); if (lane >= o) ws += t; }
    if (lane == 31) wsum[warp] = ws;
    __syncthreads();
    if (warp == 0) {
        int t = wsum[lane];
#pragma unroll
        for (int o = 1; o < 32; o <<= 1) { int u = __shfl_up_sync(0xffffffffu, t, o); if (lane >= o) t += u; }
        wsum[lane] = t;
    }
    __syncthreads();
    int run = ws - s + (warp ? wsum[warp - 1] : 0);
#pragma unroll
    for (int i = 0; i < 4; i++) { off[tid * 4 + i] = run; run += v[i]; }
    if (tid == 1023) { off[NS] = run; total[0] = run; }
}

// one block per sample: write compact row -> token id
__global__ __launch_bounds__(32) void fill_rows_kernel(
    const int* __restrict__ lens, const int* __restrict__ off,
    const int* __restrict__ toks, int* __restrict__ rowtok)
{
    const int b = blockIdx.x;
    const int len = lens[b], o = off[b];
    for (int s = threadIdx.x; s < len; s += 32) rowtok[o + s] = toks[b * LS + s];
}

// gather wte rows for compact tokens + bf16 hi/lo split, fused
__global__ __launch_bounds__(128) void gather_split_kernel(
    const float* __restrict__ wte, const int* __restrict__ rowtok,
    const int* __restrict__ total,
    __nv_bfloat16* __restrict__ Ah, __nv_bfloat16* __restrict__ Al)
{
    const int r = blockIdx.x;
    if (r >= total[0]) return;
    const float2* src = reinterpret_cast<const float2*>(wte + (size_t)rowtok[r] * DE);
    uint32_t* dh = reinterpret_cast<uint32_t*>(Ah) + (size_t)r * (DE / 2);
    uint32_t* dl = reinterpret_cast<uint32_t*>(Al) + (size_t)r * (DE / 2);
#pragma unroll
    for (int i = 0; i < 3; i++) {
        const int j = threadIdx.x + 128 * i;
        const float2 v = src[j];
        uint32_t p, q;
        split2(v.x, v.y, p, q);
        dh[j] = p; dl[j] = q;
    }
}

// ================= HMMA GEMM: C[M,N] = A[M,K] @ B[N,K]^T + bias =================
// A/B pre-split into bf16 hi/lo. 3-term: C = Ah*Bh + Ah*Bl + Al*Bh.
// AMODE: 0 direct, 2 concat A|A2 at K1 (K1 % 64 == 0)
// MDYN: effective M read from device global; CTAs beyond it exit.
#define CHUNK  64
#define STAGES 3
#define STG_BYTES 65536          // 4 tiles x 16KB (Ah,Al,Bh,Bl; 128 rows x 128B)
#define OFF_AH 0
#define OFF_AL 16384
#define OFF_BH 32768
#define OFF_BL 49152
#define TG_SMEM  (STAGES * STG_BYTES + 512)

template<int AMODE, bool RELU, bool WF32, bool WSPLIT, bool MDYN>
__global__ __launch_bounds__(256, 1) void tgemm_kernel(
    int M, int N, int K, int K1,
    const __nv_bfloat16* __restrict__ Ah, const __nv_bfloat16* __restrict__ Al,
    const __nv_bfloat16* __restrict__ A2h, const __nv_bfloat16* __restrict__ A2l,
    const int* __restrict__ Mlim,
    const __nv_bfloat16* __restrict__ Bh, const __nv_bfloat16* __restrict__ Bl,
    const float* __restrict__ bias,
    const int* __restrict__ rowscale,
    float* __restrict__ C,
    __nv_bfloat16* __restrict__ Ch, __nv_bfloat16* __restrict__ Cl)
{
    extern __shared__ char smem[];
    const uint32_t sb = smem_u32(smem);

    const int tid  = threadIdx.x;
    const int lane = tid & 31;
    const int wid  = tid >> 5;
    const int bm = blockIdx.y * 128, bn = blockIdx.x * 128;

    int Mtot = M;
    if (MDYN) {
        Mtot = Mlim[0];
        if (bm >= Mtot) return;
    }

    const int nch = K / CHUNK;

    auto issue_stage = [&](int c) {
        const int k0 = c * CHUNK;
        const uint32_t st = sb + (c % STAGES) * STG_BYTES;
#pragma unroll
        for (int i = 0; i < 4; i++) {
            const int idx = tid + 256 * i;        // 0..1023
            const int row = idx >> 3;             // 0..127
            const int seg = idx & 7;              // 16B segment
            const uint32_t sw = sw128(row * 128 + seg * 16);
            int ar = bm + row;
            if (MDYN && ar >= Mtot) ar = Mtot - 1;
            const __nv_bfloat16 *pah, *pal;
            if (AMODE == 2) {
                if (k0 < K1) {
                    const size_t off = (size_t)ar * K1 + k0 + seg * 8;
                    pah = Ah + off; pal = Al + off;
                } else {
                    const size_t off = (size_t)ar * (K - K1) + (k0 - K1) + seg * 8;
                    pah = A2h + off; pal = A2l + off;
                }
            } else {
                const size_t off = (size_t)ar * K + k0 + seg * 8;
                pah = Ah + off; pal = Al + off;
            }
            CP_ASYNC16(st + OFF_AH + sw, pah);
            CP_ASYNC16(st + OFF_AL + sw, pal);
            const size_t boff = (size_t)(bn + row) * K + k0 + seg * 8;
            CP_ASYNC16(st + OFF_BH + sw, Bh + boff);
            CP_ASYNC16(st + OFF_BL + sw, Bl + boff);
        }
        CP_COMMIT();
    };

    // prologue: fill the pipeline (all our K have nch >= 3)
#pragma unroll
    for (int s = 0; s < STAGES; s++)
        if (s < nch) issue_stage(s);

    // warp tile: 32 (M) x 64 (N); warps laid out 4 (M) x 2 (N)
    const int wm = (wid >> 1) * 32;
    const int wn = (wid & 1) * 64;

    float acc[2][8][4];
#pragma unroll
    for (int i = 0; i < 2; i++)
#pragma unroll
        for (int j = 0; j < 8; j++)
#pragma unroll
            for (int t = 0; t < 4; t++) acc[i][j][t] = 0.f;

    const int a_row  = (lane & 15);
    const int a_kb   = (lane >> 4) * 16;
    const int b_row  = (lane & 7) + ((lane >> 4) << 3);
    const int b_kb   = ((lane >> 3) & 1) * 16;

    for (int c = 0; c < nch; c++) {
        if (c == nch - 1) { CP_WAIT(0); } else { CP_WAIT(1); }
        __syncthreads();

        const uint32_t st = sb + (c % STAGES) * STG_BYTES;

#pragma unroll
        for (int ks = 0; ks < 4; ks++) {
            const int kb = ks * 32;
            uint32_t ah0[4], ah1[4], al0[4], al1[4];
            {
                const uint32_t o0 = sw128((wm + a_row) * 128 + kb + a_kb);
                const uint32_t o1 = sw128((wm + 16 + a_row) * 128 + kb + a_kb);
                LDSM4(ah0, st + OFF_AH + o0);
                LDSM4(ah1, st + OFF_AH + o1);
                LDSM4(al0, st + OFF_AL + o0);
                LDSM4(al1, st + OFF_AL + o1);
            }
            uint32_t bf[4][4];
#pragma unroll
            for (int j2 = 0; j2 < 4; j2++) {
                const uint32_t ob = sw128((wn + j2 * 16 + b_row) * 128 + kb + b_kb);
                LDSM4(bf[j2], st + OFF_BH + ob);
            }
            // Ah*Bh + Al*Bh
#pragma unroll
            for (int j2 = 0; j2 < 4; j2++) {
                mma16816(acc[0][2 * j2 + 0], ah0, bf[j2][0], bf[j2][1]);
                mma16816(acc[0][2 * j2 + 1], ah0, bf[j2][2], bf[j2][3]);
                mma16816(acc[1][2 * j2 + 0], ah1, bf[j2][0], bf[j2][1]);
                mma16816(acc[1][2 * j2 + 1], ah1, bf[j2][2], bf[j2][3]);
                mma16816(acc[0][2 * j2 + 0], al0, bf[j2][0], bf[j2][1]);
                mma16816(acc[0][2 * j2 + 1], al0, bf[j2][2], bf[j2][3]);
                mma16816(acc[1][2 * j2 + 0], al1, bf[j2][0], bf[j2][1]);
                mma16816(acc[1][2 * j2 + 1], al1, bf[j2][2], bf[j2][3]);
            }
            // Ah*Bl
#pragma unroll
            for (int j2 = 0; j2 < 4; j2++) {
                const uint32_t ob = sw128((wn + j2 * 16 + b_row) * 128 + kb + b_kb);
                LDSM4(bf[j2], st + OFF_BL + ob);
            }
#pragma unroll
            for (int j2 = 0; j2 < 4; j2++) {
                mma16816(acc[0][2 * j2 + 0], ah0, bf[j2][0], bf[j2][1]);
                mma16816(acc[0][2 * j2 + 1], ah0, bf[j2][2], bf[j2][3]);
                mma16816(acc[1][2 * j2 + 0], ah1, bf[j2][0], bf[j2][1]);
                mma16816(acc[1][2 * j2 + 1], ah1, bf[j2][2], bf[j2][3]);
            }
        }
        __syncthreads();
        if (c + STAGES < nch) issue_stage(c + STAGES);
    }

    // ---- epilogue: regs -> bias/rowscale/relu -> fp32 and/or bf16-split GMEM ----
#pragma unroll
    for (int i = 0; i < 2; i++) {
        const int r0 = bm + wm + i * 16 + (lane >> 2);
        const int r1 = r0 + 8;
        const bool ok0 = !MDYN || (r0 < Mtot);
        const bool ok1 = !MDYN || (r1 < Mtot);
        const float rs0 = rowscale ? (float)rowscale[r0] : 1.f;
        const float rs1 = rowscale ? (float)rowscale[r1] : 1.f;
#pragma unroll
        for (int j = 0; j < 8; j++) {
            const int col = bn + wn + j * 8 + (lane & 3) * 2;
            const float b0 = bias[col], b1 = bias[col + 1];
            float2 v0 = make_float2(acc[i][j][0] + rs0 * b0, acc[i][j][1] + rs0 * b1);
            float2 v1 = make_float2(acc[i][j][2] + rs1 * b0, acc[i][j][3] + rs1 * b1);
            if (RELU) {
                v0.x = fmaxf(v0.x, 0.f); v0.y = fmaxf(v0.y, 0.f);
                v1.x = fmaxf(v1.x, 0.f); v1.y = fmaxf(v1.y, 0.f);
            }
            if (WF32) {
                if (ok0) *reinterpret_cast<float2*>(C + (size_t)r0 * N + col) = v0;
                if (ok1) *reinterpret_cast<float2*>(C + (size_t)r1 * N + col) = v1;
            }
            if (WSPLIT) {
                uint32_t p, q;
                if (ok0) {
                    split2(v0.x, v0.y, p, q);
                    reinterpret_cast<uint32_t*>(Ch)[((size_t)r0 * N + col) >> 1] = p;
                    reinterpret_cast<uint32_t*>(Cl)[((size_t)r0 * N + col) >> 1] = q;
                }
                if (ok1) {
                    split2(v1.x, v1.y, p, q);
                    reinterpret_cast<uint32_t*>(Ch)[((size_t)r1 * N + col) >> 1] = p;
                    reinterpret_cast<uint32_t*>(Cl)[((size_t)r1 * N + col) >> 1] = q;
                }
            }
        }
    }
}

// ---------------- name attention on compacted qkv (all rows valid), q-summed ----------------
__global__ __launch_bounds__(192) void name_attn_kernel(
    const float* __restrict__ qkv, const int* __restrict__ off,
    __nv_bfloat16* __restrict__ attn_h, __nv_bfloat16* __restrict__ attn_l)
{
    __shared__ float Qs[LS][DHN];
    __shared__ float Ks[LS][DHN];
    __shared__ float Vs[LS][DHN];
    __shared__ float sc[LS][LS + 1];

    const int h = blockIdx.x;
    const int b = blockIdx.y;
    const int d = threadIdx.x;

    const int o   = off[b];
    const int len = off[b + 1] - o;

    const float* base = qkv + (size_t)o * (3 * DE) + h * DHN + d;
    for (int s = 0; s < len; s++) {
        Qs[s][d] = base[s * (3 * DE)];
        Ks[s][d] = base[s * (3 * DE) + DE];
        Vs[s][d] = base[s * (3 * DE) + 2 * DE];
    }
    __syncthreads();

    const int warp = d >> 5, lane = d & 31;
    const float scale = 1.0f / sqrtf((float)DHN);
    const int np = len * len;
    for (int p = warp; p < np; p += 6) {
        const int q = p / len, j = p - q * len;
        float s = 0.f;
#pragma unroll
        for (int i = 0; i < 6; i++) s += Qs[q][lane + 32 * i] * Ks[j][lane + 32 * i];
#pragma unroll
        for (int ofs = 16; ofs; ofs >>= 1) s += __shfl_down_sync(0xffffffffu, s, ofs);
        if (lane == 0) sc[q][j] = s * scale;
    }
    __syncthreads();

    if (d < len) {
        float mx = -1e30f;
        for (int j = 0; j < len; j++) mx = fmaxf(mx, sc[d][j]);
        float sum = 0.f;
        float row[LS];
        for (int j = 0; j < len; j++) { row[j] = expf(sc[d][j] - mx); sum += row[j]; }
        const float inv = 1.f / sum;
        for (int j = 0; j < len; j++) sc[d][j] = row[j] * inv;
    }
    __syncthreads();

    float accum = 0.f;
    for (int s = 0; s < len; s++) {
        float ov = 0.f;
        for (int j = 0; j < len; j++) ov += sc[s][j] * Vs[j][d];
        accum += ov;
    }
    const float a1 = __shfl_down_sync(0xffffffffu, accum, 1);
    if (!(d & 1)) {
        uint32_t p, q;
        split2(accum, a1, p, q);
        const size_t id2 = ((size_t)b * DE + h * DHN + d) >> 1;
        reinterpret_cast<uint32_t*>(attn_h)[id2] = p;
        reinterpret_cast<uint32_t*>(attn_l)[id2] = q;
    }
}

// ---------------- residual + LayerNorm (in place on h) + bf16 split output ----------------
__device__ __forceinline__ float block_reduce_sum(float v) {
    __shared__ float red[8];
    const int lane = threadIdx.x & 31, warp = threadIdx.x >> 5;
#pragma unroll
    for (int o = 16; o; o >>= 1) v += __shfl_down_sync(0xffffffffu, v, o);
    if (lane == 0) red[warp] = v;
    __syncthreads();
    v = (threadIdx.x < 8) ? red[threadIdx.x] : 0.f;
    if (warp == 0)
#pragma unroll
        for (int o = 4; o; o >>= 1) v += __shfl_down_sync(0xffffffffu, v, o);
    return v;
}

__global__ __launch_bounds__(256) void resid_ln_kernel(
    float* __restrict__ h, const float* __restrict__ a,
    const float* __restrict__ g, const float* __restrict__ b,
    __nv_bfloat16* __restrict__ hh, __nv_bfloat16* __restrict__ hl)
{
    const int row = blockIdx.x;
    const int t = threadIdx.x;
    float v[4];
    float s = 0.f;
#pragma unroll
    for (int i = 0; i < 4; i++) {
        const int c = t + 256 * i;
        v[i] = h[(size_t)row * HD + c] + a[(size_t)row * HD + c];
        s += v[i];
    }
    s = block_reduce_sum(s);
    __shared__ float mean_s, rstd_s;
    if (t == 0) mean_s = s * (1.f / HD);
    __syncthreads();
    const float m = mean_s;
    float s2 = 0.f;
#pragma unroll
    for (int i = 0; i < 4; i++) { const float dd = v[i] - m; s2 += dd * dd; }
    s2 = block_reduce_sum(s2);
    if (t == 0) rstd_s = rsqrtf(s2 * (1.f / HD) + 1e-5f);
    __syncthreads();
    const float r = rstd_s;
#pragma unroll
    for (int i = 0; i < 4; i++) {
        const int c = t + 256 * i;
        const float y = (v[i] - m) * r * g[c] + b[c];
        h[(size_t)row * HD + c] = y;
        const float y1 = __shfl_down_sync(0xffffffffu, y, 1);
        if (!(t & 1)) {
            uint32_t p, q;
            split2(y, y1, p, q);
            const size_t id2 = ((size_t)row * HD + c) >> 1;
            reinterpret_cast<uint32_t*>(hh)[id2] = p;
            reinterpret_cast<uint32_t*>(hl)[id2] = q;
        }
    }
}

// ---------------- classifier head ----------------
__global__ __launch_bounds__(512) void cls_kernel(
    const float* __restrict__ h, const float* __restrict__ w,
    const float* __restrict__ b, float* __restrict__ out)
{
    const int m = blockIdx.x;
    const int c = threadIdx.x >> 5;
    const int lane = threadIdx.x & 31;
    const float* hr = h + (size_t)m * HD;
    const float* wr = w + (size_t)c * HD;
    float s = 0.f;
#pragma unroll
    for (int i = lane; i < HD; i += 32) s += hr[i] * wr[i];
#pragma unroll
    for (int o = 16; o; o >>= 1) s += __shfl_down_sync(0xffffffffu, s, o);
    if (lane == 0) out[(size_t)m * NCLS + c] = s + b[c];
}

// ---------------- orchestration ----------------
static inline void launch_split(const float* src, __nv_bfloat16* hi, __nv_bfloat16* lo, size_t n) {
    const int n2 = (int)(n / 2);
    split_kernel<<<(n2 + 255) / 256, 256>>>(src, hi, lo, n2);
}

extern "C" void kernel_launch(void* const* d_in, const int* in_sizes, int n_in,
                              void* d_out, int out_size)
{
    const int*   name_tokens = (const int*)d_in[0];
    const int*   name_lens   = (const int*)d_in[1];
    const float* x_feats     = (const float*)d_in[2];
    const float* wte         = (const float*)d_in[3];
    const float* mha_in_w    = (const float*)d_in[4];
    const float* mha_in_b    = (const float*)d_in[5];
    const float* mha_out_w   = (const float*)d_in[6];
    const float* mha_out_b   = (const float*)d_in[7];
    const float* bott_w      = (const float*)d_in[8];
    const float* bott_b      = (const float*)d_in[9];
    const float* enc_in_w    = (const float*)d_in[10];
    const float* enc_in_b    = (const float*)d_in[11];
    const float* enc_out_w   = (const float*)d_in[12];
    const float* enc_out_b   = (const float*)d_in[13];
    const float* enc_ln1_g   = (const float*)d_in[14];
    const float* enc_ln1_b   = (const float*)d_in[15];
    const float* enc_ln2_g   = (const float*)d_in[16];
    const float* enc_ln2_b   = (const float*)d_in[17];
    const float* enc_ff1_w   = (const float*)d_in[18];
    const float* enc_ff1_b   = (const float*)d_in[19];
    const float* enc_ff2_w   = (const float*)d_in[20];
    const float* enc_ff2_b   = (const float*)d_in[21];
    const float* cls_w       = (const float*)d_in[22];
    const float* cls_b       = (const float*)d_in[23];
    float* out = (float*)d_out;

    float *qkv, *h, *ta;
    int *off, *total, *rowtok;
    cudaGetSymbolAddress((void**)&qkv,    g_qkv);
    cudaGetSymbolAddress((void**)&h,      g_h);
    cudaGetSymbolAddress((void**)&ta,     g_ta);
    cudaGetSymbolAddress((void**)&off,    g_off);
    cudaGetSymbolAddress((void**)&total,  g_total);
    cudaGetSymbolAddress((void**)&rowtok, g_rowtok);

    __nv_bfloat16 *gah, *gal, *attn_h, *attn_l, *xf_h, *xf_l, *proj_h, *proj_l, *hh, *hl, *tv_h, *tv_l, *t1_h, *t1_l;
    __nv_bfloat16 *wqkv_h, *wqkv_l, *wout_h, *wout_l, *wbott_h, *wbott_l;
    __nv_bfloat16 *wv_h, *wv_l, *wo_h, *wo_l, *wf1_h, *wf1_l, *wf2_h, *wf2_l;
    cudaGetSymbolAddress((void**)&gah,    g_gah);     cudaGetSymbolAddress((void**)&gal,    g_gal);
    cudaGetSymbolAddress((void**)&attn_h, g_attn_h);  cudaGetSymbolAddress((void**)&attn_l, g_attn_l);
    cudaGetSymbolAddress((void**)&xf_h,   g_xf_h);    cudaGetSymbolAddress((void**)&xf_l,   g_xf_l);
    cudaGetSymbolAddress((void**)&proj_h, g_proj_h);  cudaGetSymbolAddress((void**)&proj_l, g_proj_l);
    cudaGetSymbolAddress((void**)&hh,     g_hh);      cudaGetSymbolAddress((void**)&hl,     g_hl);
    cudaGetSymbolAddress((void**)&tv_h,   g_tv_h);    cudaGetSymbolAddress((void**)&tv_l,   g_tv_l);
    cudaGetSymbolAddress((void**)&t1_h,   g_t1_h);    cudaGetSymbolAddress((void**)&t1_l,   g_t1_l);
    cudaGetSymbolAddress((void**)&wqkv_h, g_wqkv_h);  cudaGetSymbolAddress((void**)&wqkv_l, g_wqkv_l);
    cudaGetSymbolAddress((void**)&wout_h, g_wout_h);  cudaGetSymbolAddress((void**)&wout_l, g_wout_l);
    cudaGetSymbolAddress((void**)&wbott_h,g_wbott_h); cudaGetSymbolAddress((void**)&wbott_l,g_wbott_l);
    cudaGetSymbolAddress((void**)&wv_h,   g_wv_h);    cudaGetSymbolAddress((void**)&wv_l,   g_wv_l);
    cudaGetSymbolAddress((void**)&wo_h,   g_wo_h);    cudaGetSymbolAddress((void**)&wo_l,   g_wo_l);
    cudaGetSymbolAddress((void**)&wf1_h,  g_wf1_h);   cudaGetSymbolAddress((void**)&wf1_l,  g_wf1_l);
    cudaGetSymbolAddress((void**)&wf2_h,  g_wf2_h);   cudaGetSymbolAddress((void**)&wf2_l,  g_wf2_l);

    cudaFuncSetAttribute(tgemm_kernel<0, false, true,  false, true >, cudaFuncAttributeMaxDynamicSharedMemorySize, TG_SMEM);
    cudaFuncSetAttribute(tgemm_kernel<0, false, false, true,  false>, cudaFuncAttributeMaxDynamicSharedMemorySize, TG_SMEM);
    cudaFuncSetAttribute(tgemm_kernel<2, false, true,  true,  false>, cudaFuncAttributeMaxDynamicSharedMemorySize, TG_SMEM);
    cudaFuncSetAttribute(tgemm_kernel<0, false, true,  false, false>, cudaFuncAttributeMaxDynamicSharedMemorySize, TG_SMEM);
    cudaFuncSetAttribute(tgemm_kernel<0, true,  false, true,  false>, cudaFuncAttributeMaxDynamicSharedMemorySize, TG_SMEM);

    // ---- 0a. compaction metadata ----
    scan_kernel<<<1, 1024>>>(name_lens, off, total);
    fill_rows_kernel<<<NS, 32>>>(name_lens, off, name_tokens, rowtok);
    // ---- 0b. gathered embedding split (compact rows only) ----
    gather_split_kernel<<<NS * LS, 128>>>(wte, rowtok, total, gah, gal);

    // ---- 0c. split weights + x_feats to bf16 hi/lo ----
    launch_split(mha_in_w,  wqkv_h,  wqkv_l,  (size_t)3 * DE * DE);
    launch_split(mha_out_w, wout_h,  wout_l,  (size_t)DE * DE);
    launch_split(bott_w,    wbott_h, wbott_l, (size_t)HD * (XFD + DE));
    launch_split(x_feats,   xf_h,    xf_l,    (size_t)NS * XFD);
    for (int l = 0; l < NLAY; l++) {
        launch_split(enc_in_w + (size_t)l * 3 * HD * HD + (size_t)2 * HD * HD,
                     wv_h + (size_t)l * HD * HD, wv_l + (size_t)l * HD * HD, (size_t)HD * HD);
        launch_split(enc_out_w + (size_t)l * HD * HD,
                     wo_h + (size_t)l * HD * HD, wo_l + (size_t)l * HD * HD, (size_t)HD * HD);
        launch_split(enc_ff1_w + (size_t)l * 2 * HD * HD,
                     wf1_h + (size_t)l * 2 * HD * HD, wf1_l + (size_t)l * 2 * HD * HD, (size_t)2 * HD * HD);
        launch_split(enc_ff2_w + (size_t)l * HD * 2 * HD,
                     wf2_h + (size_t)l * HD * 2 * HD, wf2_l + (size_t)l * HD * 2 * HD, (size_t)HD * 2 * HD);
    }

    const int MQ = NS * LS;          // 65536 (upper bound; effective M read on device)
    const int KQ = DE;               // 768
    const int NQ = 3 * DE;           // 2304

    // 1. qkv(compact) = gathered_emb @ mha_in_w^T + mha_in_b   [<=65536 x 2304] fp32
    tgemm_kernel<0, false, true, false, true><<<dim3(NQ / 128, MQ / 128), 256, TG_SMEM>>>(
        MQ, NQ, KQ, 0, gah, gal, nullptr, nullptr, total,
        wqkv_h, wqkv_l, mha_in_b, nullptr, qkv, nullptr, nullptr);

    // 2. name attention on compact rows -> attnsum split [4096 x 768]
    name_attn_kernel<<<dim3(NHN, NS), 192>>>(qkv, off, attn_h, attn_l);

    // 3. name_emb = attnsum @ mha_out_w^T + len * mha_out_b -> proj split [4096 x 768]
    tgemm_kernel<0, false, false, true, false><<<dim3(DE / 128, NS / 128), 256, TG_SMEM>>>(
        NS, DE, DE, 0, attn_h, attn_l, nullptr, nullptr, nullptr,
        wout_h, wout_l, mha_out_b, name_lens, nullptr, proj_h, proj_l);

    // 4. x = [x_feats | name_emb] @ bott_w^T + bott_b -> h fp32 + split  [4096 x 1024]
    tgemm_kernel<2, false, true, true, false><<<dim3(HD / 128, NS / 128), 256, TG_SMEM>>>(
        NS, HD, XFD + DE, XFD, xf_h, xf_l, proj_h, proj_l, nullptr,
        wbott_h, wbott_l, bott_b, nullptr, h, hh, hl);

    // 5. encoder layers (seq len 1 => attention == V/out projections only)
    for (int l = 0; l < NLAY; l++) {
        const float* bv = enc_in_b + (size_t)l * 3 * HD + 2 * HD;
        tgemm_kernel<0, false, false, true, false><<<dim3(HD / 128, NS / 128), 256, TG_SMEM>>>(
            NS, HD, HD, 0, hh, hl, nullptr, nullptr, nullptr,
            wv_h + (size_t)l * HD * HD, wv_l + (size_t)l * HD * HD, bv, nullptr,
            nullptr, tv_h, tv_l);
        tgemm_kernel<0, false, true, false, false><<<dim3(HD / 128, NS / 128), 256, TG_SMEM>>>(
            NS, HD, HD, 0, tv_h, tv_l, nullptr, nullptr, nullptr,
            wo_h + (size_t)l * HD * HD, wo_l + (size_t)l * HD * HD,
            enc_out_b + (size_t)l * HD, nullptr, ta, nullptr, nullptr);
        resid_ln_kernel<<<NS, 256>>>(h, ta, enc_ln1_g + (size_t)l * HD, enc_ln1_b + (size_t)l * HD, hh, hl);

        tgemm_kernel<0, true, false, true, false><<<dim3(2 * HD / 128, NS / 128), 256, TG_SMEM>>>(
            NS, 2 * HD, HD, 0, hh, hl, nullptr, nullptr, nullptr,
            wf1_h + (size_t)l * 2 * HD * HD, wf1_l + (size_t)l * 2 * HD * HD,
            enc_ff1_b + (size_t)l * 2 * HD, nullptr, nullptr, t1_h, t1_l);
        tgemm_kernel<0, false, true, false, false><<<dim3(HD / 128, NS / 128), 256, TG_SMEM>>>(
            NS, HD, 2 * HD, 0, t1_h, t1_l, nullptr, nullptr, nullptr,
            wf2_h + (size_t)l * HD * 2 * HD, wf2_l + (size_t)l * HD * 2 * HD,
            enc_ff2_b + (size_t)l * HD, nullptr, ta, nullptr, nullptr);
        resid_ln_kernel<<<NS, 256>>>(h, ta, enc_ln2_g + (size_t)l * HD, enc_ln2_b + (size_t)l * HD, hh, hl);
    }

    // 6. classifier head -> out [4096 x 16]
    cls_kernel<<<NS, 512>>>(h, cls_w, cls_b, out);
}

// round 7
// speedup vs baseline: 4.1266x; 1.0919x over previous
#include <cuda_runtime.h>
#include <cuda_bf16.h>
#include <cstdint>
#include <math.h>

// ---------------- problem constants ----------------
#define NS    4096          // N samples
#define LS    16            // L tokens
#define DE    768           // D embedding
#define NHN   4             // heads (name attn)
#define DHN   192           // head dim (name attn)
#define HD    1024          // H
#define NLAY  4             // NL
#define NCLS  16            // C
#define XFD   256           // XF

// ---------------- scratch (device globals; no cudaMalloc allowed) ----------------
__device__ float g_qkv[(size_t)NS * LS * 3 * DE];   // compacted qkv rows, fp32 (for attn)
__device__ float g_h[(size_t)NS * HD];              // fp32 residual stream
__device__ float g_ta[(size_t)NS * HD];             // fp32 (LN input)

__device__ int g_off[NS + 1];                       // exclusive prefix of name_lens
__device__ int g_total[1];                          // sum of name_lens
__device__ int g_rowtok[NS * LS];                   // compact row -> token id

__device__ float g_zero[2048];                      // static zero bias
__device__ float g_bc[NLAY * HD];                   // folded encoder-attn bias (Wo bv + bo)
__device__ float g_bao[HD];                         // folded bott bias (Wb2 bout)

// bf16 hi/lo split buffers (activations)
__device__ __align__(16) __nv_bfloat16 g_gah[(size_t)NS * LS * DE],   g_gal[(size_t)NS * LS * DE];
__device__ __align__(16) __nv_bfloat16 g_attn_h[(size_t)NS * DE],     g_attn_l[(size_t)NS * DE];
__device__ __align__(16) __nv_bfloat16 g_xf_h[(size_t)NS * XFD],      g_xf_l[(size_t)NS * XFD];
__device__ __align__(16) __nv_bfloat16 g_hh[(size_t)NS * HD],         g_hl[(size_t)NS * HD];
__device__ __align__(16) __nv_bfloat16 g_t1_h[(size_t)NS * 2 * HD],   g_t1_l[(size_t)NS * 2 * HD];

// bf16 hi/lo split buffers (weights)
__device__ __align__(16) __nv_bfloat16 g_wqkv_h[(size_t)3 * DE * DE], g_wqkv_l[(size_t)3 * DE * DE];
__device__ __align__(16) __nv_bfloat16 g_wbott_h[(size_t)HD * (XFD + DE)], g_wbott_l[(size_t)HD * (XFD + DE)];
__device__ __align__(16) __nv_bfloat16 g_wo_h[(size_t)NLAY * HD * HD],  g_wo_l[(size_t)NLAY * HD * HD];
__device__ __align__(16) __nv_bfloat16 g_wf1_h[(size_t)NLAY * 2 * HD * HD], g_wf1_l[(size_t)NLAY * 2 * HD * HD];
__device__ __align__(16) __nv_bfloat16 g_wf2_h[(size_t)NLAY * HD * 2 * HD], g_wf2_l[(size_t)NLAY * HD * 2 * HD];
// transposed-split weights (B operands of precompute GEMMs)
__device__ __align__(16) __nv_bfloat16 g_wvt_h[(size_t)NLAY * HD * HD],  g_wvt_l[(size_t)NLAY * HD * HD];
__device__ __align__(16) __nv_bfloat16 g_woutt_h[(size_t)DE * DE],       g_woutt_l[(size_t)DE * DE];
// folded weights (outputs of precompute GEMMs)
__device__ __align__(16) __nv_bfloat16 g_wc_h[(size_t)NLAY * HD * HD],   g_wc_l[(size_t)NLAY * HD * HD];
__device__ __align__(16) __nv_bfloat16 g_wao_h[(size_t)HD * DE],         g_wao_l[(size_t)HD * DE];

// ================= helpers =================
__device__ __forceinline__ uint32_t smem_u32(const void* p) {
    uint32_t a;
    asm("{ .reg .u64 t; cvta.to.shared.u64 t, %1; cvt.u32.u64 %0, t; }" : "=r"(a) : "l"(p));
    return a;
}
__device__ __forceinline__ uint32_t sw128(uint32_t o) { return o ^ ((o >> 3) & 0x70); }

#define LDSM4(r, addr) \
    asm volatile("ldmatrix.sync.aligned.m8n8.x4.shared.b16 {%0,%1,%2,%3}, [%4];" \
        : "=r"((r)[0]), "=r"((r)[1]), "=r"((r)[2]), "=r"((r)[3]) : "r"(addr))

__device__ __forceinline__ void mma16816(float* c, const uint32_t* a, uint32_t b0, uint32_t b1) {
    asm volatile("mma.sync.aligned.m16n8k16.row.col.f32.bf16.bf16.f32 "
        "{%0,%1,%2,%3},{%4,%5,%6,%7},{%8,%9},{%0,%1,%2,%3};"
        : "+f"(c[0]), "+f"(c[1]), "+f"(c[2]), "+f"(c[3])
        : "r"(a[0]), "r"(a[1]), "r"(a[2]), "r"(a[3]), "r"(b0), "r"(b1));
}

#define CP_ASYNC16(dst, src) \
    asm volatile("cp.async.cg.shared.global [%0], [%1], 16;" :: "r"(dst), "l"(src))
#define CP_COMMIT() asm volatile("cp.async.commit_group;" ::: "memory")
#define CP_WAIT(n)  asm volatile("cp.async.wait_group %0;" :: "n"(n) : "memory")

// split fp32 pair -> packed bf16 hi (p) and lo residual (q). p = {lo16=bf16(x), hi16=bf16(y)}
__device__ __forceinline__ void split2(float x, float y, uint32_t& p, uint32_t& q) {
    asm("cvt.rn.bf16x2.f32 %0, %1, %2;" : "=r"(p) : "f"(y), "f"(x));
    float h0 = __uint_as_float(p << 16);
    float h1 = __uint_as_float(p & 0xffff0000u);
    float r0 = x - h0, r1 = y - h1;
    asm("cvt.rn.bf16x2.f32 %0, %1, %2;" : "=r"(q) : "f"(r1), "f"(r0));
}

// ---------------- fp32 -> bf16 hi/lo split (elementwise, n2 = n/2 pairs) ----------------
__global__ __launch_bounds__(256) void split_kernel(
    const float* __restrict__ src,
    __nv_bfloat16* __restrict__ hi, __nv_bfloat16* __restrict__ lo, int n2)
{
    const int i = blockIdx.x * blockDim.x + threadIdx.x;
    if (i < n2) {
        const float2 v = reinterpret_cast<const float2*>(src)[i];
        uint32_t p, q;
        split2(v.x, v.y, p, q);
        reinterpret_cast<uint32_t*>(hi)[i] = p;
        reinterpret_cast<uint32_t*>(lo)[i] = q;
    }
}

// ---------------- fp32 [R x C] (row stride ld) -> transposed bf16 hi/lo [C x R] ----------------
__global__ __launch_bounds__(256) void transpose_split_kernel(
    const float* __restrict__ src, int ld, int R,
    __nv_bfloat16* __restrict__ dh, __nv_bfloat16* __restrict__ dl)
{
    __shared__ float tile[32][33];
    const int c0 = blockIdx.x * 32, r0 = blockIdx.y * 32;
    const int tx = threadIdx.x, ty = threadIdx.y;   // (32, 8)
#pragma unroll
    for (int i = ty; i < 32; i += 8)
        tile[i][tx] = src[(size_t)(r0 + i) * ld + c0 + tx];
    __syncthreads();
    if (tx < 16) {
#pragma unroll
        for (int i = ty; i < 32; i += 8) {
            uint32_t p, q;
            split2(tile[2 * tx][i], tile[2 * tx + 1][i], p, q);
            const size_t id2 = ((size_t)(c0 + i) * R + r0) / 2 + tx;
            reinterpret_cast<uint32_t*>(dh)[id2] = p;
            reinterpret_cast<uint32_t*>(dl)[id2] = q;
        }
    }
}

// ---------------- bias fold: out[row] = sum_k W[row, coff+k] * v[k] + base[row] ----------------
__global__ __launch_bounds__(128) void bias_fold_kernel(
    const float* __restrict__ W, int ldw, int coff,
    const float* __restrict__ v, const float* __restrict__ base,
    float* __restrict__ out, int K)
{
    __shared__ float red[4];
    const int row = blockIdx.x;
    const int t = threadIdx.x, lane = t & 31, warp = t >> 5;
    const float* wr = W + (size_t)row * ldw + coff;
    float s = 0.f;
    for (int k = t; k < K; k += 128) s += wr[k] * v[k];
#pragma unroll
    for (int o = 16; o; o >>= 1) s += __shfl_down_sync(0xffffffffu, s, o);
    if (lane == 0) red[warp] = s;
    __syncthreads();
    if (t == 0) out[row] = red[0] + red[1] + red[2] + red[3] + (base ? base[row] : 0.f);
}

// ---------------- compaction: exclusive scan of name_lens (NS = 4096 = 1024 x 4) ----------------
__global__ __launch_bounds__(1024) void scan_kernel(
    const int* __restrict__ lens, int* __restrict__ off, int* __restrict__ total)
{
    __shared__ int wsum[32];
    const int tid = threadIdx.x, lane = tid & 31, warp = tid >> 5;
    int v[4], s = 0;
#pragma unroll
    for (int i = 0; i < 4; i++) { v[i] = lens[tid * 4 + i]; s += v[i]; }
    int ws = s;
#pragma unroll
    for (int o = 1; o < 32; o <<= 1) { int t = __shfl_up_sync(0xffffffffu, ws, o); if (lane >= o) ws += t; }
    if (lane == 31) wsum[warp] = ws;
    __syncthreads();
    if (warp == 0) {
        int t = wsum[lane];
#pragma unroll
        for (int o = 1; o < 32; o <<= 1) { int u = __shfl_up_sync(0xffffffffu, t, o); if (lane >= o) t += u; }
        wsum[lane] = t;
    }
    __syncthreads();
    int run = ws - s + (warp ? wsum[warp - 1] : 0);
#pragma unroll
    for (int i = 0; i < 4; i++) { off[tid * 4 + i] = run; run += v[i]; }
    if (tid == 1023) { off[NS] = run; total[0] = run; }
}

__global__ __launch_bounds__(32) void fill_rows_kernel(
    const int* __restrict__ lens, const int* __restrict__ off,
    const int* __restrict__ toks, int* __restrict__ rowtok)
{
    const int b = blockIdx.x;
    const int len = lens[b], o = off[b];
    for (int s = threadIdx.x; s < len; s += 32) rowtok[o + s] = toks[b * LS + s];
}

__global__ __launch_bounds__(128) void gather_split_kernel(
    const float* __restrict__ wte, const int* __restrict__ rowtok,
    const int* __restrict__ total,
    __nv_bfloat16* __restrict__ Ah, __nv_bfloat16* __restrict__ Al)
{
    const int r = blockIdx.x;
    if (r >= total[0]) return;
    const float2* src = reinterpret_cast<const float2*>(wte + (size_t)rowtok[r] * DE);
    uint32_t* dh = reinterpret_cast<uint32_t*>(Ah) + (size_t)r * (DE / 2);
    uint32_t* dl = reinterpret_cast<uint32_t*>(Al) + (size_t)r * (DE / 2);
#pragma unroll
    for (int i = 0; i < 3; i++) {
        const int j = threadIdx.x + 128 * i;
        const float2 v = src[j];
        uint32_t p, q;
        split2(v.x, v.y, p, q);
        dh[j] = p; dl[j] = q;
    }
}

// ================= HMMA GEMM: C[M,N] = A[M,K] @ B[N,K]^T + bias (+rs*bias2) =================
// A/B pre-split bf16 hi/lo. 3-term: C = Ah*Bh + Ah*Bl + Al*Bh.
// AMODE/BMODE: 0 direct (lda/ldb row stride), 2 concat at K1 (second operand lda2/ldb2)
// MDYN: effective M read from device global.
#define CHUNK  64
#define STAGES 3
#define STG_BYTES 65536
#define OFF_AH 0
#define OFF_AL 16384
#define OFF_BH 32768
#define OFF_BL 49152
#define TG_SMEM  (STAGES * STG_BYTES + 512)

template<int AMODE, int BMODE, bool RELU, bool WF32, bool WSPLIT, bool MDYN, bool HASB2>
__global__ __launch_bounds__(256, 1) void tgemm_kernel(
    int M, int N, int K, int K1,
    const __nv_bfloat16* __restrict__ Ah, const __nv_bfloat16* __restrict__ Al, int lda,
    const __nv_bfloat16* __restrict__ A2h, const __nv_bfloat16* __restrict__ A2l, int lda2,
    const int* __restrict__ Mlim,
    const __nv_bfloat16* __restrict__ Bh, const __nv_bfloat16* __restrict__ Bl, int ldb,
    const __nv_bfloat16* __restrict__ B2h, const __nv_bfloat16* __restrict__ B2l, int ldb2,
    const float* __restrict__ bias, const float* __restrict__ bias2,
    const int* __restrict__ rowscale,
    float* __restrict__ C,
    __nv_bfloat16* __restrict__ Ch, __nv_bfloat16* __restrict__ Cl)
{
    extern __shared__ char smem[];
    const uint32_t sb = smem_u32(smem);

    const int tid  = threadIdx.x;
    const int lane = tid & 31;
    const int wid  = tid >> 5;
    const int bm = blockIdx.y * 128, bn = blockIdx.x * 128;

    int Mtot = M;
    if (MDYN) {
        Mtot = Mlim[0];
        if (bm >= Mtot) return;
    }

    const int nch = K / CHUNK;

    auto issue_stage = [&](int c) {
        const int k0 = c * CHUNK;
        const uint32_t st = sb + (c % STAGES) * STG_BYTES;
#pragma unroll
        for (int i = 0; i < 4; i++) {
            const int idx = tid + 256 * i;
            const int row = idx >> 3;
            const int seg = idx & 7;
            const uint32_t sw = sw128(row * 128 + seg * 16);
            int ar = bm + row;
            if (MDYN && ar >= Mtot) ar = Mtot - 1;
            const __nv_bfloat16 *pah, *pal;
            if (AMODE == 2 && k0 >= K1) {
                const size_t off = (size_t)ar * lda2 + (k0 - K1) + seg * 8;
                pah = A2h + off; pal = A2l + off;
            } else {
                const size_t off = (size_t)ar * lda + k0 + seg * 8;
                pah = Ah + off; pal = Al + off;
            }
            CP_ASYNC16(st + OFF_AH + sw, pah);
            CP_ASYNC16(st + OFF_AL + sw, pal);
            const __nv_bfloat16 *pbh, *pbl;
            if (BMODE == 2 && k0 >= K1) {
                const size_t off = (size_t)(bn + row) * ldb2 + (k0 - K1) + seg * 8;
                pbh = B2h + off; pbl = B2l + off;
            } else {
                const size_t off = (size_t)(bn + row) * ldb + k0 + seg * 8;
                pbh = Bh + off; pbl = Bl + off;
            }
            CP_ASYNC16(st + OFF_BH + sw, pbh);
            CP_ASYNC16(st + OFF_BL + sw, pbl);
        }
        CP_COMMIT();
    };

#pragma unroll
    for (int s = 0; s < STAGES; s++)
        if (s < nch) issue_stage(s);

    const int wm = (wid >> 1) * 32;
    const int wn = (wid & 1) * 64;

    float acc[2][8][4];
#pragma unroll
    for (int i = 0; i < 2; i++)
#pragma unroll
        for (int j = 0; j < 8; j++)
#pragma unroll
            for (int t = 0; t < 4; t++) acc[i][j][t] = 0.f;

    const int a_row  = (lane & 15);
    const int a_kb   = (lane >> 4) * 16;
    const int b_row  = (lane & 7) + ((lane >> 4) << 3);
    const int b_kb   = ((lane >> 3) & 1) * 16;

    for (int c = 0; c < nch; c++) {
        const int rem = nch - 1 - c;     // stages still in flight after this one
        if (rem >= 2)      { CP_WAIT(2); }
        else if (rem == 1) { CP_WAIT(1); }
        else               { CP_WAIT(0); }
        __syncthreads();

        const uint32_t st = sb + (c % STAGES) * STG_BYTES;

#pragma unroll
        for (int ks = 0; ks < 4; ks++) {
            const int kb = ks * 32;
            uint32_t ah0[4], ah1[4], al0[4], al1[4];
            {
                const uint32_t o0 = sw128((wm + a_row) * 128 + kb + a_kb);
                const uint32_t o1 = sw128((wm + 16 + a_row) * 128 + kb + a_kb);
                LDSM4(ah0, st + OFF_AH + o0);
                LDSM4(ah1, st + OFF_AH + o1);
                LDSM4(al0, st + OFF_AL + o0);
                LDSM4(al1, st + OFF_AL + o1);
            }
            uint32_t bf[4][4];
#pragma unroll
            for (int j2 = 0; j2 < 4; j2++) {
                const uint32_t ob = sw128((wn + j2 * 16 + b_row) * 128 + kb + b_kb);
                LDSM4(bf[j2], st + OFF_BH + ob);
            }
#pragma unroll
            for (int j2 = 0; j2 < 4; j2++) {
                mma16816(acc[0][2 * j2 + 0], ah0, bf[j2][0], bf[j2][1]);
                mma16816(acc[0][2 * j2 + 1], ah0, bf[j2][2], bf[j2][3]);
                mma16816(acc[1][2 * j2 + 0], ah1, bf[j2][0], bf[j2][1]);
                mma16816(acc[1][2 * j2 + 1], ah1, bf[j2][2], bf[j2][3]);
                mma16816(acc[0][2 * j2 + 0], al0, bf[j2][0], bf[j2][1]);
                mma16816(acc[0][2 * j2 + 1], al0, bf[j2][2], bf[j2][3]);
                mma16816(acc[1][2 * j2 + 0], al1, bf[j2][0], bf[j2][1]);
                mma16816(acc[1][2 * j2 + 1], al1, bf[j2][2], bf[j2][3]);
            }
#pragma unroll
            for (int j2 = 0; j2 < 4; j2++) {
                const uint32_t ob = sw128((wn + j2 * 16 + b_row) * 128 + kb + b_kb);
                LDSM4(bf[j2], st + OFF_BL + ob);
            }
#pragma unroll
            for (int j2 = 0; j2 < 4; j2++) {
                mma16816(acc[0][2 * j2 + 0], ah0, bf[j2][0], bf[j2][1]);
                mma16816(acc[0][2 * j2 + 1], ah0, bf[j2][2], bf[j2][3]);
                mma16816(acc[1][2 * j2 + 0], ah1, bf[j2][0], bf[j2][1]);
                mma16816(acc[1][2 * j2 + 1], ah1, bf[j2][2], bf[j2][3]);
            }
        }
        __syncthreads();
        if (c + STAGES < nch) issue_stage(c + STAGES);
    }

    // ---- epilogue ----
#pragma unroll
    for (int i = 0; i < 2; i++) {
        const int r0 = bm + wm + i * 16 + (lane >> 2);
        const int r1 = r0 + 8;
        const bool ok0 = !MDYN || (r0 < Mtot);
        const bool ok1 = !MDYN || (r1 < Mtot);
        const float rs0 = HASB2 ? (float)rowscale[r0] : 0.f;
        const float rs1 = HASB2 ? (float)rowscale[r1] : 0.f;
#pragma unroll
        for (int j = 0; j < 8; j++) {
            const int col = bn + wn + j * 8 + (lane & 3) * 2;
            float b00 = bias[col], b01 = bias[col + 1];
            float b10 = b00, b11 = b01;
            if (HASB2) {
                b00 += rs0 * bias2[col]; b01 += rs0 * bias2[col + 1];
                b10 += rs1 * bias2[col]; b11 += rs1 * bias2[col + 1];
            }
            float2 v0 = make_float2(acc[i][j][0] + b00, acc[i][j][1] + b01);
            float2 v1 = make_float2(acc[i][j][2] + b10, acc[i][j][3] + b11);
            if (RELU) {
                v0.x = fmaxf(v0.x, 0.f); v0.y = fmaxf(v0.y, 0.f);
                v1.x = fmaxf(v1.x, 0.f); v1.y = fmaxf(v1.y, 0.f);
            }
            if (WF32) {
                if (ok0) *reinterpret_cast<float2*>(C + (size_t)r0 * N + col) = v0;
                if (ok1) *reinterpret_cast<float2*>(C + (size_t)r1 * N + col) = v1;
            }
            if (WSPLIT) {
                uint32_t p, q;
                if (ok0) {
                    split2(v0.x, v0.y, p, q);
                    reinterpret_cast<uint32_t*>(Ch)[((size_t)r0 * N + col) >> 1] = p;
                    reinterpret_cast<uint32_t*>(Cl)[((size_t)r0 * N + col) >> 1] = q;
                }
                if (ok1) {
                    split2(v1.x, v1.y, p, q);
                    reinterpret_cast<uint32_t*>(Ch)[((size_t)r1 * N + col) >> 1] = p;
                    reinterpret_cast<uint32_t*>(Cl)[((size_t)r1 * N + col) >> 1] = q;
                }
            }
        }
    }
}

// ---------------- name attention on compacted qkv, q-summed ----------------
__global__ __launch_bounds__(192) void name_attn_kernel(
    const float* __restrict__ qkv, const int* __restrict__ off,
    __nv_bfloat16* __restrict__ attn_h, __nv_bfloat16* __restrict__ attn_l)
{
    __shared__ float Qs[LS][DHN];
    __shared__ float Ks[LS][DHN];
    __shared__ float Vs[LS][DHN];
    __shared__ float sc[LS][LS + 1];

    const int h = blockIdx.x;
    const int b = blockIdx.y;
    const int d = threadIdx.x;

    const int o   = off[b];
    const int len = off[b + 1] - o;

    const float* base = qkv + (size_t)o * (3 * DE) + h * DHN + d;
    for (int s = 0; s < len; s++) {
        Qs[s][d] = base[s * (3 * DE)];
        Ks[s][d] = base[s * (3 * DE) + DE];
        Vs[s][d] = base[s * (3 * DE) + 2 * DE];
    }
    __syncthreads();

    const int warp = d >> 5, lane = d & 31;
    const float scale = 1.0f / sqrtf((float)DHN);
    const int np = len * len;
    for (int p = warp; p < np; p += 6) {
        const int q = p / len, j = p - q * len;
        float s = 0.f;
#pragma unroll
        for (int i = 0; i < 6; i++) s += Qs[q][lane + 32 * i] * Ks[j][lane + 32 * i];
#pragma unroll
        for (int ofs = 16; ofs; ofs >>= 1) s += __shfl_down_sync(0xffffffffu, s, ofs);
        if (lane == 0) sc[q][j] = s * scale;
    }
    __syncthreads();

    if (d < len) {
        float mx = -1e30f;
        for (int j = 0; j < len; j++) mx = fmaxf(mx, sc[d][j]);
        float sum = 0.f;
        float row[LS];
        for (int j = 0; j < len; j++) { row[j] = expf(sc[d][j] - mx); sum += row[j]; }
        const float inv = 1.f / sum;
        for (int j = 0; j < len; j++) sc[d][j] = row[j] * inv;
    }
    __syncthreads();

    float accum = 0.f;
    for (int s = 0; s < len; s++) {
        float ov = 0.f;
        for (int j = 0; j < len; j++) ov += sc[s][j] * Vs[j][d];
        accum += ov;
    }
    const float a1 = __shfl_down_sync(0xffffffffu, accum, 1);
    if (!(d & 1)) {
        uint32_t p, q;
        split2(accum, a1, p, q);
        const size_t id2 = ((size_t)b * DE + h * DHN + d) >> 1;
        reinterpret_cast<uint32_t*>(attn_h)[id2] = p;
        reinterpret_cast<uint32_t*>(attn_l)[id2] = q;
    }
}

// ---------------- residual + LayerNorm (in place on h) + bf16 split output ----------------
__device__ __forceinline__ float block_reduce_sum(float v) {
    __shared__ float red[8];
    const int lane = threadIdx.x & 31, warp = threadIdx.x >> 5;
#pragma unroll
    for (int o = 16; o; o >>= 1) v += __shfl_down_sync(0xffffffffu, v, o);
    if (lane == 0) red[warp] = v;
    __syncthreads();
    v = (threadIdx.x < 8) ? red[threadIdx.x] : 0.f;
    if (warp == 0)
#pragma unroll
        for (int o = 4; o; o >>= 1) v += __shfl_down_sync(0xffffffffu, v, o);
    return v;
}

__global__ __launch_bounds__(256) void resid_ln_kernel(
    float* __restrict__ h, const float* __restrict__ a,
    const float* __restrict__ g, const float* __restrict__ b,
    __nv_bfloat16* __restrict__ hh, __nv_bfloat16* __restrict__ hl)
{
    const int row = blockIdx.x;
    const int t = threadIdx.x;
    float v[4];
    float s = 0.f;
#pragma unroll
    for (int i = 0; i < 4; i++) {
        const int c = t + 256 * i;
        v[i] = h[(size_t)row * HD + c] + a[(size_t)row * HD + c];
        s += v[i];
    }
    s = block_reduce_sum(s);
    __shared__ float mean_s, rstd_s;
    if (t == 0) mean_s = s * (1.f / HD);
    __syncthreads();
    const float m = mean_s;
    float s2 = 0.f;
#pragma unroll
    for (int i = 0; i < 4; i++) { const float dd = v[i] - m; s2 += dd * dd; }
    s2 = block_reduce_sum(s2);
    if (t == 0) rstd_s = rsqrtf(s2 * (1.f / HD) + 1e-5f);
    __syncthreads();
    const float r = rstd_s;
#pragma unroll
    for (int i = 0; i < 4; i++) {
        const int c = t + 256 * i;
        const float y = (v[i] - m) * r * g[c] + b[c];
        h[(size_t)row * HD + c] = y;
        const float y1 = __shfl_down_sync(0xffffffffu, y, 1);
        if (!(t & 1)) {
            uint32_t p, q;
            split2(y, y1, p, q);
            const size_t id2 = ((size_t)row * HD + c) >> 1;
            reinterpret_cast<uint32_t*>(hh)[id2] = p;
            reinterpret_cast<uint32_t*>(hl)[id2] = q;
        }
    }
}

// ---------------- classifier head ----------------
__global__ __launch_bounds__(512) void cls_kernel(
    const float* __restrict__ h, const float* __restrict__ w,
    const float* __restrict__ b, float* __restrict__ out)
{
    const int m = blockIdx.x;
    const int c = threadIdx.x >> 5;
    const int lane = threadIdx.x & 31;
    const float* hr = h + (size_t)m * HD;
    const float* wr = w + (size_t)c * HD;
    float s = 0.f;
#pragma unroll
    for (int i = lane; i < HD; i += 32) s += hr[i] * wr[i];
#pragma unroll
    for (int o = 16; o; o >>= 1) s += __shfl_down_sync(0xffffffffu, s, o);
    if (lane == 0) out[(size_t)m * NCLS + c] = s + b[c];
}

// ---------------- orchestration ----------------
static inline void launch_split(const float* src, __nv_bfloat16* hi, __nv_bfloat16* lo, size_t n) {
    const int n2 = (int)(n / 2);
    split_kernel<<<(n2 + 255) / 256, 256>>>(src, hi, lo, n2);
}

extern "C" void kernel_launch(void* const* d_in, const int* in_sizes, int n_in,
                              void* d_out, int out_size)
{
    const int*   name_tokens = (const int*)d_in[0];
    const int*   name_lens   = (const int*)d_in[1];
    const float* x_feats     = (const float*)d_in[2];
    const float* wte         = (const float*)d_in[3];
    const float* mha_in_w    = (const float*)d_in[4];
    const float* mha_in_b    = (const float*)d_in[5];
    const float* mha_out_w   = (const float*)d_in[6];
    const float* mha_out_b   = (const float*)d_in[7];
    const float* bott_w      = (const float*)d_in[8];
    const float* bott_b      = (const float*)d_in[9];
    const float* enc_in_w    = (const float*)d_in[10];
    const float* enc_in_b    = (const float*)d_in[11];
    const float* enc_out_w   = (const float*)d_in[12];
    const float* enc_out_b   = (const float*)d_in[13];
    const float* enc_ln1_g   = (const float*)d_in[14];
    const float* enc_ln1_b   = (const float*)d_in[15];
    const float* enc_ln2_g   = (const float*)d_in[16];
    const float* enc_ln2_b   = (const float*)d_in[17];
    const float* enc_ff1_w   = (const float*)d_in[18];
    const float* enc_ff1_b   = (const float*)d_in[19];
    const float* enc_ff2_w   = (const float*)d_in[20];
    const float* enc_ff2_b   = (const float*)d_in[21];
    const float* cls_w       = (const float*)d_in[22];
    const float* cls_b       = (const float*)d_in[23];
    float* out = (float*)d_out;

    float *qkv, *h, *ta, *zero, *bc, *bao;
    int *off, *total, *rowtok;
    cudaGetSymbolAddress((void**)&qkv,    g_qkv);
    cudaGetSymbolAddress((void**)&h,      g_h);
    cudaGetSymbolAddress((void**)&ta,     g_ta);
    cudaGetSymbolAddress((void**)&zero,   g_zero);
    cudaGetSymbolAddress((void**)&bc,     g_bc);
    cudaGetSymbolAddress((void**)&bao,    g_bao);
    cudaGetSymbolAddress((void**)&off,    g_off);
    cudaGetSymbolAddress((void**)&total,  g_total);
    cudaGetSymbolAddress((void**)&rowtok, g_rowtok);

    __nv_bfloat16 *gah, *gal, *attn_h, *attn_l, *xf_h, *xf_l, *hh, *hl, *t1_h, *t1_l;
    __nv_bfloat16 *wqkv_h, *wqkv_l, *wbott_h, *wbott_l, *wo_h, *wo_l, *wf1_h, *wf1_l, *wf2_h, *wf2_l;
    __nv_bfloat16 *wvt_h, *wvt_l, *woutt_h, *woutt_l, *wc_h, *wc_l, *wao_h, *wao_l;
    cudaGetSymbolAddress((void**)&gah,    g_gah);     cudaGetSymbolAddress((void**)&gal,    g_gal);
    cudaGetSymbolAddress((void**)&attn_h, g_attn_h);  cudaGetSymbolAddress((void**)&attn_l, g_attn_l);
    cudaGetSymbolAddress((void**)&xf_h,   g_xf_h);    cudaGetSymbolAddress((void**)&xf_l,   g_xf_l);
    cudaGetSymbolAddress((void**)&hh,     g_hh);      cudaGetSymbolAddress((void**)&hl,     g_hl);
    cudaGetSymbolAddress((void**)&t1_h,   g_t1_h);    cudaGetSymbolAddress((void**)&t1_l,   g_t1_l);
    cudaGetSymbolAddress((void**)&wqkv_h, g_wqkv_h);  cudaGetSymbolAddress((void**)&wqkv_l, g_wqkv_l);
    cudaGetSymbolAddress((void**)&wbott_h,g_wbott_h); cudaGetSymbolAddress((void**)&wbott_l,g_wbott_l);
    cudaGetSymbolAddress((void**)&wo_h,   g_wo_h);    cudaGetSymbolAddress((void**)&wo_l,   g_wo_l);
    cudaGetSymbolAddress((void**)&wf1_h,  g_wf1_h);   cudaGetSymbolAddress((void**)&wf1_l,  g_wf1_l);
    cudaGetSymbolAddress((void**)&wf2_h,  g_wf2_h);   cudaGetSymbolAddress((void**)&wf2_l,  g_wf2_l);
    cudaGetSymbolAddress((void**)&wvt_h,  g_wvt_h);   cudaGetSymbolAddress((void**)&wvt_l,  g_wvt_l);
    cudaGetSymbolAddress((void**)&woutt_h,g_woutt_h); cudaGetSymbolAddress((void**)&woutt_l,g_woutt_l);
    cudaGetSymbolAddress((void**)&wc_h,   g_wc_h);    cudaGetSymbolAddress((void**)&wc_l,   g_wc_l);
    cudaGetSymbolAddress((void**)&wao_h,  g_wao_h);   cudaGetSymbolAddress((void**)&wao_l,  g_wao_l);

    // kernel instantiations used
    auto k_qkv   = tgemm_kernel<0, 0, false, true,  false, true,  false>;
    auto k_bott  = tgemm_kernel<2, 2, false, true,  true,  false, true >;
    auto k_plain = tgemm_kernel<0, 0, false, true,  false, false, false>;  // enc attn / ff2
    auto k_ff1   = tgemm_kernel<0, 0, true,  false, true,  false, false>;
    auto k_pre   = tgemm_kernel<0, 0, false, false, true,  false, false>;  // weight-fold GEMMs
    cudaFuncSetAttribute(k_qkv,   cudaFuncAttributeMaxDynamicSharedMemorySize, TG_SMEM);
    cudaFuncSetAttribute(k_bott,  cudaFuncAttributeMaxDynamicSharedMemorySize, TG_SMEM);
    cudaFuncSetAttribute(k_plain, cudaFuncAttributeMaxDynamicSharedMemorySize, TG_SMEM);
    cudaFuncSetAttribute(k_ff1,   cudaFuncAttributeMaxDynamicSharedMemorySize, TG_SMEM);
    cudaFuncSetAttribute(k_pre,   cudaFuncAttributeMaxDynamicSharedMemorySize, TG_SMEM);

    // ---- 0a. compaction metadata + gathered embedding split ----
    scan_kernel<<<1, 1024>>>(name_lens, off, total);
    fill_rows_kernel<<<NS, 32>>>(name_lens, off, name_tokens, rowtok);
    gather_split_kernel<<<NS * LS, 128>>>(wte, rowtok, total, gah, gal);

    // ---- 0b. split weights + x_feats ----
    launch_split(mha_in_w,  wqkv_h,  wqkv_l,  (size_t)3 * DE * DE);
    launch_split(bott_w,    wbott_h, wbott_l, (size_t)HD * (XFD + DE));
    launch_split(x_feats,   xf_h,    xf_l,    (size_t)NS * XFD);
    for (int l = 0; l < NLAY; l++) {
        launch_split(enc_out_w + (size_t)l * HD * HD,
                     wo_h + (size_t)l * HD * HD, wo_l + (size_t)l * HD * HD, (size_t)HD * HD);
        launch_split(enc_ff1_w + (size_t)l * 2 * HD * HD,
                     wf1_h + (size_t)l * 2 * HD * HD, wf1_l + (size_t)l * 2 * HD * HD, (size_t)2 * HD * HD);
        launch_split(enc_ff2_w + (size_t)l * HD * 2 * HD,
                     wf2_h + (size_t)l * HD * 2 * HD, wf2_l + (size_t)l * HD * 2 * HD, (size_t)HD * 2 * HD);
        // transposed split of Wv (B operand of Wc = Wo @ Wv)
        transpose_split_kernel<<<dim3(HD / 32, HD / 32), dim3(32, 8)>>>(
            enc_in_w + (size_t)l * 3 * HD * HD + (size_t)2 * HD * HD, HD, HD,
            wvt_h + (size_t)l * HD * HD, wvt_l + (size_t)l * HD * HD);
        // folded bias bc = Wo @ bv + bo
        bias_fold_kernel<<<HD, 128>>>(
            enc_out_w + (size_t)l * HD * HD, HD, 0,
            enc_in_b + (size_t)l * 3 * HD + 2 * HD,
            enc_out_b + (size_t)l * HD, bc + (size_t)l * HD, HD);
    }
    transpose_split_kernel<<<dim3(DE / 32, DE / 32), dim3(32, 8)>>>(
        mha_out_w, DE, DE, woutt_h, woutt_l);
    bias_fold_kernel<<<HD, 128>>>(bott_w, XFD + DE, XFD, mha_out_b, nullptr, bao, DE);

    // ---- 0c. weight-fold GEMMs ----
    // Wc[l] = Wo[l] @ Wv[l]  (A = Wo split, B = Wv^T split)
    for (int l = 0; l < NLAY; l++) {
        k_pre<<<dim3(HD / 128, HD / 128), 256, TG_SMEM>>>(
            HD, HD, HD, 0,
            wo_h + (size_t)l * HD * HD, wo_l + (size_t)l * HD * HD, HD,
            nullptr, nullptr, 0, nullptr,
            wvt_h + (size_t)l * HD * HD, wvt_l + (size_t)l * HD * HD, HD,
            nullptr, nullptr, 0,
            zero, nullptr, nullptr,
            nullptr, wc_h + (size_t)l * HD * HD, wc_l + (size_t)l * HD * HD);
    }
    // Wao = Wb2 @ Wout  (A = wbott split cols [256:1024], B = Wout^T split)
    k_pre<<<dim3(DE / 128, HD / 128), 256, TG_SMEM>>>(
        HD, DE, DE, 0,
        wbott_h + XFD, wbott_l + XFD, XFD + DE,
        nullptr, nullptr, 0, nullptr,
        woutt_h, woutt_l, DE,
        nullptr, nullptr, 0,
        zero, nullptr, nullptr,
        nullptr, wao_h, wao_l);

    const int MQ = NS * LS;
    const int KQ = DE;
    const int NQ = 3 * DE;

    // 1. qkv(compact) = gathered_emb @ mha_in_w^T + mha_in_b
    k_qkv<<<dim3(NQ / 128, MQ / 128), 256, TG_SMEM>>>(
        MQ, NQ, KQ, 0,
        gah, gal, KQ, nullptr, nullptr, 0, total,
        wqkv_h, wqkv_l, KQ, nullptr, nullptr, 0,
        mha_in_b, nullptr, nullptr, qkv, nullptr, nullptr);

    // 2. name attention on compact rows -> attnsum split [4096 x 768]
    name_attn_kernel<<<dim3(NHN, NS), 192>>>(qkv, off, attn_h, attn_l);

    // 3+4 fused. x = xf@Wb1^T + attnsum@Wao^T + bbott + len*bao -> h fp32 + split
    k_bott<<<dim3(HD / 128, NS / 128), 256, TG_SMEM>>>(
        NS, HD, XFD + DE, XFD,
        xf_h, xf_l, XFD, attn_h, attn_l, DE, nullptr,
        wbott_h, wbott_l, XFD + DE, wao_h, wao_l, DE,
        bott_b, bao, name_lens, h, hh, hl);

    // 5. encoder layers: attn block folded to single GEMM with Wc
    for (int l = 0; l < NLAY; l++) {
        k_plain<<<dim3(HD / 128, NS / 128), 256, TG_SMEM>>>(
            NS, HD, HD, 0,
            hh, hl, HD, nullptr, nullptr, 0, nullptr,
            wc_h + (size_t)l * HD * HD, wc_l + (size_t)l * HD * HD, HD,
            nullptr, nullptr, 0,
            bc + (size_t)l * HD, nullptr, nullptr, ta, nullptr, nullptr);
        resid_ln_kernel<<<NS, 256>>>(h, ta, enc_ln1_g + (size_t)l * HD, enc_ln1_b + (size_t)l * HD, hh, hl);

        k_ff1<<<dim3(2 * HD / 128, NS / 128), 256, TG_SMEM>>>(
            NS, 2 * HD, HD, 0,
            hh, hl, HD, nullptr, nullptr, 0, nullptr,
            wf1_h + (size_t)l * 2 * HD * HD, wf1_l + (size_t)l * 2 * HD * HD, HD,
            nullptr, nullptr, 0,
            enc_ff1_b + (size_t)l * 2 * HD, nullptr, nullptr, nullptr, t1_h, t1_l);
        k_plain<<<dim3(HD / 128, NS / 128), 256, TG_SMEM>>>(
            NS, HD, 2 * HD, 0,
            t1_h, t1_l, 2 * HD, nullptr, nullptr, 0, nullptr,
            wf2_h + (size_t)l * HD * 2 * HD, wf2_l + (size_t)l * HD * 2 * HD, 2 * HD,
            nullptr, nullptr, 0,
            enc_ff2_b + (size_t)l * HD, nullptr, nullptr, ta, nullptr, nullptr);
        resid_ln_kernel<<<NS, 256>>>(h, ta, enc_ln2_g + (size_t)l * HD, enc_ln2_b + (size_t)l * HD, hh, hl);
    }

    // 6. classifier head -> out [4096 x 16]
    cls_kernel<<<NS, 512>>>(h, cls_w, cls_b, out);
}

// round 8
// speedup vs baseline: 4.4557x; 1.0798x over previous
#include <cuda_runtime.h>
#include <cuda_bf16.h>
#include <cstdint>
#include <math.h>

// ---------------- problem constants ----------------
#define NS    4096          // N samples
#define LS    16            // L tokens
#define DE    768           // D embedding
#define NHN   4             // heads (name attn)
#define DHN   192           // head dim (name attn)
#define HD    1024          // H
#define NLAY  4             // NL
#define NCLS  16            // C
#define XFD   256           // XF

// ---------------- scratch (device globals; no cudaMalloc allowed) ----------------
__device__ float g_qkv[(size_t)NS * LS * 3 * DE];   // compacted qkv rows, fp32 (for attn)
__device__ float g_h[(size_t)NS * HD];              // fp32 residual stream
__device__ float g_ta[(size_t)NS * HD];             // fp32 (LN input)

__device__ int g_off[NS + 1];
__device__ int g_total[1];
__device__ int g_rowtok[NS * LS];

__device__ float g_zero[2048];
__device__ float g_bc[NLAY * HD];
__device__ float g_bao[HD];

// bf16 hi/lo split buffers (activations)
__device__ __align__(16) __nv_bfloat16 g_gah[(size_t)NS * LS * DE],   g_gal[(size_t)NS * LS * DE];
__device__ __align__(16) __nv_bfloat16 g_attn_h[(size_t)NS * DE],     g_attn_l[(size_t)NS * DE];
__device__ __align__(16) __nv_bfloat16 g_xf_h[(size_t)NS * XFD],      g_xf_l[(size_t)NS * XFD];
__device__ __align__(16) __nv_bfloat16 g_hh[(size_t)NS * HD],         g_hl[(size_t)NS * HD];
__device__ __align__(16) __nv_bfloat16 g_t1_h[(size_t)NS * 2 * HD],   g_t1_l[(size_t)NS * 2 * HD];

// bf16 hi/lo split buffers (weights)
__device__ __align__(16) __nv_bfloat16 g_wqkv_h[(size_t)3 * DE * DE], g_wqkv_l[(size_t)3 * DE * DE];
__device__ __align__(16) __nv_bfloat16 g_wbott_h[(size_t)HD * (XFD + DE)], g_wbott_l[(size_t)HD * (XFD + DE)];
__device__ __align__(16) __nv_bfloat16 g_wo_h[(size_t)NLAY * HD * HD],  g_wo_l[(size_t)NLAY * HD * HD];
__device__ __align__(16) __nv_bfloat16 g_wf1_h[(size_t)NLAY * 2 * HD * HD], g_wf1_l[(size_t)NLAY * 2 * HD * HD];
__device__ __align__(16) __nv_bfloat16 g_wf2_h[(size_t)NLAY * HD * 2 * HD], g_wf2_l[(size_t)NLAY * HD * 2 * HD];
__device__ __align__(16) __nv_bfloat16 g_wvt_h[(size_t)NLAY * HD * HD],  g_wvt_l[(size_t)NLAY * HD * HD];
__device__ __align__(16) __nv_bfloat16 g_woutt_h[(size_t)DE * DE],       g_woutt_l[(size_t)DE * DE];
__device__ __align__(16) __nv_bfloat16 g_wc_h[(size_t)NLAY * HD * HD],   g_wc_l[(size_t)NLAY * HD * HD];
__device__ __align__(16) __nv_bfloat16 g_wao_h[(size_t)HD * DE],         g_wao_l[(size_t)HD * DE];

// ================= helpers =================
__device__ __forceinline__ uint32_t smem_u32(const void* p) {
    uint32_t a;
    asm("{ .reg .u64 t; cvta.to.shared.u64 t, %1; cvt.u32.u64 %0, t; }" : "=r"(a) : "l"(p));
    return a;
}
__device__ __forceinline__ uint32_t sw128(uint32_t o) { return o ^ ((o >> 3) & 0x70); }

#define LDSM4(r, addr) \
    asm volatile("ldmatrix.sync.aligned.m8n8.x4.shared.b16 {%0,%1,%2,%3}, [%4];" \
        : "=r"((r)[0]), "=r"((r)[1]), "=r"((r)[2]), "=r"((r)[3]) : "r"(addr))

__device__ __forceinline__ void mma16816(float* c, const uint32_t* a, uint32_t b0, uint32_t b1) {
    asm volatile("mma.sync.aligned.m16n8k16.row.col.f32.bf16.bf16.f32 "
        "{%0,%1,%2,%3},{%4,%5,%6,%7},{%8,%9},{%0,%1,%2,%3};"
        : "+f"(c[0]), "+f"(c[1]), "+f"(c[2]), "+f"(c[3])
        : "r"(a[0]), "r"(a[1]), "r"(a[2]), "r"(a[3]), "r"(b0), "r"(b1));
}

#define CP_ASYNC16(dst, src) \
    asm volatile("cp.async.cg.shared.global [%0], [%1], 16;" :: "r"(dst), "l"(src))
#define CP_COMMIT() asm volatile("cp.async.commit_group;" ::: "memory")
#define CP_WAIT(n)  asm volatile("cp.async.wait_group %0;" :: "n"(n) : "memory")

// split fp32 pair -> packed bf16 hi (p) and lo residual (q)
__device__ __forceinline__ void split2(float x, float y, uint32_t& p, uint32_t& q) {
    asm("cvt.rn.bf16x2.f32 %0, %1, %2;" : "=r"(p) : "f"(y), "f"(x));
    float h0 = __uint_as_float(p << 16);
    float h1 = __uint_as_float(p & 0xffff0000u);
    float r0 = x - h0, r1 = y - h1;
    asm("cvt.rn.bf16x2.f32 %0, %1, %2;" : "=r"(q) : "f"(r1), "f"(r0));
}

// ---------------- fp32 -> bf16 hi/lo split ----------------
__global__ __launch_bounds__(256) void split_kernel(
    const float* __restrict__ src,
    __nv_bfloat16* __restrict__ hi, __nv_bfloat16* __restrict__ lo, int n2)
{
    const int i = blockIdx.x * blockDim.x + threadIdx.x;
    if (i < n2) {
        const float2 v = reinterpret_cast<const float2*>(src)[i];
        uint32_t p, q;
        split2(v.x, v.y, p, q);
        reinterpret_cast<uint32_t*>(hi)[i] = p;
        reinterpret_cast<uint32_t*>(lo)[i] = q;
    }
}

// ---------------- batched fp32 [R x C] -> transposed bf16 hi/lo [C x R] ----------------
__global__ __launch_bounds__(256) void transpose_split_kernel(
    const float* __restrict__ src, int ld, int R,
    __nv_bfloat16* __restrict__ dh, __nv_bfloat16* __restrict__ dl,
    size_t srcStride, size_t dstStride)
{
    __shared__ float tile[32][33];
    const int z = blockIdx.z;
    src += (size_t)z * srcStride;
    dh  += (size_t)z * dstStride;
    dl  += (size_t)z * dstStride;
    const int c0 = blockIdx.x * 32, r0 = blockIdx.y * 32;
    const int tx = threadIdx.x, ty = threadIdx.y;   // (32, 8)
#pragma unroll
    for (int i = ty; i < 32; i += 8)
        tile[i][tx] = src[(size_t)(r0 + i) * ld + c0 + tx];
    __syncthreads();
    if (tx < 16) {
#pragma unroll
        for (int i = ty; i < 32; i += 8) {
            uint32_t p, q;
            split2(tile[2 * tx][i], tile[2 * tx + 1][i], p, q);
            const size_t id2 = ((size_t)(c0 + i) * R + r0) / 2 + tx;
            reinterpret_cast<uint32_t*>(dh)[id2] = p;
            reinterpret_cast<uint32_t*>(dl)[id2] = q;
        }
    }
}

// ---------------- batched bias fold: out[row] = W[row,:]·v + base[row] ----------------
__global__ __launch_bounds__(128) void bias_fold_kernel(
    const float* __restrict__ W, int ldw, int coff,
    const float* __restrict__ v, const float* __restrict__ base,
    float* __restrict__ out, int K,
    size_t wStride, size_t vStride, size_t baseStride, size_t outStride)
{
    __shared__ float red[4];
    const int z = blockIdx.y;
    W += (size_t)z * wStride;
    v += (size_t)z * vStride;
    if (base) base += (size_t)z * baseStride;
    out += (size_t)z * outStride;
    const int row = blockIdx.x;
    const int t = threadIdx.x, lane = t & 31, warp = t >> 5;
    const float* wr = W + (size_t)row * ldw + coff;
    float s = 0.f;
    for (int k = t; k < K; k += 128) s += wr[k] * v[k];
#pragma unroll
    for (int o = 16; o; o >>= 1) s += __shfl_down_sync(0xffffffffu, s, o);
    if (lane == 0) red[warp] = s;
    __syncthreads();
    if (t == 0) out[row] = red[0] + red[1] + red[2] + red[3] + (base ? base[row] : 0.f);
}

// ---------------- compaction scan ----------------
__global__ __launch_bounds__(1024) void scan_kernel(
    const int* __restrict__ lens, int* __restrict__ off, int* __restrict__ total)
{
    __shared__ int wsum[32];
    const int tid = threadIdx.x, lane = tid & 31, warp = tid >> 5;
    int v[4], s = 0;
#pragma unroll
    for (int i = 0; i < 4; i++) { v[i] = lens[tid * 4 + i]; s += v[i]; }
    int ws = s;
#pragma unroll
    for (int o = 1; o < 32; o <<= 1) { int t = __shfl_up_sync(0xffffffffu, ws, o); if (lane >= o) ws += t; }
    if (lane == 31) wsum[warp] = ws;
    __syncthreads();
    if (warp == 0) {
        int t = wsum[lane];
#pragma unroll
        for (int o = 1; o < 32; o <<= 1) { int u = __shfl_up_sync(0xffffffffu, t, o); if (lane >= o) t += u; }
        wsum[lane] = t;
    }
    __syncthreads();
    int run = ws - s + (warp ? wsum[warp - 1] : 0);
#pragma unroll
    for (int i = 0; i < 4; i++) { off[tid * 4 + i] = run; run += v[i]; }
    if (tid == 1023) { off[NS] = run; total[0] = run; }
}

__global__ __launch_bounds__(32) void fill_rows_kernel(
    const int* __restrict__ lens, const int* __restrict__ off,
    const int* __restrict__ toks, int* __restrict__ rowtok)
{
    const int b = blockIdx.x;
    const int len = lens[b], o = off[b];
    for (int s = threadIdx.x; s < len; s += 32) rowtok[o + s] = toks[b * LS + s];
}

__global__ __launch_bounds__(128) void gather_split_kernel(
    const float* __restrict__ wte, const int* __restrict__ rowtok,
    const int* __restrict__ total,
    __nv_bfloat16* __restrict__ Ah, __nv_bfloat16* __restrict__ Al)
{
    const int r = blockIdx.x;
    if (r >= total[0]) return;
    const float2* src = reinterpret_cast<const float2*>(wte + (size_t)rowtok[r] * DE);
    uint32_t* dh = reinterpret_cast<uint32_t*>(Ah) + (size_t)r * (DE / 2);
    uint32_t* dl = reinterpret_cast<uint32_t*>(Al) + (size_t)r * (DE / 2);
#pragma unroll
    for (int i = 0; i < 3; i++) {
        const int j = threadIdx.x + 128 * i;
        const float2 v = src[j];
        uint32_t p, q;
        split2(v.x, v.y, p, q);
        dh[j] = p; dl[j] = q;
    }
}

// ================= HMMA GEMM: C[M,N] = A[M,K] @ B[N,K]^T + bias (+rs*bias2) =================
// CTA tile 256x128, warp tile 64x64 (8 warps, 4M x 2N). STAGES=2, one sync/chunk.
// 3-term bf16: C = Ah*Bh + Ah*Bl + Al*Bh. blockIdx.z batching via strides.
#define CHUNK  64
#define STG_BYTES (96 * 1024)
#define OFF_AH 0
#define OFF_AL 32768
#define OFF_BH 65536
#define OFF_BL 81920
#define TG_SMEM  (2 * STG_BYTES + 256)

template<int AMODE, int BMODE, bool RELU, bool WF32, bool WSPLIT, bool MDYN, bool HASB2>
__global__ __launch_bounds__(256, 1) void tgemm_kernel(
    int M, int N, int K, int K1,
    const __nv_bfloat16* __restrict__ Ah, const __nv_bfloat16* __restrict__ Al, int lda,
    const __nv_bfloat16* __restrict__ A2h, const __nv_bfloat16* __restrict__ A2l, int lda2,
    const int* __restrict__ Mlim,
    const __nv_bfloat16* __restrict__ Bh, const __nv_bfloat16* __restrict__ Bl, int ldb,
    const __nv_bfloat16* __restrict__ B2h, const __nv_bfloat16* __restrict__ B2l, int ldb2,
    const float* __restrict__ bias, const float* __restrict__ bias2,
    const int* __restrict__ rowscale,
    float* __restrict__ C,
    __nv_bfloat16* __restrict__ Ch, __nv_bfloat16* __restrict__ Cl,
    size_t strideA, size_t strideB, size_t strideC)
{
    extern __shared__ char smem[];
    const uint32_t sb = smem_u32(smem);

    const int z = blockIdx.z;
    if (strideA) { Ah += (size_t)z * strideA; Al += (size_t)z * strideA; }
    if (strideB) { Bh += (size_t)z * strideB; Bl += (size_t)z * strideB; }
    if (strideC) { Ch += (size_t)z * strideC; Cl += (size_t)z * strideC; }

    const int tid  = threadIdx.x;
    const int lane = tid & 31;
    const int wid  = tid >> 5;
    const int bm = blockIdx.y * 256, bn = blockIdx.x * 128;

    int Mtot = M;
    if (MDYN) {
        Mtot = Mlim[0];
        if (bm >= Mtot) return;
    }

    const int nch = K / CHUNK;

    auto issue_stage = [&](int c) {
        const int k0 = c * CHUNK;
        const uint32_t st = sb + (c & 1) * STG_BYTES;
        // A: 256 rows x 8 segs (hi+lo)
#pragma unroll
        for (int i = 0; i < 8; i++) {
            const int idx = tid + 256 * i;
            const int row = idx >> 3;
            const int seg = idx & 7;
            const uint32_t sw = sw128(row * 128 + seg * 16);
            int ar = bm + row;
            if (MDYN && ar >= Mtot) ar = Mtot - 1;
            const __nv_bfloat16 *pah, *pal;
            if (AMODE == 2 && k0 >= K1) {
                const size_t off = (size_t)ar * lda2 + (k0 - K1) + seg * 8;
                pah = A2h + off; pal = A2l + off;
            } else {
                const size_t off = (size_t)ar * lda + k0 + seg * 8;
                pah = Ah + off; pal = Al + off;
            }
            CP_ASYNC16(st + OFF_AH + sw, pah);
            CP_ASYNC16(st + OFF_AL + sw, pal);
        }
        // B: 128 rows x 8 segs (hi+lo)
#pragma unroll
        for (int i = 0; i < 4; i++) {
            const int idx = tid + 256 * i;
            const int row = idx >> 3;
            const int seg = idx & 7;
            const uint32_t sw = sw128(row * 128 + seg * 16);
            const __nv_bfloat16 *pbh, *pbl;
            if (BMODE == 2 && k0 >= K1) {
                const size_t off = (size_t)(bn + row) * ldb2 + (k0 - K1) + seg * 8;
                pbh = B2h + off; pbl = B2l + off;
            } else {
                const size_t off = (size_t)(bn + row) * ldb + k0 + seg * 8;
                pbh = Bh + off; pbl = Bl + off;
            }
            CP_ASYNC16(st + OFF_BH + sw, pbh);
            CP_ASYNC16(st + OFF_BL + sw, pbl);
        }
        CP_COMMIT();
    };

    issue_stage(0);

    const int wm = (wid >> 1) * 64;
    const int wn = (wid & 1) * 64;

    float acc[4][8][4];
#pragma unroll
    for (int i = 0; i < 4; i++)
#pragma unroll
        for (int j = 0; j < 8; j++)
#pragma unroll
            for (int t = 0; t < 4; t++) acc[i][j][t] = 0.f;

    const int a_row  = (lane & 15);
    const int a_kb   = (lane >> 4) * 16;
    const int b_row  = (lane & 7) + ((lane >> 4) << 3);
    const int b_kb   = ((lane >> 3) & 1) * 16;

    for (int c = 0; c < nch; c++) {
        CP_WAIT(0);             // chunk c data arrived (only group outstanding)
        __syncthreads();        // visibility + guards buffer (c+1)&1 (read finished for chunk c-1)
        if (c + 1 < nch) issue_stage(c + 1);

        const uint32_t st = sb + (c & 1) * STG_BYTES;

#pragma unroll
        for (int ks = 0; ks < 4; ks++) {
            const int kb = ks * 32;
            uint32_t ah[4][4], al[4][4];
#pragma unroll
            for (int i = 0; i < 4; i++) {
                const uint32_t oa = sw128((wm + i * 16 + a_row) * 128 + kb + a_kb);
                LDSM4(ah[i], st + OFF_AH + oa);
                LDSM4(al[i], st + OFF_AL + oa);
            }
            uint32_t bf[4][4];
#pragma unroll
            for (int j2 = 0; j2 < 4; j2++) {
                const uint32_t ob = sw128((wn + j2 * 16 + b_row) * 128 + kb + b_kb);
                LDSM4(bf[j2], st + OFF_BH + ob);
            }
            // Ah*Bh + Al*Bh
#pragma unroll
            for (int i = 0; i < 4; i++)
#pragma unroll
                for (int j2 = 0; j2 < 4; j2++) {
                    mma16816(acc[i][2 * j2 + 0], ah[i], bf[j2][0], bf[j2][1]);
                    mma16816(acc[i][2 * j2 + 1], ah[i], bf[j2][2], bf[j2][3]);
                    mma16816(acc[i][2 * j2 + 0], al[i], bf[j2][0], bf[j2][1]);
                    mma16816(acc[i][2 * j2 + 1], al[i], bf[j2][2], bf[j2][3]);
                }
            // Ah*Bl
#pragma unroll
            for (int j2 = 0; j2 < 4; j2++) {
                const uint32_t ob = sw128((wn + j2 * 16 + b_row) * 128 + kb + b_kb);
                LDSM4(bf[j2], st + OFF_BL + ob);
            }
#pragma unroll
            for (int i = 0; i < 4; i++)
#pragma unroll
                for (int j2 = 0; j2 < 4; j2++) {
                    mma16816(acc[i][2 * j2 + 0], ah[i], bf[j2][0], bf[j2][1]);
                    mma16816(acc[i][2 * j2 + 1], ah[i], bf[j2][2], bf[j2][3]);
                }
        }
    }

    // ---- epilogue ----
#pragma unroll
    for (int i = 0; i < 4; i++) {
        const int r0 = bm + wm + i * 16 + (lane >> 2);
        const int r1 = r0 + 8;
        const bool ok0 = !MDYN || (r0 < Mtot);
        const bool ok1 = !MDYN || (r1 < Mtot);
        const float rs0 = HASB2 ? (float)rowscale[r0] : 0.f;
        const float rs1 = HASB2 ? (float)rowscale[r1] : 0.f;
#pragma unroll
        for (int j = 0; j < 8; j++) {
            const int col = bn + wn + j * 8 + (lane & 3) * 2;
            float b00 = bias[col], b01 = bias[col + 1];
            float b10 = b00, b11 = b01;
            if (HASB2) {
                b00 += rs0 * bias2[col]; b01 += rs0 * bias2[col + 1];
                b10 += rs1 * bias2[col]; b11 += rs1 * bias2[col + 1];
            }
            float2 v0 = make_float2(acc[i][j][0] + b00, acc[i][j][1] + b01);
            float2 v1 = make_float2(acc[i][j][2] + b10, acc[i][j][3] + b11);
            if (RELU) {
                v0.x = fmaxf(v0.x, 0.f); v0.y = fmaxf(v0.y, 0.f);
                v1.x = fmaxf(v1.x, 0.f); v1.y = fmaxf(v1.y, 0.f);
            }
            if (WF32) {
                if (ok0) *reinterpret_cast<float2*>(C + (size_t)r0 * N + col) = v0;
                if (ok1) *reinterpret_cast<float2*>(C + (size_t)r1 * N + col) = v1;
            }
            if (WSPLIT) {
                uint32_t p, q;
                if (ok0) {
                    split2(v0.x, v0.y, p, q);
                    reinterpret_cast<uint32_t*>(Ch)[((size_t)r0 * N + col) >> 1] = p;
                    reinterpret_cast<uint32_t*>(Cl)[((size_t)r0 * N + col) >> 1] = q;
                }
                if (ok1) {
                    split2(v1.x, v1.y, p, q);
                    reinterpret_cast<uint32_t*>(Ch)[((size_t)r1 * N + col) >> 1] = p;
                    reinterpret_cast<uint32_t*>(Cl)[((size_t)r1 * N + col) >> 1] = q;
                }
            }
        }
    }
}

// ---------------- name attention on compacted qkv, q-summed ----------------
__global__ __launch_bounds__(192) void name_attn_kernel(
    const float* __restrict__ qkv, const int* __restrict__ off,
    __nv_bfloat16* __restrict__ attn_h, __nv_bfloat16* __restrict__ attn_l)
{
    __shared__ float Qs[LS][DHN];
    __shared__ float Ks[LS][DHN];
    __shared__ float Vs[LS][DHN];
    __shared__ float sc[LS][LS + 1];

    const int h = blockIdx.x;
    const int b = blockIdx.y;
    const int d = threadIdx.x;

    const int o   = off[b];
    const int len = off[b + 1] - o;

    const float* base = qkv + (size_t)o * (3 * DE) + h * DHN + d;
    for (int s = 0; s < len; s++) {
        Qs[s][d] = base[s * (3 * DE)];
        Ks[s][d] = base[s * (3 * DE) + DE];
        Vs[s][d] = base[s * (3 * DE) + 2 * DE];
    }
    __syncthreads();

    const int warp = d >> 5, lane = d & 31;
    const float scale = 1.0f / sqrtf((float)DHN);
    const int np = len * len;
    for (int p = warp; p < np; p += 6) {
        const int q = p / len, j = p - q * len;
        float s = 0.f;
#pragma unroll
        for (int i = 0; i < 6; i++) s += Qs[q][lane + 32 * i] * Ks[j][lane + 32 * i];
#pragma unroll
        for (int ofs = 16; ofs; ofs >>= 1) s += __shfl_down_sync(0xffffffffu, s, ofs);
        if (lane == 0) sc[q][j] = s * scale;
    }
    __syncthreads();

    if (d < len) {
        float mx = -1e30f;
        for (int j = 0; j < len; j++) mx = fmaxf(mx, sc[d][j]);
        float sum = 0.f;
        float row[LS];
        for (int j = 0; j < len; j++) { row[j] = expf(sc[d][j] - mx); sum += row[j]; }
        const float inv = 1.f / sum;
        for (int j = 0; j < len; j++) sc[d][j] = row[j] * inv;
    }
    __syncthreads();

    float accum = 0.f;
    for (int s = 0; s < len; s++) {
        float ov = 0.f;
        for (int j = 0; j < len; j++) ov += sc[s][j] * Vs[j][d];
        accum += ov;
    }
    const float a1 = __shfl_down_sync(0xffffffffu, accum, 1);
    if (!(d & 1)) {
        uint32_t p, q;
        split2(accum, a1, p, q);
        const size_t id2 = ((size_t)b * DE + h * DHN + d) >> 1;
        reinterpret_cast<uint32_t*>(attn_h)[id2] = p;
        reinterpret_cast<uint32_t*>(attn_l)[id2] = q;
    }
}

// ---------------- residual + LayerNorm + bf16 split output ----------------
__device__ __forceinline__ float block_reduce_sum(float v) {
    __shared__ float red[8];
    const int lane = threadIdx.x & 31, warp = threadIdx.x >> 5;
#pragma unroll
    for (int o = 16; o; o >>= 1) v += __shfl_down_sync(0xffffffffu, v, o);
    if (lane == 0) red[warp] = v;
    __syncthreads();
    v = (threadIdx.x < 8) ? red[threadIdx.x] : 0.f;
    if (warp == 0)
#pragma unroll
        for (int o = 4; o; o >>= 1) v += __shfl_down_sync(0xffffffffu, v, o);
    return v;
}

__global__ __launch_bounds__(256) void resid_ln_kernel(
    float* __restrict__ h, const float* __restrict__ a,
    const float* __restrict__ g, const float* __restrict__ b,
    __nv_bfloat16* __restrict__ hh, __nv_bfloat16* __restrict__ hl)
{
    const int row = blockIdx.x;
    const int t = threadIdx.x;
    float v[4];
    float s = 0.f;
#pragma unroll
    for (int i = 0; i < 4; i++) {
        const int c = t + 256 * i;
        v[i] = h[(size_t)row * HD + c] + a[(size_t)row * HD + c];
        s += v[i];
    }
    s = block_reduce_sum(s);
    __shared__ float mean_s, rstd_s;
    if (t == 0) mean_s = s * (1.f / HD);
    __syncthreads();
    const float m = mean_s;
    float s2 = 0.f;
#pragma unroll
    for (int i = 0; i < 4; i++) { const float dd = v[i] - m; s2 += dd * dd; }
    s2 = block_reduce_sum(s2);
    if (t == 0) rstd_s = rsqrtf(s2 * (1.f / HD) + 1e-5f);
    __syncthreads();
    const float r = rstd_s;
#pragma unroll
    for (int i = 0; i < 4; i++) {
        const int c = t + 256 * i;
        const float y = (v[i] - m) * r * g[c] + b[c];
        h[(size_t)row * HD + c] = y;
        const float y1 = __shfl_down_sync(0xffffffffu, y, 1);
        if (!(t & 1)) {
            uint32_t p, q;
            split2(y, y1, p, q);
            const size_t id2 = ((size_t)row * HD + c) >> 1;
            reinterpret_cast<uint32_t*>(hh)[id2] = p;
            reinterpret_cast<uint32_t*>(hl)[id2] = q;
        }
    }
}

// ---------------- classifier head ----------------
__global__ __launch_bounds__(512) void cls_kernel(
    const float* __restrict__ h, const float* __restrict__ w,
    const float* __restrict__ b, float* __restrict__ out)
{
    const int m = blockIdx.x;
    const int c = threadIdx.x >> 5;
    const int lane = threadIdx.x & 31;
    const float* hr = h + (size_t)m * HD;
    const float* wr = w + (size_t)c * HD;
    float s = 0.f;
#pragma unroll
    for (int i = lane; i < HD; i += 32) s += hr[i] * wr[i];
#pragma unroll
    for (int o = 16; o; o >>= 1) s += __shfl_down_sync(0xffffffffu, s, o);
    if (lane == 0) out[(size_t)m * NCLS + c] = s + b[c];
}

// ---------------- orchestration ----------------
static inline void launch_split(const float* src, __nv_bfloat16* hi, __nv_bfloat16* lo, size_t n) {
    const int n2 = (int)(n / 2);
    split_kernel<<<(n2 + 255) / 256, 256>>>(src, hi, lo, n2);
}

extern "C" void kernel_launch(void* const* d_in, const int* in_sizes, int n_in,
                              void* d_out, int out_size)
{
    const int*   name_tokens = (const int*)d_in[0];
    const int*   name_lens   = (const int*)d_in[1];
    const float* x_feats     = (const float*)d_in[2];
    const float* wte         = (const float*)d_in[3];
    const float* mha_in_w    = (const float*)d_in[4];
    const float* mha_in_b    = (const float*)d_in[5];
    const float* mha_out_w   = (const float*)d_in[6];
    const float* mha_out_b   = (const float*)d_in[7];
    const float* bott_w      = (const float*)d_in[8];
    const float* bott_b      = (const float*)d_in[9];
    const float* enc_in_w    = (const float*)d_in[10];
    const float* enc_in_b    = (const float*)d_in[11];
    const float* enc_out_w   = (const float*)d_in[12];
    const float* enc_out_b   = (const float*)d_in[13];
    const float* enc_ln1_g   = (const float*)d_in[14];
    const float* enc_ln1_b   = (const float*)d_in[15];
    const float* enc_ln2_g   = (const float*)d_in[16];
    const float* enc_ln2_b   = (const float*)d_in[17];
    const float* enc_ff1_w   = (const float*)d_in[18];
    const float* enc_ff1_b   = (const float*)d_in[19];
    const float* enc_ff2_w   = (const float*)d_in[20];
    const float* enc_ff2_b   = (const float*)d_in[21];
    const float* cls_w       = (const float*)d_in[22];
    const float* cls_b       = (const float*)d_in[23];
    float* out = (float*)d_out;

    float *qkv, *h, *ta, *zero, *bc, *bao;
    int *off, *total, *rowtok;
    cudaGetSymbolAddress((void**)&qkv,    g_qkv);
    cudaGetSymbolAddress((void**)&h,      g_h);
    cudaGetSymbolAddress((void**)&ta,     g_ta);
    cudaGetSymbolAddress((void**)&zero,   g_zero);
    cudaGetSymbolAddress((void**)&bc,     g_bc);
    cudaGetSymbolAddress((void**)&bao,    g_bao);
    cudaGetSymbolAddress((void**)&off,    g_off);
    cudaGetSymbolAddress((void**)&total,  g_total);
    cudaGetSymbolAddress((void**)&rowtok, g_rowtok);

    __nv_bfloat16 *gah, *gal, *attn_h, *attn_l, *xf_h, *xf_l, *hh, *hl, *t1_h, *t1_l;
    __nv_bfloat16 *wqkv_h, *wqkv_l, *wbott_h, *wbott_l, *wo_h, *wo_l, *wf1_h, *wf1_l, *wf2_h, *wf2_l;
    __nv_bfloat16 *wvt_h, *wvt_l, *woutt_h, *woutt_l, *wc_h, *wc_l, *wao_h, *wao_l;
    cudaGetSymbolAddress((void**)&gah,    g_gah);     cudaGetSymbolAddress((void**)&gal,    g_gal);
    cudaGetSymbolAddress((void**)&attn_h, g_attn_h);  cudaGetSymbolAddress((void**)&attn_l, g_attn_l);
    cudaGetSymbolAddress((void**)&xf_h,   g_xf_h);    cudaGetSymbolAddress((void**)&xf_l,   g_xf_l);
    cudaGetSymbolAddress((void**)&hh,     g_hh);      cudaGetSymbolAddress((void**)&hl,     g_hl);
    cudaGetSymbolAddress((void**)&t1_h,   g_t1_h);    cudaGetSymbolAddress((void**)&t1_l,   g_t1_l);
    cudaGetSymbolAddress((void**)&wqkv_h, g_wqkv_h);  cudaGetSymbolAddress((void**)&wqkv_l, g_wqkv_l);
    cudaGetSymbolAddress((void**)&wbott_h,g_wbott_h); cudaGetSymbolAddress((void**)&wbott_l,g_wbott_l);
    cudaGetSymbolAddress((void**)&wo_h,   g_wo_h);    cudaGetSymbolAddress((void**)&wo_l,   g_wo_l);
    cudaGetSymbolAddress((void**)&wf1_h,  g_wf1_h);   cudaGetSymbolAddress((void**)&wf1_l,  g_wf1_l);
    cudaGetSymbolAddress((void**)&wf2_h,  g_wf2_h);   cudaGetSymbolAddress((void**)&wf2_l,  g_wf2_l);
    cudaGetSymbolAddress((void**)&wvt_h,  g_wvt_h);   cudaGetSymbolAddress((void**)&wvt_l,  g_wvt_l);
    cudaGetSymbolAddress((void**)&woutt_h,g_woutt_h); cudaGetSymbolAddress((void**)&woutt_l,g_woutt_l);
    cudaGetSymbolAddress((void**)&wc_h,   g_wc_h);    cudaGetSymbolAddress((void**)&wc_l,   g_wc_l);
    cudaGetSymbolAddress((void**)&wao_h,  g_wao_h);   cudaGetSymbolAddress((void**)&wao_l,  g_wao_l);

    auto k_qkv   = tgemm_kernel<0, 0, false, true,  false, true,  false>;
    auto k_bott  = tgemm_kernel<2, 2, false, true,  true,  false, true >;
    auto k_plain = tgemm_kernel<0, 0, false, true,  false, false, false>;
    auto k_ff1   = tgemm_kernel<0, 0, true,  false, true,  false, false>;
    auto k_pre   = tgemm_kernel<0, 0, false, false, true,  false, false>;
    cudaFuncSetAttribute(k_qkv,   cudaFuncAttributeMaxDynamicSharedMemorySize, TG_SMEM);
    cudaFuncSetAttribute(k_bott,  cudaFuncAttributeMaxDynamicSharedMemorySize, TG_SMEM);
    cudaFuncSetAttribute(k_plain, cudaFuncAttributeMaxDynamicSharedMemorySize, TG_SMEM);
    cudaFuncSetAttribute(k_ff1,   cudaFuncAttributeMaxDynamicSharedMemorySize, TG_SMEM);
    cudaFuncSetAttribute(k_pre,   cudaFuncAttributeMaxDynamicSharedMemorySize, TG_SMEM);

    // ---- 0a. compaction metadata + gathered embedding split ----
    scan_kernel<<<1, 1024>>>(name_lens, off, total);
    fill_rows_kernel<<<NS, 32>>>(name_lens, off, name_tokens, rowtok);
    gather_split_kernel<<<NS * LS, 128>>>(wte, rowtok, total, gah, gal);

    // ---- 0b. split weights + x_feats (batched across layers where contiguous) ----
    launch_split(mha_in_w,  wqkv_h,  wqkv_l,  (size_t)3 * DE * DE);
    launch_split(bott_w,    wbott_h, wbott_l, (size_t)HD * (XFD + DE));
    launch_split(x_feats,   xf_h,    xf_l,    (size_t)NS * XFD);
    launch_split(enc_out_w, wo_h,    wo_l,    (size_t)NLAY * HD * HD);
    launch_split(enc_ff1_w, wf1_h,   wf1_l,   (size_t)NLAY * 2 * HD * HD);
    launch_split(enc_ff2_w, wf2_h,   wf2_l,   (size_t)NLAY * HD * 2 * HD);
    // batched transposed split of Wv (layer stride 3*HD*HD in src)
    transpose_split_kernel<<<dim3(HD / 32, HD / 32, NLAY), dim3(32, 8)>>>(
        enc_in_w + (size_t)2 * HD * HD, HD, HD, wvt_h, wvt_l,
        (size_t)3 * HD * HD, (size_t)HD * HD);
    transpose_split_kernel<<<dim3(DE / 32, DE / 32, 1), dim3(32, 8)>>>(
        mha_out_w, DE, DE, woutt_h, woutt_l, 0, 0);
    // batched folded bias bc[l] = Wo[l] @ bv[l] + bo[l]
    bias_fold_kernel<<<dim3(HD, NLAY), 128>>>(
        enc_out_w, HD, 0, enc_in_b + 2 * HD, enc_out_b, bc, HD,
        (size_t)HD * HD, (size_t)3 * HD, (size_t)HD, (size_t)HD);
    bias_fold_kernel<<<dim3(HD, 1), 128>>>(
        bott_w, XFD + DE, XFD, mha_out_b, nullptr, bao, DE, 0, 0, 0, 0);

    // ---- 0c. weight-fold GEMMs ----
    // batched: Wc[l] = Wo[l] @ Wv[l]
    k_pre<<<dim3(HD / 128, HD / 256, NLAY), 256, TG_SMEM>>>(
        HD, HD, HD, 0,
        wo_h, wo_l, HD, nullptr, nullptr, 0, nullptr,
        wvt_h, wvt_l, HD, nullptr, nullptr, 0,
        zero, nullptr, nullptr,
        nullptr, wc_h, wc_l,
        (size_t)HD * HD, (size_t)HD * HD, (size_t)HD * HD);
    // Wao = Wb2 @ Wout
    k_pre<<<dim3(DE / 128, HD / 256, 1), 256, TG_SMEM>>>(
        HD, DE, DE, 0,
        wbott_h + XFD, wbott_l + XFD, XFD + DE, nullptr, nullptr, 0, nullptr,
        woutt_h, woutt_l, DE, nullptr, nullptr, 0,
        zero, nullptr, nullptr,
        nullptr, wao_h, wao_l, 0, 0, 0);

    const int MQ = NS * LS;
    const int KQ = DE;
    const int NQ = 3 * DE;

    // 1. qkv(compact) = gathered_emb @ mha_in_w^T + mha_in_b
    k_qkv<<<dim3(NQ / 128, MQ / 256, 1), 256, TG_SMEM>>>(
        MQ, NQ, KQ, 0,
        gah, gal, KQ, nullptr, nullptr, 0, total,
        wqkv_h, wqkv_l, KQ, nullptr, nullptr, 0,
        mha_in_b, nullptr, nullptr, qkv, nullptr, nullptr, 0, 0, 0);

    // 2. name attention on compact rows -> attnsum split
    name_attn_kernel<<<dim3(NHN, NS), 192>>>(qkv, off, attn_h, attn_l);

    // 3. x = xf@Wb1^T + attnsum@Wao^T + bbott + len*bao -> h fp32 + split
    k_bott<<<dim3(HD / 128, NS / 256, 1), 256, TG_SMEM>>>(
        NS, HD, XFD + DE, XFD,
        xf_h, xf_l, XFD, attn_h, attn_l, DE, nullptr,
        wbott_h, wbott_l, XFD + DE, wao_h, wao_l, DE,
        bott_b, bao, name_lens, h, hh, hl, 0, 0, 0);

    // 4. encoder layers
    for (int l = 0; l < NLAY; l++) {
        k_plain<<<dim3(HD / 128, NS / 256, 1), 256, TG_SMEM>>>(
            NS, HD, HD, 0,
            hh, hl, HD, nullptr, nullptr, 0, nullptr,
            wc_h + (size_t)l * HD * HD, wc_l + (size_t)l * HD * HD, HD,
            nullptr, nullptr, 0,
            bc + (size_t)l * HD, nullptr, nullptr, ta, nullptr, nullptr, 0, 0, 0);
        resid_ln_kernel<<<NS, 256>>>(h, ta, enc_ln1_g + (size_t)l * HD, enc_ln1_b + (size_t)l * HD, hh, hl);

        k_ff1<<<dim3(2 * HD / 128, NS / 256, 1), 256, TG_SMEM>>>(
            NS, 2 * HD, HD, 0,
            hh, hl, HD, nullptr, nullptr, 0, nullptr,
            wf1_h + (size_t)l * 2 * HD * HD, wf1_l + (size_t)l * 2 * HD * HD, HD,
            nullptr, nullptr, 0,
            enc_ff1_b + (size_t)l * 2 * HD, nullptr, nullptr, nullptr, t1_h, t1_l, 0, 0, 0);
        k_plain<<<dim3(HD / 128, NS / 256, 1), 256, TG_SMEM>>>(
            NS, HD, 2 * HD, 0,
            t1_h, t1_l, 2 * HD, nullptr, nullptr, 0, nullptr,
            wf2_h + (size_t)l * HD * 2 * HD, wf2_l + (size_t)l * HD * 2 * HD, 2 * HD,
            nullptr, nullptr, 0,
            enc_ff2_b + (size_t)l * HD, nullptr, nullptr, ta, nullptr, nullptr, 0, 0, 0);
        resid_ln_kernel<<<NS, 256>>>(h, ta, enc_ln2_g + (size_t)l * HD, enc_ln2_b + (size_t)l * HD, hh, hl);
    }

    // 5. classifier head
    cls_kernel<<<NS, 512>>>(h, cls_w, cls_b, out);
}

// round 9
// speedup vs baseline: 4.5245x; 1.0154x over previous
#include <cuda_runtime.h>
#include <cuda_bf16.h>
#include <cstdint>
#include <math.h>

// ---------------- problem constants ----------------
#define NS    4096          // N samples
#define LS    16            // L tokens
#define DE    768           // D embedding
#define NHN   4             // heads (name attn)
#define DHN   192           // head dim (name attn)
#define HD    1024          // H
#define NLAY  4             // NL
#define NCLS  16            // C
#define XFD   256           // XF

// ---------------- scratch (device globals; no cudaMalloc allowed) ----------------
__device__ float g_qkv[(size_t)NS * LS * 3 * DE];   // compacted qkv rows, fp32 (for attn)
__device__ float g_h[(size_t)NS * HD];              // fp32 residual stream
__device__ float g_ta[(size_t)NS * HD];             // fp32 (LN input)

__device__ int g_off[NS + 1];
__device__ int g_total[1];
__device__ int g_rowtok[NS * LS];

__device__ float g_zero[2048];
__device__ float g_bc[NLAY * HD];
__device__ float g_bao[HD];

// bf16 hi/lo split buffers (activations)
__device__ __align__(16) __nv_bfloat16 g_gah[(size_t)NS * LS * DE],   g_gal[(size_t)NS * LS * DE];
__device__ __align__(16) __nv_bfloat16 g_attn_h[(size_t)NS * DE],     g_attn_l[(size_t)NS * DE];
__device__ __align__(16) __nv_bfloat16 g_xf_h[(size_t)NS * XFD],      g_xf_l[(size_t)NS * XFD];
__device__ __align__(16) __nv_bfloat16 g_hh[(size_t)NS * HD],         g_hl[(size_t)NS * HD];
__device__ __align__(16) __nv_bfloat16 g_t1_h[(size_t)NS * 2 * HD],   g_t1_l[(size_t)NS * 2 * HD];

// bf16 hi/lo split buffers (weights)
__device__ __align__(16) __nv_bfloat16 g_wqkv_h[(size_t)3 * DE * DE], g_wqkv_l[(size_t)3 * DE * DE];
__device__ __align__(16) __nv_bfloat16 g_wbott_h[(size_t)HD * (XFD + DE)], g_wbott_l[(size_t)HD * (XFD + DE)];
__device__ __align__(16) __nv_bfloat16 g_wo_h[(size_t)NLAY * HD * HD],  g_wo_l[(size_t)NLAY * HD * HD];
__device__ __align__(16) __nv_bfloat16 g_wf1_h[(size_t)NLAY * 2 * HD * HD], g_wf1_l[(size_t)NLAY * 2 * HD * HD];
__device__ __align__(16) __nv_bfloat16 g_wf2_h[(size_t)NLAY * HD * 2 * HD], g_wf2_l[(size_t)NLAY * HD * 2 * HD];
__device__ __align__(16) __nv_bfloat16 g_wvt_h[(size_t)NLAY * HD * HD],  g_wvt_l[(size_t)NLAY * HD * HD];
__device__ __align__(16) __nv_bfloat16 g_woutt_h[(size_t)DE * DE],       g_woutt_l[(size_t)DE * DE];
__device__ __align__(16) __nv_bfloat16 g_wc_h[(size_t)NLAY * HD * HD],   g_wc_l[(size_t)NLAY * HD * HD];
__device__ __align__(16) __nv_bfloat16 g_wao_h[(size_t)HD * DE],         g_wao_l[(size_t)HD * DE];

// ================= helpers =================
__device__ __forceinline__ uint32_t smem_u32(const void* p) {
    uint32_t a;
    asm("{ .reg .u64 t; cvta.to.shared.u64 t, %1; cvt.u32.u64 %0, t; }" : "=r"(a) : "l"(p));
    return a;
}
__device__ __forceinline__ uint32_t sw128(uint32_t o) { return o ^ ((o >> 3) & 0x70); }

#define LDSM4(r, addr) \
    asm volatile("ldmatrix.sync.aligned.m8n8.x4.shared.b16 {%0,%1,%2,%3}, [%4];" \
        : "=r"((r)[0]), "=r"((r)[1]), "=r"((r)[2]), "=r"((r)[3]) : "r"(addr))

__device__ __forceinline__ void mma16816(float* c, const uint32_t* a, uint32_t b0, uint32_t b1) {
    asm volatile("mma.sync.aligned.m16n8k16.row.col.f32.bf16.bf16.f32 "
        "{%0,%1,%2,%3},{%4,%5,%6,%7},{%8,%9},{%0,%1,%2,%3};"
        : "+f"(c[0]), "+f"(c[1]), "+f"(c[2]), "+f"(c[3])
        : "r"(a[0]), "r"(a[1]), "r"(a[2]), "r"(a[3]), "r"(b0), "r"(b1));
}

#define CP_ASYNC16(dst, src) \
    asm volatile("cp.async.cg.shared.global [%0], [%1], 16;" :: "r"(dst), "l"(src))
#define CP_COMMIT() asm volatile("cp.async.commit_group;" ::: "memory")
#define CP_WAIT(n)  asm volatile("cp.async.wait_group %0;" :: "n"(n) : "memory")

// split fp32 pair -> packed bf16 hi (p) and lo residual (q)
__device__ __forceinline__ void split2(float x, float y, uint32_t& p, uint32_t& q) {
    asm("cvt.rn.bf16x2.f32 %0, %1, %2;" : "=r"(p) : "f"(y), "f"(x));
    float h0 = __uint_as_float(p << 16);
    float h1 = __uint_as_float(p & 0xffff0000u);
    float r0 = x - h0, r1 = y - h1;
    asm("cvt.rn.bf16x2.f32 %0, %1, %2;" : "=r"(q) : "f"(r1), "f"(r0));
}

// ---------------- fp32 -> bf16 hi/lo split ----------------
__global__ __launch_bounds__(256) void split_kernel(
    const float* __restrict__ src,
    __nv_bfloat16* __restrict__ hi, __nv_bfloat16* __restrict__ lo, int n2)
{
    const int i = blockIdx.x * blockDim.x + threadIdx.x;
    if (i < n2) {
        const float2 v = reinterpret_cast<const float2*>(src)[i];
        uint32_t p, q;
        split2(v.x, v.y, p, q);
        reinterpret_cast<uint32_t*>(hi)[i] = p;
        reinterpret_cast<uint32_t*>(lo)[i] = q;
    }
}

// ---------------- batched fp32 [R x C] -> transposed bf16 hi/lo [C x R] ----------------
__global__ __launch_bounds__(256) void transpose_split_kernel(
    const float* __restrict__ src, int ld, int R,
    __nv_bfloat16* __restrict__ dh, __nv_bfloat16* __restrict__ dl,
    size_t srcStride, size_t dstStride)
{
    __shared__ float tile[32][33];
    const int z = blockIdx.z;
    src += (size_t)z * srcStride;
    dh  += (size_t)z * dstStride;
    dl  += (size_t)z * dstStride;
    const int c0 = blockIdx.x * 32, r0 = blockIdx.y * 32;
    const int tx = threadIdx.x, ty = threadIdx.y;   // (32, 8)
#pragma unroll
    for (int i = ty; i < 32; i += 8)
        tile[i][tx] = src[(size_t)(r0 + i) * ld + c0 + tx];
    __syncthreads();
    if (tx < 16) {
#pragma unroll
        for (int i = ty; i < 32; i += 8) {
            uint32_t p, q;
            split2(tile[2 * tx][i], tile[2 * tx + 1][i], p, q);
            const size_t id2 = ((size_t)(c0 + i) * R + r0) / 2 + tx;
            reinterpret_cast<uint32_t*>(dh)[id2] = p;
            reinterpret_cast<uint32_t*>(dl)[id2] = q;
        }
    }
}

// ---------------- batched bias fold: out[row] = W[row,:]·v + base[row] ----------------
__global__ __launch_bounds__(128) void bias_fold_kernel(
    const float* __restrict__ W, int ldw, int coff,
    const float* __restrict__ v, const float* __restrict__ base,
    float* __restrict__ out, int K,
    size_t wStride, size_t vStride, size_t baseStride, size_t outStride)
{
    __shared__ float red[4];
    const int z = blockIdx.y;
    W += (size_t)z * wStride;
    v += (size_t)z * vStride;
    if (base) base += (size_t)z * baseStride;
    out += (size_t)z * outStride;
    const int row = blockIdx.x;
    const int t = threadIdx.x, lane = t & 31, warp = t >> 5;
    const float* wr = W + (size_t)row * ldw + coff;
    float s = 0.f;
    for (int k = t; k < K; k += 128) s += wr[k] * v[k];
#pragma unroll
    for (int o = 16; o; o >>= 1) s += __shfl_down_sync(0xffffffffu, s, o);
    if (lane == 0) red[warp] = s;
    __syncthreads();
    if (t == 0) out[row] = red[0] + red[1] + red[2] + red[3] + (base ? base[row] : 0.f);
}

// ---------------- compaction scan ----------------
__global__ __launch_bounds__(1024) void scan_kernel(
    const int* __restrict__ lens, int* __restrict__ off, int* __restrict__ total)
{
    __shared__ int wsum[32];
    const int tid = threadIdx.x, lane = tid & 31, warp = tid >> 5;
    int v[4], s = 0;
#pragma unroll
    for (int i = 0; i < 4; i++) { v[i] = lens[tid * 4 + i]; s += v[i]; }
    int ws = s;
#pragma unroll
    for (int o = 1; o < 32; o <<= 1) { int t = __shfl_up_sync(0xffffffffu, ws, o); if (lane >= o) ws += t; }
    if (lane == 31) wsum[warp] = ws;
    __syncthreads();
    if (warp == 0) {
        int t = wsum[lane];
#pragma unroll
        for (int o = 1; o < 32; o <<= 1) { int u = __shfl_up_sync(0xffffffffu, t, o); if (lane >= o) t += u; }
        wsum[lane] = t;
    }
    __syncthreads();
    int run = ws - s + (warp ? wsum[warp - 1] : 0);
#pragma unroll
    for (int i = 0; i < 4; i++) { off[tid * 4 + i] = run; run += v[i]; }
    if (tid == 1023) { off[NS] = run; total[0] = run; }
}

__global__ __launch_bounds__(32) void fill_rows_kernel(
    const int* __restrict__ lens, const int* __restrict__ off,
    const int* __restrict__ toks, int* __restrict__ rowtok)
{
    const int b = blockIdx.x;
    const int len = lens[b], o = off[b];
    for (int s = threadIdx.x; s < len; s += 32) rowtok[o + s] = toks[b * LS + s];
}

__global__ __launch_bounds__(128) void gather_split_kernel(
    const float* __restrict__ wte, const int* __restrict__ rowtok,
    const int* __restrict__ total,
    __nv_bfloat16* __restrict__ Ah, __nv_bfloat16* __restrict__ Al)
{
    const int r = blockIdx.x;
    if (r >= total[0]) return;
    const float2* src = reinterpret_cast<const float2*>(wte + (size_t)rowtok[r] * DE);
    uint32_t* dh = reinterpret_cast<uint32_t*>(Ah) + (size_t)r * (DE / 2);
    uint32_t* dl = reinterpret_cast<uint32_t*>(Al) + (size_t)r * (DE / 2);
#pragma unroll
    for (int i = 0; i < 3; i++) {
        const int j = threadIdx.x + 128 * i;
        const float2 v = src[j];
        uint32_t p, q;
        split2(v.x, v.y, p, q);
        dh[j] = p; dl[j] = q;
    }
}

// ================= HMMA GEMM: C[M,N] = A[M,K] @ B[N,K]^T + bias (+rs*bias2) =================
// CTA tile 256x128, warp tile 64x64 (8 warps, 4M x 2N). STAGES=2, one sync/chunk.
// 3-term bf16: C = Ah*Bh + Ah*Bl + Al*Bh. blockIdx.z batching via strides.
#define CHUNK  64
#define STG_BYTES (96 * 1024)
#define OFF_AH 0
#define OFF_AL 32768
#define OFF_BH 65536
#define OFF_BL 81920
#define TG_SMEM  (2 * STG_BYTES + 256)

template<int AMODE, int BMODE, bool RELU, bool WF32, bool WSPLIT, bool MDYN, bool HASB2>
__global__ __launch_bounds__(256, 1) void tgemm_kernel(
    int M, int N, int K, int K1,
    const __nv_bfloat16* __restrict__ Ah, const __nv_bfloat16* __restrict__ Al, int lda,
    const __nv_bfloat16* __restrict__ A2h, const __nv_bfloat16* __restrict__ A2l, int lda2,
    const int* __restrict__ Mlim,
    const __nv_bfloat16* __restrict__ Bh, const __nv_bfloat16* __restrict__ Bl, int ldb,
    const __nv_bfloat16* __restrict__ B2h, const __nv_bfloat16* __restrict__ B2l, int ldb2,
    const float* __restrict__ bias, const float* __restrict__ bias2,
    const int* __restrict__ rowscale,
    float* __restrict__ C,
    __nv_bfloat16* __restrict__ Ch, __nv_bfloat16* __restrict__ Cl,
    size_t strideA, size_t strideB, size_t strideC)
{
    extern __shared__ char smem[];
    const uint32_t sb = smem_u32(smem);

    const int z = blockIdx.z;
    if (strideA) { Ah += (size_t)z * strideA; Al += (size_t)z * strideA; }
    if (strideB) { Bh += (size_t)z * strideB; Bl += (size_t)z * strideB; }
    if (strideC) { Ch += (size_t)z * strideC; Cl += (size_t)z * strideC; }

    const int tid  = threadIdx.x;
    const int lane = tid & 31;
    const int wid  = tid >> 5;
    const int bm = blockIdx.y * 256, bn = blockIdx.x * 128;

    int Mtot = M;
    if (MDYN) {
        Mtot = Mlim[0];
        if (bm >= Mtot) return;
    }

    const int nch = K / CHUNK;

    auto issue_stage = [&](int c) {
        const int k0 = c * CHUNK;
        const uint32_t st = sb + (c & 1) * STG_BYTES;
#pragma unroll
        for (int i = 0; i < 8; i++) {
            const int idx = tid + 256 * i;
            const int row = idx >> 3;
            const int seg = idx & 7;
            const uint32_t sw = sw128(row * 128 + seg * 16);
            int ar = bm + row;
            if (MDYN && ar >= Mtot) ar = Mtot - 1;
            const __nv_bfloat16 *pah, *pal;
            if (AMODE == 2 && k0 >= K1) {
                const size_t off = (size_t)ar * lda2 + (k0 - K1) + seg * 8;
                pah = A2h + off; pal = A2l + off;
            } else {
                const size_t off = (size_t)ar * lda + k0 + seg * 8;
                pah = Ah + off; pal = Al + off;
            }
            CP_ASYNC16(st + OFF_AH + sw, pah);
            CP_ASYNC16(st + OFF_AL + sw, pal);
        }
#pragma unroll
        for (int i = 0; i < 4; i++) {
            const int idx = tid + 256 * i;
            const int row = idx >> 3;
            const int seg = idx & 7;
            const uint32_t sw = sw128(row * 128 + seg * 16);
            const __nv_bfloat16 *pbh, *pbl;
            if (BMODE == 2 && k0 >= K1) {
                const size_t off = (size_t)(bn + row) * ldb2 + (k0 - K1) + seg * 8;
                pbh = B2h + off; pbl = B2l + off;
            } else {
                const size_t off = (size_t)(bn + row) * ldb + k0 + seg * 8;
                pbh = Bh + off; pbl = Bl + off;
            }
            CP_ASYNC16(st + OFF_BH + sw, pbh);
            CP_ASYNC16(st + OFF_BL + sw, pbl);
        }
        CP_COMMIT();
    };

    issue_stage(0);

    const int wm = (wid >> 1) * 64;
    const int wn = (wid & 1) * 64;

    float acc[4][8][4];
#pragma unroll
    for (int i = 0; i < 4; i++)
#pragma unroll
        for (int j = 0; j < 8; j++)
#pragma unroll
            for (int t = 0; t < 4; t++) acc[i][j][t] = 0.f;

    const int a_row  = (lane & 15);
    const int a_kb   = (lane >> 4) * 16;
    const int b_row  = (lane & 7) + ((lane >> 4) << 3);
    const int b_kb   = ((lane >> 3) & 1) * 16;

    for (int c = 0; c < nch; c++) {
        CP_WAIT(0);
        __syncthreads();
        if (c + 1 < nch) issue_stage(c + 1);

        const uint32_t st = sb + (c & 1) * STG_BYTES;

#pragma unroll
        for (int ks = 0; ks < 4; ks++) {
            const int kb = ks * 32;
            uint32_t ah[4][4], al[4][4];
#pragma unroll
            for (int i = 0; i < 4; i++) {
                const uint32_t oa = sw128((wm + i * 16 + a_row) * 128 + kb + a_kb);
                LDSM4(ah[i], st + OFF_AH + oa);
                LDSM4(al[i], st + OFF_AL + oa);
            }
            uint32_t bf[4][4];
#pragma unroll
            for (int j2 = 0; j2 < 4; j2++) {
                const uint32_t ob = sw128((wn + j2 * 16 + b_row) * 128 + kb + b_kb);
                LDSM4(bf[j2], st + OFF_BH + ob);
            }
#pragma unroll
            for (int i = 0; i < 4; i++)
#pragma unroll
                for (int j2 = 0; j2 < 4; j2++) {
                    mma16816(acc[i][2 * j2 + 0], ah[i], bf[j2][0], bf[j2][1]);
                    mma16816(acc[i][2 * j2 + 1], ah[i], bf[j2][2], bf[j2][3]);
                    mma16816(acc[i][2 * j2 + 0], al[i], bf[j2][0], bf[j2][1]);
                    mma16816(acc[i][2 * j2 + 1], al[i], bf[j2][2], bf[j2][3]);
                }
#pragma unroll
            for (int j2 = 0; j2 < 4; j2++) {
                const uint32_t ob = sw128((wn + j2 * 16 + b_row) * 128 + kb + b_kb);
                LDSM4(bf[j2], st + OFF_BL + ob);
            }
#pragma unroll
            for (int i = 0; i < 4; i++)
#pragma unroll
                for (int j2 = 0; j2 < 4; j2++) {
                    mma16816(acc[i][2 * j2 + 0], ah[i], bf[j2][0], bf[j2][1]);
                    mma16816(acc[i][2 * j2 + 1], ah[i], bf[j2][2], bf[j2][3]);
                }
        }
    }

    // ---- epilogue ----
#pragma unroll
    for (int i = 0; i < 4; i++) {
        const int r0 = bm + wm + i * 16 + (lane >> 2);
        const int r1 = r0 + 8;
        const bool ok0 = !MDYN || (r0 < Mtot);
        const bool ok1 = !MDYN || (r1 < Mtot);
        const float rs0 = HASB2 ? (float)rowscale[r0] : 0.f;
        const float rs1 = HASB2 ? (float)rowscale[r1] : 0.f;
#pragma unroll
        for (int j = 0; j < 8; j++) {
            const int col = bn + wn + j * 8 + (lane & 3) * 2;
            float b00 = bias[col], b01 = bias[col + 1];
            float b10 = b00, b11 = b01;
            if (HASB2) {
                b00 += rs0 * bias2[col]; b01 += rs0 * bias2[col + 1];
                b10 += rs1 * bias2[col]; b11 += rs1 * bias2[col + 1];
            }
            float2 v0 = make_float2(acc[i][j][0] + b00, acc[i][j][1] + b01);
            float2 v1 = make_float2(acc[i][j][2] + b10, acc[i][j][3] + b11);
            if (RELU) {
                v0.x = fmaxf(v0.x, 0.f); v0.y = fmaxf(v0.y, 0.f);
                v1.x = fmaxf(v1.x, 0.f); v1.y = fmaxf(v1.y, 0.f);
            }
            if (WF32) {
                if (ok0) *reinterpret_cast<float2*>(C + (size_t)r0 * N + col) = v0;
                if (ok1) *reinterpret_cast<float2*>(C + (size_t)r1 * N + col) = v1;
            }
            if (WSPLIT) {
                uint32_t p, q;
                if (ok0) {
                    split2(v0.x, v0.y, p, q);
                    reinterpret_cast<uint32_t*>(Ch)[((size_t)r0 * N + col) >> 1] = p;
                    reinterpret_cast<uint32_t*>(Cl)[((size_t)r0 * N + col) >> 1] = q;
                }
                if (ok1) {
                    split2(v1.x, v1.y, p, q);
                    reinterpret_cast<uint32_t*>(Ch)[((size_t)r1 * N + col) >> 1] = p;
                    reinterpret_cast<uint32_t*>(Cl)[((size_t)r1 * N + col) >> 1] = q;
                }
            }
        }
    }
}

// ---------------- name attention on compacted qkv, q-summed ----------------
__global__ __launch_bounds__(192) void name_attn_kernel(
    const float* __restrict__ qkv, const int* __restrict__ off,
    __nv_bfloat16* __restrict__ attn_h, __nv_bfloat16* __restrict__ attn_l)
{
    __shared__ float Qs[LS][DHN];
    __shared__ float Ks[LS][DHN];
    __shared__ float Vs[LS][DHN];
    __shared__ float sc[LS][LS + 1];

    const int h = blockIdx.x;
    const int b = blockIdx.y;
    const int d = threadIdx.x;

    const int o   = off[b];
    const int len = off[b + 1] - o;

    const float* base = qkv + (size_t)o * (3 * DE) + h * DHN + d;
    for (int s = 0; s < len; s++) {
        Qs[s][d] = base[s * (3 * DE)];
        Ks[s][d] = base[s * (3 * DE) + DE];
        Vs[s][d] = base[s * (3 * DE) + 2 * DE];
    }
    __syncthreads();

    const int warp = d >> 5, lane = d & 31;
    const float scale = 1.0f / sqrtf((float)DHN);
    const int np = len * len;
    for (int p = warp; p < np; p += 6) {
        const int q = p / len, j = p - q * len;
        float s = 0.f;
#pragma unroll
        for (int i = 0; i < 6; i++) s += Qs[q][lane + 32 * i] * Ks[j][lane + 32 * i];
#pragma unroll
        for (int ofs = 16; ofs; ofs >>= 1) s += __shfl_down_sync(0xffffffffu, s, ofs);
        if (lane == 0) sc[q][j] = s * scale;
    }
    __syncthreads();

    if (d < len) {
        float mx = -1e30f;
        for (int j = 0; j < len; j++) mx = fmaxf(mx, sc[d][j]);
        float sum = 0.f;
        float row[LS];
        for (int j = 0; j < len; j++) { row[j] = expf(sc[d][j] - mx); sum += row[j]; }
        const float inv = 1.f / sum;
        for (int j = 0; j < len; j++) sc[d][j] = row[j] * inv;
    }
    __syncthreads();

    float accum = 0.f;
    for (int s = 0; s < len; s++) {
        float ov = 0.f;
        for (int j = 0; j < len; j++) ov += sc[s][j] * Vs[j][d];
        accum += ov;
    }
    const float a1 = __shfl_down_sync(0xffffffffu, accum, 1);
    if (!(d & 1)) {
        uint32_t p, q;
        split2(accum, a1, p, q);
        const size_t id2 = ((size_t)b * DE + h * DHN + d) >> 1;
        reinterpret_cast<uint32_t*>(attn_h)[id2] = p;
        reinterpret_cast<uint32_t*>(attn_l)[id2] = q;
    }
}

// ---------------- residual + LayerNorm + bf16 split output ----------------
__device__ __forceinline__ float block_reduce_sum(float v) {
    __shared__ float red[8];
    const int lane = threadIdx.x & 31, warp = threadIdx.x >> 5;
#pragma unroll
    for (int o = 16; o; o >>= 1) v += __shfl_down_sync(0xffffffffu, v, o);
    if (lane == 0) red[warp] = v;
    __syncthreads();
    v = (threadIdx.x < 8) ? red[threadIdx.x] : 0.f;
    if (warp == 0)
#pragma unroll
        for (int o = 4; o; o >>= 1) v += __shfl_down_sync(0xffffffffu, v, o);
    return v;
}

__global__ __launch_bounds__(256) void resid_ln_kernel(
    float* __restrict__ h, const float* __restrict__ a,
    const float* __restrict__ g, const float* __restrict__ b,
    __nv_bfloat16* __restrict__ hh, __nv_bfloat16* __restrict__ hl)
{
    const int row = blockIdx.x;
    const int t = threadIdx.x;
    float v[4];
    float s = 0.f;
#pragma unroll
    for (int i = 0; i < 4; i++) {
        const int c = t + 256 * i;
        v[i] = h[(size_t)row * HD + c] + a[(size_t)row * HD + c];
        s += v[i];
    }
    s = block_reduce_sum(s);
    __shared__ float mean_s, rstd_s;
    if (t == 0) mean_s = s * (1.f / HD);
    __syncthreads();
    const float m = mean_s;
    float s2 = 0.f;
#pragma unroll
    for (int i = 0; i < 4; i++) { const float dd = v[i] - m; s2 += dd * dd; }
    s2 = block_reduce_sum(s2);
    if (t == 0) rstd_s = rsqrtf(s2 * (1.f / HD) + 1e-5f);
    __syncthreads();
    const float r = rstd_s;
#pragma unroll
    for (int i = 0; i < 4; i++) {
        const int c = t + 256 * i;
        const float y = (v[i] - m) * r * g[c] + b[c];
        h[(size_t)row * HD + c] = y;
        const float y1 = __shfl_down_sync(0xffffffffu, y, 1);
        if (!(t & 1)) {
            uint32_t p, q;
            split2(y, y1, p, q);
            const size_t id2 = ((size_t)row * HD + c) >> 1;
            reinterpret_cast<uint32_t*>(hh)[id2] = p;
            reinterpret_cast<uint32_t*>(hl)[id2] = q;
        }
    }
}

// ---------------- classifier head ----------------
__global__ __launch_bounds__(512) void cls_kernel(
    const float* __restrict__ h, const float* __restrict__ w,
    const float* __restrict__ b, float* __restrict__ out)
{
    const int m = blockIdx.x;
    const int c = threadIdx.x >> 5;
    const int lane = threadIdx.x & 31;
    const float* hr = h + (size_t)m * HD;
    const float* wr = w + (size_t)c * HD;
    float s = 0.f;
#pragma unroll
    for (int i = lane; i < HD; i += 32) s += hr[i] * wr[i];
#pragma unroll
    for (int o = 16; o; o >>= 1) s += __shfl_down_sync(0xffffffffu, s, o);
    if (lane == 0) out[(size_t)m * NCLS + c] = s + b[c];
}

// ---------------- orchestration ----------------
static inline void launch_split_s(cudaStream_t st, const float* src,
                                  __nv_bfloat16* hi, __nv_bfloat16* lo, size_t n) {
    const int n2 = (int)(n / 2);
    split_kernel<<<(n2 + 255) / 256, 256, 0, st>>>(src, hi, lo, n2);
}

extern "C" void kernel_launch(void* const* d_in, const int* in_sizes, int n_in,
                              void* d_out, int out_size)
{
    const int*   name_tokens = (const int*)d_in[0];
    const int*   name_lens   = (const int*)d_in[1];
    const float* x_feats     = (const float*)d_in[2];
    const float* wte         = (const float*)d_in[3];
    const float* mha_in_w    = (const float*)d_in[4];
    const float* mha_in_b    = (const float*)d_in[5];
    const float* mha_out_w   = (const float*)d_in[6];
    const float* mha_out_b   = (const float*)d_in[7];
    const float* bott_w      = (const float*)d_in[8];
    const float* bott_b      = (const float*)d_in[9];
    const float* enc_in_w    = (const float*)d_in[10];
    const float* enc_in_b    = (const float*)d_in[11];
    const float* enc_out_w   = (const float*)d_in[12];
    const float* enc_out_b   = (const float*)d_in[13];
    const float* enc_ln1_g   = (const float*)d_in[14];
    const float* enc_ln1_b   = (const float*)d_in[15];
    const float* enc_ln2_g   = (const float*)d_in[16];
    const float* enc_ln2_b   = (const float*)d_in[17];
    const float* enc_ff1_w   = (const float*)d_in[18];
    const float* enc_ff1_b   = (const float*)d_in[19];
    const float* enc_ff2_w   = (const float*)d_in[20];
    const float* enc_ff2_b   = (const float*)d_in[21];
    const float* cls_w       = (const float*)d_in[22];
    const float* cls_b       = (const float*)d_in[23];
    float* out = (float*)d_out;

    float *qkv, *h, *ta, *zero, *bc, *bao;
    int *off, *total, *rowtok;
    cudaGetSymbolAddress((void**)&qkv,    g_qkv);
    cudaGetSymbolAddress((void**)&h,      g_h);
    cudaGetSymbolAddress((void**)&ta,     g_ta);
    cudaGetSymbolAddress((void**)&zero,   g_zero);
    cudaGetSymbolAddress((void**)&bc,     g_bc);
    cudaGetSymbolAddress((void**)&bao,    g_bao);
    cudaGetSymbolAddress((void**)&off,    g_off);
    cudaGetSymbolAddress((void**)&total,  g_total);
    cudaGetSymbolAddress((void**)&rowtok, g_rowtok);

    __nv_bfloat16 *gah, *gal, *attn_h, *attn_l, *xf_h, *xf_l, *hh, *hl, *t1_h, *t1_l;
    __nv_bfloat16 *wqkv_h, *wqkv_l, *wbott_h, *wbott_l, *wo_h, *wo_l, *wf1_h, *wf1_l, *wf2_h, *wf2_l;
    __nv_bfloat16 *wvt_h, *wvt_l, *woutt_h, *woutt_l, *wc_h, *wc_l, *wao_h, *wao_l;
    cudaGetSymbolAddress((void**)&gah,    g_gah);     cudaGetSymbolAddress((void**)&gal,    g_gal);
    cudaGetSymbolAddress((void**)&attn_h, g_attn_h);  cudaGetSymbolAddress((void**)&attn_l, g_attn_l);
    cudaGetSymbolAddress((void**)&xf_h,   g_xf_h);    cudaGetSymbolAddress((void**)&xf_l,   g_xf_l);
    cudaGetSymbolAddress((void**)&hh,     g_hh);      cudaGetSymbolAddress((void**)&hl,     g_hl);
    cudaGetSymbolAddress((void**)&t1_h,   g_t1_h);    cudaGetSymbolAddress((void**)&t1_l,   g_t1_l);
    cudaGetSymbolAddress((void**)&wqkv_h, g_wqkv_h);  cudaGetSymbolAddress((void**)&wqkv_l, g_wqkv_l);
    cudaGetSymbolAddress((void**)&wbott_h,g_wbott_h); cudaGetSymbolAddress((void**)&wbott_l,g_wbott_l);
    cudaGetSymbolAddress((void**)&wo_h,   g_wo_h);    cudaGetSymbolAddress((void**)&wo_l,   g_wo_l);
    cudaGetSymbolAddress((void**)&wf1_h,  g_wf1_h);   cudaGetSymbolAddress((void**)&wf1_l,  g_wf1_l);
    cudaGetSymbolAddress((void**)&wf2_h,  g_wf2_h);   cudaGetSymbolAddress((void**)&wf2_l,  g_wf2_l);
    cudaGetSymbolAddress((void**)&wvt_h,  g_wvt_h);   cudaGetSymbolAddress((void**)&wvt_l,  g_wvt_l);
    cudaGetSymbolAddress((void**)&woutt_h,g_woutt_h); cudaGetSymbolAddress((void**)&woutt_l,g_woutt_l);
    cudaGetSymbolAddress((void**)&wc_h,   g_wc_h);    cudaGetSymbolAddress((void**)&wc_l,   g_wc_l);
    cudaGetSymbolAddress((void**)&wao_h,  g_wao_h);   cudaGetSymbolAddress((void**)&wao_l,  g_wao_l);

    auto k_qkv   = tgemm_kernel<0, 0, false, true,  false, true,  false>;
    auto k_bott  = tgemm_kernel<2, 2, false, true,  true,  false, true >;
    auto k_plain = tgemm_kernel<0, 0, false, true,  false, false, false>;
    auto k_ff1   = tgemm_kernel<0, 0, true,  false, true,  false, false>;
    auto k_pre   = tgemm_kernel<0, 0, false, false, true,  false, false>;
    cudaFuncSetAttribute(k_qkv,   cudaFuncAttributeMaxDynamicSharedMemorySize, TG_SMEM);
    cudaFuncSetAttribute(k_bott,  cudaFuncAttributeMaxDynamicSharedMemorySize, TG_SMEM);
    cudaFuncSetAttribute(k_plain, cudaFuncAttributeMaxDynamicSharedMemorySize, TG_SMEM);
    cudaFuncSetAttribute(k_ff1,   cudaFuncAttributeMaxDynamicSharedMemorySize, TG_SMEM);
    cudaFuncSetAttribute(k_pre,   cudaFuncAttributeMaxDynamicSharedMemorySize, TG_SMEM);

    // side stream + fork/join events (created per call; host-side only, no device mem)
    cudaStream_t side = 0;
    cudaEvent_t evFork = 0, evJoin = 0;
    bool use_side = (cudaStreamCreateWithFlags(&side, cudaStreamNonBlocking) == cudaSuccess)
                 && (cudaEventCreateWithFlags(&evFork, cudaEventDisableTiming) == cudaSuccess)
                 && (cudaEventCreateWithFlags(&evJoin, cudaEventDisableTiming) == cudaSuccess);
    cudaStream_t prepSt = use_side ? side : (cudaStream_t)0;

    // ---- main-path prep (needed by qkv / bott) ----
    scan_kernel<<<1, 1024>>>(name_lens, off, total);
    fill_rows_kernel<<<NS, 32>>>(name_lens, off, name_tokens, rowtok);
    gather_split_kernel<<<NS * LS, 128>>>(wte, rowtok, total, gah, gal);
    launch_split_s(0, mha_in_w, wqkv_h, wqkv_l, (size_t)3 * DE * DE);
    launch_split_s(0, bott_w,   wbott_h, wbott_l, (size_t)HD * (XFD + DE));
    launch_split_s(0, x_feats,  xf_h, xf_l, (size_t)NS * XFD);
    transpose_split_kernel<<<dim3(DE / 32, DE / 32, 1), dim3(32, 8)>>>(
        mha_out_w, DE, DE, woutt_h, woutt_l, 0, 0);
    bias_fold_kernel<<<dim3(HD, 1), 128>>>(
        bott_w, XFD + DE, XFD, mha_out_b, nullptr, bao, DE, 0, 0, 0, 0);

    // ---- fork: encoder-weight prep on side stream, overlapped with qkv chain ----
    if (use_side) {
        cudaEventRecord(evFork, 0);
        cudaStreamWaitEvent(side, evFork, 0);
    }
    launch_split_s(prepSt, enc_out_w, wo_h,  wo_l,  (size_t)NLAY * HD * HD);
    launch_split_s(prepSt, enc_ff1_w, wf1_h, wf1_l, (size_t)NLAY * 2 * HD * HD);
    launch_split_s(prepSt, enc_ff2_w, wf2_h, wf2_l, (size_t)NLAY * HD * 2 * HD);
    transpose_split_kernel<<<dim3(HD / 32, HD / 32, NLAY), dim3(32, 8), 0, prepSt>>>(
        enc_in_w + (size_t)2 * HD * HD, HD, HD, wvt_h, wvt_l,
        (size_t)3 * HD * HD, (size_t)HD * HD);
    bias_fold_kernel<<<dim3(HD, NLAY), 128, 0, prepSt>>>(
        enc_out_w, HD, 0, enc_in_b + 2 * HD, enc_out_b, bc, HD,
        (size_t)HD * HD, (size_t)3 * HD, (size_t)HD, (size_t)HD);
    k_pre<<<dim3(HD / 128, HD / 256, NLAY), 256, TG_SMEM, prepSt>>>(
        HD, HD, HD, 0,
        wo_h, wo_l, HD, nullptr, nullptr, 0, nullptr,
        wvt_h, wvt_l, HD, nullptr, nullptr, 0,
        zero, nullptr, nullptr,
        nullptr, wc_h, wc_l,
        (size_t)HD * HD, (size_t)HD * HD, (size_t)HD * HD);
    k_pre<<<dim3(DE / 128, HD / 256, 1), 256, TG_SMEM, prepSt>>>(
        HD, DE, DE, 0,
        wbott_h + XFD, wbott_l + XFD, XFD + DE, nullptr, nullptr, 0, nullptr,
        woutt_h, woutt_l, DE, nullptr, nullptr, 0,
        zero, nullptr, nullptr,
        nullptr, wao_h, wao_l, 0, 0, 0);
    if (use_side) cudaEventRecord(evJoin, side);

    const int MQ = NS * LS;
    const int KQ = DE;
    const int NQ = 3 * DE;

    // 1. qkv(compact) = gathered_emb @ mha_in_w^T + mha_in_b   (overlaps side prep)
    k_qkv<<<dim3(NQ / 128, MQ / 256, 1), 256, TG_SMEM>>>(
        MQ, NQ, KQ, 0,
        gah, gal, KQ, nullptr, nullptr, 0, total,
        wqkv_h, wqkv_l, KQ, nullptr, nullptr, 0,
        mha_in_b, nullptr, nullptr, qkv, nullptr, nullptr, 0, 0, 0);

    // 2. name attention on compact rows -> attnsum split
    name_attn_kernel<<<dim3(NHN, NS), 192>>>(qkv, off, attn_h, attn_l);

    // ---- join: everything after needs the folded encoder weights ----
    if (use_side) cudaStreamWaitEvent(0, evJoin, 0);

    // 3. x = xf@Wb1^T + attnsum@Wao^T + bbott + len*bao -> h fp32 + split
    k_bott<<<dim3(HD / 128, NS / 256, 1), 256, TG_SMEM>>>(
        NS, HD, XFD + DE, XFD,
        xf_h, xf_l, XFD, attn_h, attn_l, DE, nullptr,
        wbott_h, wbott_l, XFD + DE, wao_h, wao_l, DE,
        bott_b, bao, name_lens, h, hh, hl, 0, 0, 0);

    // 4. encoder layers
    for (int l = 0; l < NLAY; l++) {
        k_plain<<<dim3(HD / 128, NS / 256, 1), 256, TG_SMEM>>>(
            NS, HD, HD, 0,
            hh, hl, HD, nullptr, nullptr, 0, nullptr,
            wc_h + (size_t)l * HD * HD, wc_l + (size_t)l * HD * HD, HD,
            nullptr, nullptr, 0,
            bc + (size_t)l * HD, nullptr, nullptr, ta, nullptr, nullptr, 0, 0, 0);
        resid_ln_kernel<<<NS, 256>>>(h, ta, enc_ln1_g + (size_t)l * HD, enc_ln1_b + (size_t)l * HD, hh, hl);

        k_ff1<<<dim3(2 * HD / 128, NS / 256, 1), 256, TG_SMEM>>>(
            NS, 2 * HD, HD, 0,
            hh, hl, HD, nullptr, nullptr, 0, nullptr,
            wf1_h + (size_t)l * 2 * HD * HD, wf1_l + (size_t)l * 2 * HD * HD, HD,
            nullptr, nullptr, 0,
            enc_ff1_b + (size_t)l * 2 * HD, nullptr, nullptr, nullptr, t1_h, t1_l, 0, 0, 0);
        k_plain<<<dim3(HD / 128, NS / 256, 1), 256, TG_SMEM>>>(
            NS, HD, 2 * HD, 0,
            t1_h, t1_l, 2 * HD, nullptr, nullptr, 0, nullptr,
            wf2_h + (size_t)l * HD * 2 * HD, wf2_l + (size_t)l * HD * 2 * HD, 2 * HD,
            nullptr, nullptr, 0,
            enc_ff2_b + (size_t)l * HD, nullptr, nullptr, ta, nullptr, nullptr, 0, 0, 0);
        resid_ln_kernel<<<NS, 256>>>(h, ta, enc_ln2_g + (size_t)l * HD, enc_ln2_b + (size_t)l * HD, hh, hl);
    }

    // 5. classifier head
    cls_kernel<<<NS, 512>>>(h, cls_w, cls_b, out);
}

// round 10
// speedup vs baseline: 5.0001x; 1.1051x over previous
#include <cuda_runtime.h>
#include <cuda_bf16.h>
#include <cstdint>
#include <math.h>

// ---------------- problem constants ----------------
#define NS    4096          // N samples
#define LS    16            // L tokens
#define DE    768           // D embedding
#define NHN   4             // heads (name attn)
#define DHN   192           // head dim (name attn)
#define HD    1024          // H
#define NLAY  4             // NL
#define NCLS  16            // C
#define XFD   256           // XF

// ---------------- scratch (device globals; no cudaMalloc allowed) ----------------
__device__ float g_qkv[(size_t)NS * LS * 2 * DE];   // compacted Q,K rows, fp32
__device__ float g_h[(size_t)NS * HD];              // fp32 residual stream
__device__ float g_ta[(size_t)NS * HD];             // fp32 (LN input)

__device__ int g_off[NS + 1];
__device__ int g_total[1];
__device__ int g_rowtok[NS * LS];

__device__ float g_zero[4096];
__device__ float g_bc[NLAY * HD];
__device__ float g_bao[HD];

// bf16 hi/lo split buffers (activations)
__device__ __align__(16) __nv_bfloat16 g_gah[(size_t)NS * LS * DE],   g_gal[(size_t)NS * LS * DE];
__device__ __align__(16) __nv_bfloat16 g_ce_h[(size_t)NS * NHN * DE], g_ce_l[(size_t)NS * NHN * DE];
__device__ __align__(16) __nv_bfloat16 g_attn_h[(size_t)NS * DE],     g_attn_l[(size_t)NS * DE];
__device__ __align__(16) __nv_bfloat16 g_xf_h[(size_t)NS * XFD],      g_xf_l[(size_t)NS * XFD];
__device__ __align__(16) __nv_bfloat16 g_hh[(size_t)NS * HD],         g_hl[(size_t)NS * HD];
__device__ __align__(16) __nv_bfloat16 g_t1_h[(size_t)NS * 2 * HD],   g_t1_l[(size_t)NS * 2 * HD];

// bf16 hi/lo split buffers (weights)
__device__ __align__(16) __nv_bfloat16 g_wqkv_h[(size_t)3 * DE * DE], g_wqkv_l[(size_t)3 * DE * DE];
__device__ __align__(16) __nv_bfloat16 g_wbott_h[(size_t)HD * (XFD + DE)], g_wbott_l[(size_t)HD * (XFD + DE)];
__device__ __align__(16) __nv_bfloat16 g_wo_h[(size_t)NLAY * HD * HD],  g_wo_l[(size_t)NLAY * HD * HD];
__device__ __align__(16) __nv_bfloat16 g_wf1_h[(size_t)NLAY * 2 * HD * HD], g_wf1_l[(size_t)NLAY * 2 * HD * HD];
__device__ __align__(16) __nv_bfloat16 g_wf2_h[(size_t)NLAY * HD * 2 * HD], g_wf2_l[(size_t)NLAY * HD * 2 * HD];
__device__ __align__(16) __nv_bfloat16 g_wvt_h[(size_t)NLAY * HD * HD],  g_wvt_l[(size_t)NLAY * HD * HD];
__device__ __align__(16) __nv_bfloat16 g_woutt_h[(size_t)DE * DE],       g_woutt_l[(size_t)DE * DE];
__device__ __align__(16) __nv_bfloat16 g_wc_h[(size_t)NLAY * HD * HD],   g_wc_l[(size_t)NLAY * HD * HD];
__device__ __align__(16) __nv_bfloat16 g_wao_h[(size_t)HD * DE],         g_wao_l[(size_t)HD * DE];

// ================= helpers =================
__device__ __forceinline__ uint32_t smem_u32(const void* p) {
    uint32_t a;
    asm("{ .reg .u64 t; cvta.to.shared.u64 t, %1; cvt.u32.u64 %0, t; }" : "=r"(a) : "l"(p));
    return a;
}
__device__ __forceinline__ uint32_t sw128(uint32_t o) { return o ^ ((o >> 3) & 0x70); }

#define LDSM4(r, addr) \
    asm volatile("ldmatrix.sync.aligned.m8n8.x4.shared.b16 {%0,%1,%2,%3}, [%4];" \
        : "=r"((r)[0]), "=r"((r)[1]), "=r"((r)[2]), "=r"((r)[3]) : "r"(addr))

__device__ __forceinline__ void mma16816(float* c, const uint32_t* a, uint32_t b0, uint32_t b1) {
    asm volatile("mma.sync.aligned.m16n8k16.row.col.f32.bf16.bf16.f32 "
        "{%0,%1,%2,%3},{%4,%5,%6,%7},{%8,%9},{%0,%1,%2,%3};"
        : "+f"(c[0]), "+f"(c[1]), "+f"(c[2]), "+f"(c[3])
        : "r"(a[0]), "r"(a[1]), "r"(a[2]), "r"(a[3]), "r"(b0), "r"(b1));
}

#define CP_ASYNC16(dst, src) \
    asm volatile("cp.async.cg.shared.global [%0], [%1], 16;" :: "r"(dst), "l"(src))
#define CP_COMMIT() asm volatile("cp.async.commit_group;" ::: "memory")
#define CP_WAIT(n)  asm volatile("cp.async.wait_group %0;" :: "n"(n) : "memory")

// split fp32 pair -> packed bf16 hi (p) and lo residual (q)
__device__ __forceinline__ void split2(float x, float y, uint32_t& p, uint32_t& q) {
    asm("cvt.rn.bf16x2.f32 %0, %1, %2;" : "=r"(p) : "f"(y), "f"(x));
    float h0 = __uint_as_float(p << 16);
    float h1 = __uint_as_float(p & 0xffff0000u);
    float r0 = x - h0, r1 = y - h1;
    asm("cvt.rn.bf16x2.f32 %0, %1, %2;" : "=r"(q) : "f"(r1), "f"(r0));
}

// ---------------- fp32 -> bf16 hi/lo split ----------------
__global__ __launch_bounds__(256) void split_kernel(
    const float* __restrict__ src,
    __nv_bfloat16* __restrict__ hi, __nv_bfloat16* __restrict__ lo, int n2)
{
    const int i = blockIdx.x * blockDim.x + threadIdx.x;
    if (i < n2) {
        const float2 v = reinterpret_cast<const float2*>(src)[i];
        uint32_t p, q;
        split2(v.x, v.y, p, q);
        reinterpret_cast<uint32_t*>(hi)[i] = p;
        reinterpret_cast<uint32_t*>(lo)[i] = q;
    }
}

// ---------------- batched fp32 [R x C] -> transposed bf16 hi/lo [C x R] ----------------
__global__ __launch_bounds__(256) void transpose_split_kernel(
    const float* __restrict__ src, int ld, int R,
    __nv_bfloat16* __restrict__ dh, __nv_bfloat16* __restrict__ dl,
    size_t srcStride, size_t dstStride)
{
    __shared__ float tile[32][33];
    const int z = blockIdx.z;
    src += (size_t)z * srcStride;
    dh  += (size_t)z * dstStride;
    dl  += (size_t)z * dstStride;
    const int c0 = blockIdx.x * 32, r0 = blockIdx.y * 32;
    const int tx = threadIdx.x, ty = threadIdx.y;   // (32, 8)
#pragma unroll
    for (int i = ty; i < 32; i += 8)
        tile[i][tx] = src[(size_t)(r0 + i) * ld + c0 + tx];
    __syncthreads();
    if (tx < 16) {
#pragma unroll
        for (int i = ty; i < 32; i += 8) {
            uint32_t p, q;
            split2(tile[2 * tx][i], tile[2 * tx + 1][i], p, q);
            const size_t id2 = ((size_t)(c0 + i) * R + r0) / 2 + tx;
            reinterpret_cast<uint32_t*>(dh)[id2] = p;
            reinterpret_cast<uint32_t*>(dl)[id2] = q;
        }
    }
}

// ---------------- batched bias fold: out[row] = W[row,:]·v + base[row] ----------------
__global__ __launch_bounds__(128) void bias_fold_kernel(
    const float* __restrict__ W, int ldw, int coff,
    const float* __restrict__ v, const float* __restrict__ base,
    float* __restrict__ out, int K,
    size_t wStride, size_t vStride, size_t baseStride, size_t outStride)
{
    __shared__ float red[4];
    const int z = blockIdx.y;
    W += (size_t)z * wStride;
    v += (size_t)z * vStride;
    if (base) base += (size_t)z * baseStride;
    out += (size_t)z * outStride;
    const int row = blockIdx.x;
    const int t = threadIdx.x, lane = t & 31, warp = t >> 5;
    const float* wr = W + (size_t)row * ldw + coff;
    float s = 0.f;
    for (int k = t; k < K; k += 128) s += wr[k] * v[k];
#pragma unroll
    for (int o = 16; o; o >>= 1) s += __shfl_down_sync(0xffffffffu, s, o);
    if (lane == 0) red[warp] = s;
    __syncthreads();
    if (t == 0) out[row] = red[0] + red[1] + red[2] + red[3] + (base ? base[row] : 0.f);
}

// ---------------- compaction scan ----------------
__global__ __launch_bounds__(1024) void scan_kernel(
    const int* __restrict__ lens, int* __restrict__ off, int* __restrict__ total)
{
    __shared__ int wsum[32];
    const int tid = threadIdx.x, lane = tid & 31, warp = tid >> 5;
    int v[4], s = 0;
#pragma unroll
    for (int i = 0; i < 4; i++) { v[i] = lens[tid * 4 + i]; s += v[i]; }
    int ws = s;
#pragma unroll
    for (int o = 1; o < 32; o <<= 1) { int t = __shfl_up_sync(0xffffffffu, ws, o); if (lane >= o) ws += t; }
    if (lane == 31) wsum[warp] = ws;
    __syncthreads();
    if (warp == 0) {
        int t = wsum[lane];
#pragma unroll
        for (int o = 1; o < 32; o <<= 1) { int u = __shfl_up_sync(0xffffffffu, t, o); if (lane >= o) t += u; }
        wsum[lane] = t;
    }
    __syncthreads();
    int run = ws - s + (warp ? wsum[warp - 1] : 0);
#pragma unroll
    for (int i = 0; i < 4; i++) { off[tid * 4 + i] = run; run += v[i]; }
    if (tid == 1023) { off[NS] = run; total[0] = run; }
}

__global__ __launch_bounds__(32) void fill_rows_kernel(
    const int* __restrict__ lens, const int* __restrict__ off,
    const int* __restrict__ toks, int* __restrict__ rowtok)
{
    const int b = blockIdx.x;
    const int len = lens[b], o = off[b];
    for (int s = threadIdx.x; s < len; s += 32) rowtok[o + s] = toks[b * LS + s];
}

__global__ __launch_bounds__(128) void gather_split_kernel(
    const float* __restrict__ wte, const int* __restrict__ rowtok,
    const int* __restrict__ total,
    __nv_bfloat16* __restrict__ Ah, __nv_bfloat16* __restrict__ Al)
{
    const int r = blockIdx.x;
    if (r >= total[0]) return;
    const float2* src = reinterpret_cast<const float2*>(wte + (size_t)rowtok[r] * DE);
    uint32_t* dh = reinterpret_cast<uint32_t*>(Ah) + (size_t)r * (DE / 2);
    uint32_t* dl = reinterpret_cast<uint32_t*>(Al) + (size_t)r * (DE / 2);
#pragma unroll
    for (int i = 0; i < 3; i++) {
        const int j = threadIdx.x + 128 * i;
        const float2 v = src[j];
        uint32_t p, q;
        split2(v.x, v.y, p, q);
        dh[j] = p; dl[j] = q;
    }
}

// ================= HMMA GEMM: C[M,N] = A[M,K] @ B[N,K]^T + bias (+rs*bias2) =================
// CTA tile 256x128, warp tile 64x64 (8 warps). STAGES=2, one sync/chunk.
// 3-term bf16: C = Ah*Bh + Ah*Bl + Al*Bh. blockIdx.z batching via strides.
// NDYN: N not tile-aligned — clamp B rows, predicate epilogue on col < Nlim.
#define CHUNK  64
#define STG_BYTES (96 * 1024)
#define OFF_AH 0
#define OFF_AL 32768
#define OFF_BH 65536
#define OFF_BL 81920
#define TG_SMEM  (2 * STG_BYTES + 256)

template<int AMODE, int BMODE, bool RELU, bool WF32, bool WSPLIT, bool MDYN, bool HASB2, bool NDYN>
__global__ __launch_bounds__(256, 1) void tgemm_kernel(
    int M, int N, int K, int K1,
    const __nv_bfloat16* __restrict__ Ah, const __nv_bfloat16* __restrict__ Al, int lda,
    const __nv_bfloat16* __restrict__ A2h, const __nv_bfloat16* __restrict__ A2l, int lda2,
    const int* __restrict__ Mlim,
    const __nv_bfloat16* __restrict__ Bh, const __nv_bfloat16* __restrict__ Bl, int ldb,
    const __nv_bfloat16* __restrict__ B2h, const __nv_bfloat16* __restrict__ B2l, int ldb2,
    const float* __restrict__ bias, const float* __restrict__ bias2,
    const int* __restrict__ rowscale,
    float* __restrict__ C,
    __nv_bfloat16* __restrict__ Ch, __nv_bfloat16* __restrict__ Cl,
    size_t strideA, size_t strideB, size_t strideC,
    int ldc, int Nlim, size_t strideB2)
{
    extern __shared__ char smem[];
    const uint32_t sb = smem_u32(smem);

    const int z = blockIdx.z;
    if (strideA) { Ah += (size_t)z * strideA; Al += (size_t)z * strideA; }
    if (strideB) { Bh += (size_t)z * strideB; Bl += (size_t)z * strideB; }
    if (strideC) { Ch += (size_t)z * strideC; Cl += (size_t)z * strideC; }
    if (HASB2 && strideB2) bias2 += (size_t)z * strideB2;

    const int tid  = threadIdx.x;
    const int lane = tid & 31;
    const int wid  = tid >> 5;
    const int bm = blockIdx.y * 256, bn = blockIdx.x * 128;

    int Mtot = M;
    if (MDYN) {
        Mtot = Mlim[0];
        if (bm >= Mtot) return;
    }

    const int nch = K / CHUNK;

    auto issue_stage = [&](int c) {
        const int k0 = c * CHUNK;
        const uint32_t st = sb + (c & 1) * STG_BYTES;
#pragma unroll
        for (int i = 0; i < 8; i++) {
            const int idx = tid + 256 * i;
            const int row = idx >> 3;
            const int seg = idx & 7;
            const uint32_t sw = sw128(row * 128 + seg * 16);
            int ar = bm + row;
            if (MDYN && ar >= Mtot) ar = Mtot - 1;
            const __nv_bfloat16 *pah, *pal;
            if (AMODE == 2 && k0 >= K1) {
                const size_t off = (size_t)ar * lda2 + (k0 - K1) + seg * 8;
                pah = A2h + off; pal = A2l + off;
            } else {
                const size_t off = (size_t)ar * lda + k0 + seg * 8;
                pah = Ah + off; pal = Al + off;
            }
            CP_ASYNC16(st + OFF_AH + sw, pah);
            CP_ASYNC16(st + OFF_AL + sw, pal);
        }
#pragma unroll
        for (int i = 0; i < 4; i++) {
            const int idx = tid + 256 * i;
            const int row = idx >> 3;
            const int seg = idx & 7;
            const uint32_t sw = sw128(row * 128 + seg * 16);
            int br = bn + row;
            if (NDYN && br >= Nlim) br = Nlim - 1;
            const __nv_bfloat16 *pbh, *pbl;
            if (BMODE == 2 && k0 >= K1) {
                const size_t off = (size_t)br * ldb2 + (k0 - K1) + seg * 8;
                pbh = B2h + off; pbl = B2l + off;
            } else {
                const size_t off = (size_t)br * ldb + k0 + seg * 8;
                pbh = Bh + off; pbl = Bl + off;
            }
            CP_ASYNC16(st + OFF_BH + sw, pbh);
            CP_ASYNC16(st + OFF_BL + sw, pbl);
        }
        CP_COMMIT();
    };

    issue_stage(0);

    const int wm = (wid >> 1) * 64;
    const int wn = (wid & 1) * 64;

    float acc[4][8][4];
#pragma unroll
    for (int i = 0; i < 4; i++)
#pragma unroll
        for (int j = 0; j < 8; j++)
#pragma unroll
            for (int t = 0; t < 4; t++) acc[i][j][t] = 0.f;

    const int a_row  = (lane & 15);
    const int a_kb   = (lane >> 4) * 16;
    const int b_row  = (lane & 7) + ((lane >> 4) << 3);
    const int b_kb   = ((lane >> 3) & 1) * 16;

    for (int c = 0; c < nch; c++) {
        CP_WAIT(0);
        __syncthreads();
        if (c + 1 < nch) issue_stage(c + 1);

        const uint32_t st = sb + (c & 1) * STG_BYTES;

#pragma unroll
        for (int ks = 0; ks < 4; ks++) {
            const int kb = ks * 32;
            uint32_t ah[4][4], al[4][4];
#pragma unroll
            for (int i = 0; i < 4; i++) {
                const uint32_t oa = sw128((wm + i * 16 + a_row) * 128 + kb + a_kb);
                LDSM4(ah[i], st + OFF_AH + oa);
                LDSM4(al[i], st + OFF_AL + oa);
            }
            uint32_t bf[4][4];
#pragma unroll
            for (int j2 = 0; j2 < 4; j2++) {
                const uint32_t ob = sw128((wn + j2 * 16 + b_row) * 128 + kb + b_kb);
                LDSM4(bf[j2], st + OFF_BH + ob);
            }
#pragma unroll
            for (int i = 0; i < 4; i++)
#pragma unroll
                for (int j2 = 0; j2 < 4; j2++) {
                    mma16816(acc[i][2 * j2 + 0], ah[i], bf[j2][0], bf[j2][1]);
                    mma16816(acc[i][2 * j2 + 1], ah[i], bf[j2][2], bf[j2][3]);
                    mma16816(acc[i][2 * j2 + 0], al[i], bf[j2][0], bf[j2][1]);
                    mma16816(acc[i][2 * j2 + 1], al[i], bf[j2][2], bf[j2][3]);
                }
#pragma unroll
            for (int j2 = 0; j2 < 4; j2++) {
                const uint32_t ob = sw128((wn + j2 * 16 + b_row) * 128 + kb + b_kb);
                LDSM4(bf[j2], st + OFF_BL + ob);
            }
#pragma unroll
            for (int i = 0; i < 4; i++)
#pragma unroll
                for (int j2 = 0; j2 < 4; j2++) {
                    mma16816(acc[i][2 * j2 + 0], ah[i], bf[j2][0], bf[j2][1]);
                    mma16816(acc[i][2 * j2 + 1], ah[i], bf[j2][2], bf[j2][3]);
                }
        }
    }

    // ---- epilogue ----
#pragma unroll
    for (int i = 0; i < 4; i++) {
        const int r0 = bm + wm + i * 16 + (lane >> 2);
        const int r1 = r0 + 8;
        const bool ok0 = !MDYN || (r0 < Mtot);
        const bool ok1 = !MDYN || (r1 < Mtot);
        const float rs0 = HASB2 ? (float)rowscale[r0] : 0.f;
        const float rs1 = HASB2 ? (float)rowscale[r1] : 0.f;
#pragma unroll
        for (int j = 0; j < 8; j++) {
            const int col = bn + wn + j * 8 + (lane & 3) * 2;
            const bool okc = !NDYN || (col < Nlim);
            float b00 = bias[col], b01 = bias[col + 1];
            float b10 = b00, b11 = b01;
            if (HASB2) {
                b00 += rs0 * bias2[col]; b01 += rs0 * bias2[col + 1];
                b10 += rs1 * bias2[col]; b11 += rs1 * bias2[col + 1];
            }
            float2 v0 = make_float2(acc[i][j][0] + b00, acc[i][j][1] + b01);
            float2 v1 = make_float2(acc[i][j][2] + b10, acc[i][j][3] + b11);
            if (RELU) {
                v0.x = fmaxf(v0.x, 0.f); v0.y = fmaxf(v0.y, 0.f);
                v1.x = fmaxf(v1.x, 0.f); v1.y = fmaxf(v1.y, 0.f);
            }
            if (WF32) {
                if (ok0 && okc) *reinterpret_cast<float2*>(C + (size_t)r0 * ldc + col) = v0;
                if (ok1 && okc) *reinterpret_cast<float2*>(C + (size_t)r1 * ldc + col) = v1;
            }
            if (WSPLIT) {
                uint32_t p, q;
                if (ok0 && okc) {
                    split2(v0.x, v0.y, p, q);
                    reinterpret_cast<uint32_t*>(Ch)[((size_t)r0 * ldc + col) >> 1] = p;
                    reinterpret_cast<uint32_t*>(Cl)[((size_t)r0 * ldc + col) >> 1] = q;
                }
                if (ok1 && okc) {
                    split2(v1.x, v1.y, p, q);
                    reinterpret_cast<uint32_t*>(Ch)[((size_t)r1 * ldc + col) >> 1] = p;
                    reinterpret_cast<uint32_t*>(Cl)[((size_t)r1 * ldc + col) >> 1] = q;
                }
            }
        }
    }
}

// ---------------- name attention: weights only, emits per-head mixed embeddings CE ----------------
// CE_h = sum_j (sum_{s<len} a_h[s,j]) * e_j   (e reconstructed as hi+lo)
__global__ __launch_bounds__(192) void name_attn_kernel(
    const float* __restrict__ qk, const int* __restrict__ off,
    const __nv_bfloat16* __restrict__ eh, const __nv_bfloat16* __restrict__ el,
    __nv_bfloat16* __restrict__ CEh, __nv_bfloat16* __restrict__ CEl)
{
    __shared__ float Qs[LS][DHN];
    __shared__ float Ks[LS][DHN];
    __shared__ float sc[LS][LS + 1];
    __shared__ float cw[LS];

    const int h = blockIdx.x;
    const int b = blockIdx.y;
    const int d = threadIdx.x;

    const int o   = off[b];
    const int len = off[b + 1] - o;

    const float* base = qk + (size_t)o * (2 * DE) + h * DHN + d;
    for (int s = 0; s < len; s++) {
        Qs[s][d] = base[s * (2 * DE)];
        Ks[s][d] = base[s * (2 * DE) + DE];
    }
    if (d < LS) cw[d] = 0.f;
    __syncthreads();

    const int warp = d >> 5, lane = d & 31;
    const float scale = 1.0f / sqrtf((float)DHN);
    const int np = len * len;
    for (int p = warp; p < np; p += 6) {
        const int q = p / len, j = p - q * len;
        float s = 0.f;
#pragma unroll
        for (int i = 0; i < 6; i++) s += Qs[q][lane + 32 * i] * Ks[j][lane + 32 * i];
#pragma unroll
        for (int ofs = 16; ofs; ofs >>= 1) s += __shfl_down_sync(0xffffffffu, s, ofs);
        if (lane == 0) sc[q][j] = s * scale;
    }
    __syncthreads();

    if (d < len) {
        float mx = -1e30f;
        for (int j = 0; j < len; j++) mx = fmaxf(mx, sc[d][j]);
        float sum = 0.f;
        float row[LS];
        for (int j = 0; j < len; j++) { row[j] = expf(sc[d][j] - mx); sum += row[j]; }
        const float inv = 1.f / sum;
        for (int j = 0; j < len; j++) sc[d][j] = row[j] * inv;
    }
    __syncthreads();

    // column weights c[j] = sum over valid q rows
    if (d < len) {
        float c = 0.f;
        for (int s = 0; s < len; s++) c += sc[s][d];
        cw[d] = c;
    }
    __syncthreads();

    // CE_h = sum_j cw[j] * e_j  (768 dims, processed as 384 pairs)
    const uint32_t* ehp = reinterpret_cast<const uint32_t*>(eh);
    const uint32_t* elp = reinterpret_cast<const uint32_t*>(el);
    for (int p = d; p < DE / 2; p += 192) {
        float ce0 = 0.f, ce1 = 0.f;
        for (int j = 0; j < len; j++) {
            const size_t idx = (size_t)(o + j) * (DE / 2) + p;
            const uint32_t uh = ehp[idx], ul = elp[idx];
            const float e0 = __uint_as_float(uh << 16) + __uint_as_float(ul << 16);
            const float e1 = __uint_as_float(uh & 0xffff0000u) + __uint_as_float(ul & 0xffff0000u);
            ce0 += cw[j] * e0;
            ce1 += cw[j] * e1;
        }
        uint32_t P, Q;
        split2(ce0, ce1, P, Q);
        const size_t id2 = (size_t)b * (NHN * DE / 2) + h * (DE / 2) + p;
        reinterpret_cast<uint32_t*>(CEh)[id2] = P;
        reinterpret_cast<uint32_t*>(CEl)[id2] = Q;
    }
}

// ---------------- residual + LayerNorm + bf16 split output ----------------
__device__ __forceinline__ float block_reduce_sum(float v) {
    __shared__ float red[8];
    const int lane = threadIdx.x & 31, warp = threadIdx.x >> 5;
#pragma unroll
    for (int o = 16; o; o >>= 1) v += __shfl_down_sync(0xffffffffu, v, o);
    if (lane == 0) red[warp] = v;
    __syncthreads();
    v = (threadIdx.x < 8) ? red[threadIdx.x] : 0.f;
    if (warp == 0)
#pragma unroll
        for (int o = 4; o; o >>= 1) v += __shfl_down_sync(0xffffffffu, v, o);
    return v;
}

__global__ __launch_bounds__(256) void resid_ln_kernel(
    float* __restrict__ h, const float* __restrict__ a,
    const float* __restrict__ g, const float* __restrict__ b,
    __nv_bfloat16* __restrict__ hh, __nv_bfloat16* __restrict__ hl)
{
    const int row = blockIdx.x;
    const int t = threadIdx.x;
    float v[4];
    float s = 0.f;
#pragma unroll
    for (int i = 0; i < 4; i++) {
        const int c = t + 256 * i;
        v[i] = h[(size_t)row * HD + c] + a[(size_t)row * HD + c];
        s += v[i];
    }
    s = block_reduce_sum(s);
    __shared__ float mean_s, rstd_s;
    if (t == 0) mean_s = s * (1.f / HD);
    __syncthreads();
    const float m = mean_s;
    float s2 = 0.f;
#pragma unroll
    for (int i = 0; i < 4; i++) { const float dd = v[i] - m; s2 += dd * dd; }
    s2 = block_reduce_sum(s2);
    if (t == 0) rstd_s = rsqrtf(s2 * (1.f / HD) + 1e-5f);
    __syncthreads();
    const float r = rstd_s;
#pragma unroll
    for (int i = 0; i < 4; i++) {
        const int c = t + 256 * i;
        const float y = (v[i] - m) * r * g[c] + b[c];
        h[(size_t)row * HD + c] = y;
        const float y1 = __shfl_down_sync(0xffffffffu, y, 1);
        if (!(t & 1)) {
            uint32_t p, q;
            split2(y, y1, p, q);
            const size_t id2 = ((size_t)row * HD + c) >> 1;
            reinterpret_cast<uint32_t*>(hh)[id2] = p;
            reinterpret_cast<uint32_t*>(hl)[id2] = q;
        }
    }
}

// ---------------- classifier head ----------------
__global__ __launch_bounds__(512) void cls_kernel(
    const float* __restrict__ h, const float* __restrict__ w,
    const float* __restrict__ b, float* __restrict__ out)
{
    const int m = blockIdx.x;
    const int c = threadIdx.x >> 5;
    const int lane = threadIdx.x & 31;
    const float* hr = h + (size_t)m * HD;
    const float* wr = w + (size_t)c * HD;
    float s = 0.f;
#pragma unroll
    for (int i = lane; i < HD; i += 32) s += hr[i] * wr[i];
#pragma unroll
    for (int o = 16; o; o >>= 1) s += __shfl_down_sync(0xffffffffu, s, o);
    if (lane == 0) out[(size_t)m * NCLS + c] = s + b[c];
}

// ---------------- orchestration ----------------
static inline void launch_split_s(cudaStream_t st, const float* src,
                                  __nv_bfloat16* hi, __nv_bfloat16* lo, size_t n) {
    const int n2 = (int)(n / 2);
    split_kernel<<<(n2 + 255) / 256, 256, 0, st>>>(src, hi, lo, n2);
}

extern "C" void kernel_launch(void* const* d_in, const int* in_sizes, int n_in,
                              void* d_out, int out_size)
{
    const int*   name_tokens = (const int*)d_in[0];
    const int*   name_lens   = (const int*)d_in[1];
    const float* x_feats     = (const float*)d_in[2];
    const float* wte         = (const float*)d_in[3];
    const float* mha_in_w    = (const float*)d_in[4];
    const float* mha_in_b    = (const float*)d_in[5];
    const float* mha_out_w   = (const float*)d_in[6];
    const float* mha_out_b   = (const float*)d_in[7];
    const float* bott_w      = (const float*)d_in[8];
    const float* bott_b      = (const float*)d_in[9];
    const float* enc_in_w    = (const float*)d_in[10];
    const float* enc_in_b    = (const float*)d_in[11];
    const float* enc_out_w   = (const float*)d_in[12];
    const float* enc_out_b   = (const float*)d_in[13];
    const float* enc_ln1_g   = (const float*)d_in[14];
    const float* enc_ln1_b   = (const float*)d_in[15];
    const float* enc_ln2_g   = (const float*)d_in[16];
    const float* enc_ln2_b   = (const float*)d_in[17];
    const float* enc_ff1_w   = (const float*)d_in[18];
    const float* enc_ff1_b   = (const float*)d_in[19];
    const float* enc_ff2_w   = (const float*)d_in[20];
    const float* enc_ff2_b   = (const float*)d_in[21];
    const float* cls_w       = (const float*)d_in[22];
    const float* cls_b       = (const float*)d_in[23];
    float* out = (float*)d_out;

    float *qkv, *h, *ta, *zero, *bc, *bao;
    int *off, *total, *rowtok;
    cudaGetSymbolAddress((void**)&qkv,    g_qkv);
    cudaGetSymbolAddress((void**)&h,      g_h);
    cudaGetSymbolAddress((void**)&ta,     g_ta);
    cudaGetSymbolAddress((void**)&zero,   g_zero);
    cudaGetSymbolAddress((void**)&bc,     g_bc);
    cudaGetSymbolAddress((void**)&bao,    g_bao);
    cudaGetSymbolAddress((void**)&off,    g_off);
    cudaGetSymbolAddress((void**)&total,  g_total);
    cudaGetSymbolAddress((void**)&rowtok, g_rowtok);

    __nv_bfloat16 *gah, *gal, *ce_h, *ce_l, *attn_h, *attn_l, *xf_h, *xf_l, *hh, *hl, *t1_h, *t1_l;
    __nv_bfloat16 *wqkv_h, *wqkv_l, *wbott_h, *wbott_l, *wo_h, *wo_l, *wf1_h, *wf1_l, *wf2_h, *wf2_l;
    __nv_bfloat16 *wvt_h, *wvt_l, *woutt_h, *woutt_l, *wc_h, *wc_l, *wao_h, *wao_l;
    cudaGetSymbolAddress((void**)&gah,    g_gah);     cudaGetSymbolAddress((void**)&gal,    g_gal);
    cudaGetSymbolAddress((void**)&ce_h,   g_ce_h);    cudaGetSymbolAddress((void**)&ce_l,   g_ce_l);
    cudaGetSymbolAddress((void**)&attn_h, g_attn_h);  cudaGetSymbolAddress((void**)&attn_l, g_attn_l);
    cudaGetSymbolAddress((void**)&xf_h,   g_xf_h);    cudaGetSymbolAddress((void**)&xf_l,   g_xf_l);
    cudaGetSymbolAddress((void**)&hh,     g_hh);      cudaGetSymbolAddress((void**)&hl,     g_hl);
    cudaGetSymbolAddress((void**)&t1_h,   g_t1_h);    cudaGetSymbolAddress((void**)&t1_l,   g_t1_l);
    cudaGetSymbolAddress((void**)&wqkv_h, g_wqkv_h);  cudaGetSymbolAddress((void**)&wqkv_l, g_wqkv_l);
    cudaGetSymbolAddress((void**)&wbott_h,g_wbott_h); cudaGetSymbolAddress((void**)&wbott_l,g_wbott_l);
    cudaGetSymbolAddress((void**)&wo_h,   g_wo_h);    cudaGetSymbolAddress((void**)&wo_l,   g_wo_l);
    cudaGetSymbolAddress((void**)&wf1_h,  g_wf1_h);   cudaGetSymbolAddress((void**)&wf1_l,  g_wf1_l);
    cudaGetSymbolAddress((void**)&wf2_h,  g_wf2_h);   cudaGetSymbolAddress((void**)&wf2_l,  g_wf2_l);
    cudaGetSymbolAddress((void**)&wvt_h,  g_wvt_h);   cudaGetSymbolAddress((void**)&wvt_l,  g_wvt_l);
    cudaGetSymbolAddress((void**)&woutt_h,g_woutt_h); cudaGetSymbolAddress((void**)&woutt_l,g_woutt_l);
    cudaGetSymbolAddress((void**)&wc_h,   g_wc_h);    cudaGetSymbolAddress((void**)&wc_l,   g_wc_l);
    cudaGetSymbolAddress((void**)&wao_h,  g_wao_h);   cudaGetSymbolAddress((void**)&wao_l,  g_wao_l);

    auto k_qk    = tgemm_kernel<0, 0, false, true,  false, true,  false, false>;
    auto k_csum  = tgemm_kernel<0, 0, false, false, true,  false, true,  true >;
    auto k_bott  = tgemm_kernel<2, 2, false, true,  true,  false, true,  false>;
    auto k_plain = tgemm_kernel<0, 0, false, true,  false, false, false, false>;
    auto k_ff1   = tgemm_kernel<0, 0, true,  false, true,  false, false, false>;
    auto k_pre   = tgemm_kernel<0, 0, false, false, true,  false, false, false>;
    cudaFuncSetAttribute(k_qk,    cudaFuncAttributeMaxDynamicSharedMemorySize, TG_SMEM);
    cudaFuncSetAttribute(k_csum,  cudaFuncAttributeMaxDynamicSharedMemorySize, TG_SMEM);
    cudaFuncSetAttribute(k_bott,  cudaFuncAttributeMaxDynamicSharedMemorySize, TG_SMEM);
    cudaFuncSetAttribute(k_plain, cudaFuncAttributeMaxDynamicSharedMemorySize, TG_SMEM);
    cudaFuncSetAttribute(k_ff1,   cudaFuncAttributeMaxDynamicSharedMemorySize, TG_SMEM);
    cudaFuncSetAttribute(k_pre,   cudaFuncAttributeMaxDynamicSharedMemorySize, TG_SMEM);

    cudaStream_t side = 0;
    cudaEvent_t evFork = 0, evJoin = 0;
    bool use_side = (cudaStreamCreateWithFlags(&side, cudaStreamNonBlocking) == cudaSuccess)
                 && (cudaEventCreateWithFlags(&evFork, cudaEventDisableTiming) == cudaSuccess)
                 && (cudaEventCreateWithFlags(&evJoin, cudaEventDisableTiming) == cudaSuccess);
    cudaStream_t prepSt = use_side ? side : (cudaStream_t)0;

    // ---- main-path prep ----
    scan_kernel<<<1, 1024>>>(name_lens, off, total);
    fill_rows_kernel<<<NS, 32>>>(name_lens, off, name_tokens, rowtok);
    gather_split_kernel<<<NS * LS, 128>>>(wte, rowtok, total, gah, gal);
    launch_split_s(0, mha_in_w, wqkv_h, wqkv_l, (size_t)3 * DE * DE);
    launch_split_s(0, bott_w,   wbott_h, wbott_l, (size_t)HD * (XFD + DE));
    launch_split_s(0, x_feats,  xf_h, xf_l, (size_t)NS * XFD);
    transpose_split_kernel<<<dim3(DE / 32, DE / 32, 1), dim3(32, 8)>>>(
        mha_out_w, DE, DE, woutt_h, woutt_l, 0, 0);
    bias_fold_kernel<<<dim3(HD, 1), 128>>>(
        bott_w, XFD + DE, XFD, mha_out_b, nullptr, bao, DE, 0, 0, 0, 0);

    // ---- fork: encoder-weight prep on side stream ----
    if (use_side) {
        cudaEventRecord(evFork, 0);
        cudaStreamWaitEvent(side, evFork, 0);
    }
    launch_split_s(prepSt, enc_out_w, wo_h,  wo_l,  (size_t)NLAY * HD * HD);
    launch_split_s(prepSt, enc_ff1_w, wf1_h, wf1_l, (size_t)NLAY * 2 * HD * HD);
    launch_split_s(prepSt, enc_ff2_w, wf2_h, wf2_l, (size_t)NLAY * HD * 2 * HD);
    transpose_split_kernel<<<dim3(HD / 32, HD / 32, NLAY), dim3(32, 8), 0, prepSt>>>(
        enc_in_w + (size_t)2 * HD * HD, HD, HD, wvt_h, wvt_l,
        (size_t)3 * HD * HD, (size_t)HD * HD);
    bias_fold_kernel<<<dim3(HD, NLAY), 128, 0, prepSt>>>(
        enc_out_w, HD, 0, enc_in_b + 2 * HD, enc_out_b, bc, HD,
        (size_t)HD * HD, (size_t)3 * HD, (size_t)HD, (size_t)HD);
    k_pre<<<dim3(HD / 128, HD / 256, NLAY), 256, TG_SMEM, prepSt>>>(
        HD, HD, HD, 0,
        wo_h, wo_l, HD, nullptr, nullptr, 0, nullptr,
        wvt_h, wvt_l, HD, nullptr, nullptr, 0,
        zero, nullptr, nullptr,
        nullptr, wc_h, wc_l,
        (size_t)HD * HD, (size_t)HD * HD, (size_t)HD * HD, HD, HD, 0);
    k_pre<<<dim3(DE / 128, HD / 256, 1), 256, TG_SMEM, prepSt>>>(
        HD, DE, DE, 0,
        wbott_h + XFD, wbott_l + XFD, XFD + DE, nullptr, nullptr, 0, nullptr,
        woutt_h, woutt_l, DE, nullptr, nullptr, 0,
        zero, nullptr, nullptr,
        nullptr, wao_h, wao_l, 0, 0, 0, DE, DE, 0);
    if (use_side) cudaEventRecord(evJoin, side);

    const int MQ = NS * LS;
    const int KQ = DE;
    const int NQ = 2 * DE;       // Q,K only — V eliminated algebraically

    // 1. qk(compact) = gathered_emb @ [Wq;Wk]^T + bias
    k_qk<<<dim3(NQ / 128, MQ / 256, 1), 256, TG_SMEM>>>(
        MQ, NQ, KQ, 0,
        gah, gal, KQ, nullptr, nullptr, 0, total,
        wqkv_h, wqkv_l, KQ, nullptr, nullptr, 0,
        mha_in_b, nullptr, nullptr, qkv, nullptr, nullptr, 0, 0, 0, NQ, NQ, 0);

    // 2. attention weights -> per-head mixed embeddings CE [4096 x 4 x 768]
    name_attn_kernel<<<dim3(NHN, NS), 192>>>(qkv, off, gah, gal, ce_h, ce_l);

    // 2b. attnsum_h = CE_h @ Wv_h^T + len*bv_h  (z = head, N=192, 128 CTAs total)
    k_csum<<<dim3(2, NS / 256, NHN), 256, TG_SMEM>>>(
        NS, DHN, DE, 0,
        ce_h, ce_l, NHN * DE, nullptr, nullptr, 0, nullptr,
        wqkv_h + (size_t)2 * DE * DE, wqkv_l + (size_t)2 * DE * DE, DE, nullptr, nullptr, 0,
        zero, mha_in_b + 2 * DE, name_lens,
        nullptr, attn_h, attn_l,
        (size_t)DE, (size_t)DHN * DE, (size_t)DHN,
        DE, DHN, (size_t)DHN);

    // ---- join ----
    if (use_side) cudaStreamWaitEvent(0, evJoin, 0);

    // 3. x = xf@Wb1^T + attnsum@Wao^T + bbott + len*bao -> h fp32 + split
    k_bott<<<dim3(HD / 128, NS / 256, 1), 256, TG_SMEM>>>(
        NS, HD, XFD + DE, XFD,
        xf_h, xf_l, XFD, attn_h, attn_l, DE, nullptr,
        wbott_h, wbott_l, XFD + DE, wao_h, wao_l, DE,
        bott_b, bao, name_lens, h, hh, hl, 0, 0, 0, HD, HD, 0);

    // 4. encoder layers
    for (int l = 0; l < NLAY; l++) {
        k_plain<<<dim3(HD / 128, NS / 256, 1), 256, TG_SMEM>>>(
            NS, HD, HD, 0,
            hh, hl, HD, nullptr, nullptr, 0, nullptr,
            wc_h + (size_t)l * HD * HD, wc_l + (size_t)l * HD * HD, HD,
            nullptr, nullptr, 0,
            bc + (size_t)l * HD, nullptr, nullptr, ta, nullptr, nullptr, 0, 0, 0, HD, HD, 0);
        resid_ln_kernel<<<NS, 256>>>(h, ta, enc_ln1_g + (size_t)l * HD, enc_ln1_b + (size_t)l * HD, hh, hl);

        k_ff1<<<dim3(2 * HD / 128, NS / 256, 1), 256, TG_SMEM>>>(
            NS, 2 * HD, HD, 0,
            hh, hl, HD, nullptr, nullptr, 0, nullptr,
            wf1_h + (size_t)l * 2 * HD * HD, wf1_l + (size_t)l * 2 * HD * HD, HD,
            nullptr, nullptr, 0,
            enc_ff1_b + (size_t)l * 2 * HD, nullptr, nullptr, nullptr, t1_h, t1_l,
            0, 0, 0, 2 * HD, 2 * HD, 0);
        k_plain<<<dim3(HD / 128, NS / 256, 1), 256, TG_SMEM>>>(
            NS, HD, 2 * HD, 0,
            t1_h, t1_l, 2 * HD, nullptr, nullptr, 0, nullptr,
            wf2_h + (size_t)l * HD * 2 * HD, wf2_l + (size_t)l * HD * 2 * HD, 2 * HD,
            nullptr, nullptr, 0,
            enc_ff2_b + (size_t)l * HD, nullptr, nullptr, ta, nullptr, nullptr, 0, 0, 0, HD, HD, 0);
        resid_ln_kernel<<<NS, 256>>>(h, ta, enc_ln2_g + (size_t)l * HD, enc_ln2_b + (size_t)l * HD, hh, hl);
    }

    // 5. classifier head
    cls_kernel<<<NS, 512>>>(h, cls_w, cls_b, out);
}